// round 5
// baseline (speedup 1.0000x reference)
#include <cuda_runtime.h>
#include <cuda_bf16.h>
#include <cstdint>

#define B 512
#define EDIM 200
#define NUM_ENT 100000
#define FDIM 4608          // 32*8*18
#define EPS 1e-5f
#define KC2 512            // [hi(256) | lo(256)]
#define ENT_TILE 128
#define N_GRID ((NUM_ENT + ENT_TILE - 1) / ENT_TILE)   // 782
#define ENT_PAD (N_GRID * ENT_TILE)                    // 100096

// ---------------- device scratch (static allocations only) ----------------
__device__ float d_y[B * FDIM];            // conv output, pre-bn1
__device__ float d_h[B * EDIM];            // fc output, pre-bn2
__device__ __nv_bfloat16 d_zcat[B * KC2];          // [batch][512] = [z_hi|z_lo]
__device__ __nv_bfloat16 d_ecat[ENT_PAD * KC2];    // [ent][512]  = [e_hi|e_lo]
__device__ float d_chsum[32];
__device__ float d_chsq[32];
__device__ float d_bn0acc[2];              // {sum, sumsq} partials
__device__ float d_bn0[2];                 // {scale, shift}
__device__ float d_bn1a[32];
__device__ float d_bn1c[32];

// ---------------- PTX helpers (sm_80-compatible subset only) ----------------
__device__ __forceinline__ uint32_t smem_u32(const void* p) {
    uint32_t a;
    asm("{ .reg .u64 t; cvta.to.shared.u64 t, %1; cvt.u32.u64 %0, t; }" : "=r"(a) : "l"(p));
    return a;
}
__device__ __forceinline__ void cp_async16(uint32_t dst, const void* src) {
    asm volatile("cp.async.cg.shared.global [%0], [%1], 16;" :: "r"(dst), "l"(src) : "memory");
}
__device__ __forceinline__ void cp_commit() {
    asm volatile("cp.async.commit_group;" ::: "memory");
}
__device__ __forceinline__ void ldm4(uint32_t* r, uint32_t a) {
    asm volatile("ldmatrix.sync.aligned.m8n8.x4.shared.b16 {%0,%1,%2,%3}, [%4];"
                 : "=r"(r[0]), "=r"(r[1]), "=r"(r[2]), "=r"(r[3]) : "r"(a));
}
__device__ __forceinline__ void mma16816(float* d, const uint32_t* a, const uint32_t* b) {
    asm volatile("mma.sync.aligned.m16n8k16.row.col.f32.bf16.bf16.f32 "
                 "{%0,%1,%2,%3}, {%4,%5,%6,%7}, {%8,%9}, {%0,%1,%2,%3};"
                 : "+f"(d[0]), "+f"(d[1]), "+f"(d[2]), "+f"(d[3])
                 : "r"(a[0]), "r"(a[1]), "r"(a[2]), "r"(a[3]), "r"(b[0]), "r"(b[1]));
}
__device__ __forceinline__ uint32_t swz(uint32_t off) { return off ^ ((off >> 3) & 0x70); }
__device__ __forceinline__ uint32_t pack_bf16(__nv_bfloat16 a, __nv_bfloat16 b) {
    return (uint32_t)__bfloat16_as_ushort(a) | ((uint32_t)__bfloat16_as_ushort(b) << 16);
}

// ---------------- K0: zero accumulators ----------------
__global__ void k0_zero() {
    int i = blockIdx.x * blockDim.x + threadIdx.x;
    if (i < B * EDIM) d_h[i] = 0.f;
    if (i < B * KC2 / 2) ((uint32_t*)d_zcat)[i] = 0u;
    if (i < 32) { d_chsum[i] = 0.f; d_chsq[i] = 0.f; }
    if (i < 2) d_bn0acc[i] = 0.f;
}

// ---------------- K1: bn0 stats (multi-CTA) ----------------
__global__ void k1_bn0(const int* __restrict__ e1, const float* __restrict__ emb) {
    int tid = threadIdx.x, lane = tid & 31;
    float s = 0.f, q = 0.f;
    for (int idx = blockIdx.x * 512 + tid; idx < B * EDIM; idx += gridDim.x * 512) {
        int b = idx / EDIM, j = idx - b * EDIM;
        float v = emb[(size_t)e1[b] * EDIM + j];
        s += v; q += v * v;
    }
    #pragma unroll
    for (int o = 16; o; o >>= 1) {
        s += __shfl_down_sync(0xffffffffu, s, o);
        q += __shfl_down_sync(0xffffffffu, q, o);
    }
    if (lane == 0) { atomicAdd(&d_bn0acc[0], s); atomicAdd(&d_bn0acc[1], q); }
}
__global__ void k1b_bn0fin(const float* __restrict__ g0, const float* __restrict__ b0) {
    const float inv = 1.f / (float)(B * EDIM);
    float m = d_bn0acc[0] * inv;
    float var = d_bn0acc[1] * inv - m * m;
    float sc = rsqrtf(var + EPS) * g0[0];
    d_bn0[0] = sc;
    d_bn0[1] = b0[0] - m * sc;
}

// ---------------- K2: relation-indexed 3x3 conv ----------------
__global__ void k2_conv(const int* __restrict__ e1, const int* __restrict__ rel,
                        const float* __restrict__ emb,
                        const float* __restrict__ conv_w, const float* __restrict__ conv_b) {
    __shared__ float sx[200];
    __shared__ float sw[288];
    __shared__ float scb[32];
    int b = blockIdx.x;
    int tid = threadIdx.x;
    int r = rel[b];
    float bn_s = d_bn0[0], bn_b = d_bn0[1];
    if (tid < 200) sx[tid] = fmaf(emb[(size_t)e1[b] * EDIM + tid], bn_s, bn_b);
    for (int i = tid; i < 288; i += 256) sw[i] = conv_w[(size_t)r * 288 + i];
    if (tid < 32) scb[tid] = conv_b[(size_t)r * 32 + tid];
    __syncthreads();

    int o = tid >> 3;
    int i = tid & 7;
    const float* w = &sw[o * 9];
    float cb = scb[o];
    float ls = 0.f, lq = 0.f;
    float* yrow = &d_y[(size_t)b * FDIM + o * 144 + i * 18];
    #pragma unroll
    for (int j = 0; j < 18; j++) {
        float acc = cb;
        #pragma unroll
        for (int di = 0; di < 3; di++)
            #pragma unroll
            for (int dj = 0; dj < 3; dj++)
                acc = fmaf(sx[(i + di) * 20 + (j + dj)], w[di * 3 + dj], acc);
        yrow[j] = acc;
        ls += acc; lq += acc * acc;
    }
    #pragma unroll
    for (int off = 4; off; off >>= 1) {
        ls += __shfl_down_sync(0xffffffffu, ls, off, 8);
        lq += __shfl_down_sync(0xffffffffu, lq, off, 8);
    }
    if ((tid & 7) == 0) {
        atomicAdd(&d_chsum[o], ls);
        atomicAdd(&d_chsq[o], lq);
    }
}

// ---------------- K3a: bn1 affine ----------------
__global__ void k3a_bn1(const float* __restrict__ g1, const float* __restrict__ b1) {
    int c = threadIdx.x;
    if (c < 32) {
        const float inv = 1.f / (float)(B * 144);
        float m = d_chsum[c] * inv;
        float var = d_chsq[c] * inv - m * m;
        float a = rsqrtf(var + EPS) * g1[c];
        d_bn1a[c] = a;
        d_bn1c[c] = b1[c] - m * a;
    }
}

// ---------------- K3: fc GEMM (fp32 SIMT, 12 k-splits x 3 inner chunks) ----------------
#define FC_SY_STRIDE 68
#define FC_SW_STRIDE 132
#define FC_SMEM ((128*FC_SY_STRIDE + 128*FC_SW_STRIDE) * 4)
__global__ void __launch_bounds__(256) k3_fc(const float* __restrict__ fc_w) {
    extern __shared__ float sm[];
    float* s_y = sm;
    float* s_w = sm + 128 * FC_SY_STRIDE;
    __shared__ float s_a[32], s_c[32];

    int tid = threadIdx.x;
    int n0 = blockIdx.x * 128, m0 = blockIdx.y * 64;
    if (tid < 32) { s_a[tid] = d_bn1a[tid]; s_c[tid] = d_bn1c[tid]; }

    int mg = (tid & 15) * 4;
    int ng = (tid >> 4) * 8;
    float acc[32];
    #pragma unroll
    for (int i = 0; i < 32; i++) acc[i] = 0.f;

    for (int cc = 0; cc < 3; cc++) {
        int k0 = blockIdx.z * 384 + cc * 128;
        __syncthreads();
        #pragma unroll
        for (int i = 0; i < 8; i++) {
            int p = tid + i * 256;
            int m = p >> 5, c4 = p & 31;
            float4 v = *(const float4*)&d_y[(size_t)(m0 + m) * FDIM + k0 + c4 * 4];
            int kk = k0 + c4 * 4;
            int ch0 = kk / 144, ch1 = (kk + 1) / 144, ch2 = (kk + 2) / 144, ch3 = (kk + 3) / 144;
            s_y[(c4 * 4 + 0) * FC_SY_STRIDE + m] = fmaxf(fmaf(v.x, s_a[ch0], s_c[ch0]), 0.f);
            s_y[(c4 * 4 + 1) * FC_SY_STRIDE + m] = fmaxf(fmaf(v.y, s_a[ch1], s_c[ch1]), 0.f);
            s_y[(c4 * 4 + 2) * FC_SY_STRIDE + m] = fmaxf(fmaf(v.z, s_a[ch2], s_c[ch2]), 0.f);
            s_y[(c4 * 4 + 3) * FC_SY_STRIDE + m] = fmaxf(fmaf(v.w, s_a[ch3], s_c[ch3]), 0.f);
        }
        #pragma unroll
        for (int i = 0; i < 16; i++) {
            int p = tid + i * 256;
            int n = p >> 5, c4 = p & 31;
            float4 v = make_float4(0.f, 0.f, 0.f, 0.f);
            if (n0 + n < EDIM) v = *(const float4*)&fc_w[(size_t)(n0 + n) * FDIM + k0 + c4 * 4];
            s_w[(c4 * 4 + 0) * FC_SW_STRIDE + n] = v.x;
            s_w[(c4 * 4 + 1) * FC_SW_STRIDE + n] = v.y;
            s_w[(c4 * 4 + 2) * FC_SW_STRIDE + n] = v.z;
            s_w[(c4 * 4 + 3) * FC_SW_STRIDE + n] = v.w;
        }
        __syncthreads();

        #pragma unroll 8
        for (int k = 0; k < 128; k++) {
            float4 z = *(const float4*)(s_y + k * FC_SY_STRIDE + mg);
            float4 ea = *(const float4*)(s_w + k * FC_SW_STRIDE + ng);
            float4 eb = *(const float4*)(s_w + k * FC_SW_STRIDE + ng + 4);
            float zz[4] = {z.x, z.y, z.z, z.w};
            float ee[8] = {ea.x, ea.y, ea.z, ea.w, eb.x, eb.y, eb.z, eb.w};
            #pragma unroll
            for (int mi = 0; mi < 4; mi++)
                #pragma unroll
                for (int nj = 0; nj < 8; nj++)
                    acc[mi * 8 + nj] = fmaf(zz[mi], ee[nj], acc[mi * 8 + nj]);
        }
    }

    #pragma unroll
    for (int mi = 0; mi < 4; mi++)
        #pragma unroll
        for (int nj = 0; nj < 8; nj++) {
            int n = n0 + ng + nj;
            if (n < EDIM)
                atomicAdd(&d_h[(size_t)(m0 + mg + mi) * EDIM + n], acc[mi * 8 + nj]);
        }
}

// ---------------- K4: bn2 + relu, emit bf16 [z_hi | z_lo] ----------------
__global__ void k4_bn2(const float* __restrict__ g2, const float* __restrict__ b2) {
    int n = blockIdx.x;        // feature 0..199
    int t = threadIdx.x;       // 256
    float v0 = d_h[(size_t)t * EDIM + n];
    float v1 = d_h[(size_t)(t + 256) * EDIM + n];
    __shared__ float rs[256], rq[256];
    rs[t] = v0 + v1; rq[t] = v0 * v0 + v1 * v1;
    __syncthreads();
    for (int o = 128; o; o >>= 1) {
        if (t < o) { rs[t] += rs[t + o]; rq[t] += rq[t + o]; }
        __syncthreads();
    }
    __shared__ float sa, sc;
    if (t == 0) {
        float m = rs[0] * (1.f / 512.f);
        float var = rq[0] * (1.f / 512.f) - m * m;
        float a = rsqrtf(var + EPS) * g2[n];
        sa = a; sc = b2[n] - m * a;
    }
    __syncthreads();
    float z0 = fmaxf(fmaf(v0, sa, sc), 0.f);
    float z1 = fmaxf(fmaf(v1, sa, sc), 0.f);
    __nv_bfloat16 h0 = __float2bfloat16(z0);
    __nv_bfloat16 h1 = __float2bfloat16(z1);
    __nv_bfloat16 l0 = __float2bfloat16(z0 - __bfloat162float(h0));
    __nv_bfloat16 l1 = __float2bfloat16(z1 - __bfloat162float(h1));
    size_t r0 = (size_t)t * KC2, r1 = (size_t)(t + 256) * KC2;
    d_zcat[r0 + n] = h0; d_zcat[r0 + 256 + n] = l0;
    d_zcat[r1 + n] = h1; d_zcat[r1 + 256 + n] = l1;
}

// ---------------- K4b: build e_cat = [e_hi | e_lo], fully coalesced ----------------
__global__ void __launch_bounds__(256) k4b_ecat(const float* __restrict__ emb) {
    int warp = threadIdx.x >> 5, lane = threadIdx.x & 31;
    int row0 = blockIdx.x * 128;
    #pragma unroll 4
    for (int it = 0; it < 16; it++) {
        int row = row0 + warp + it * 8;
        bool rv = (row < NUM_ENT) && (lane < 25);     // 25*8 = 200 cols
        float4 f0 = make_float4(0.f, 0.f, 0.f, 0.f);
        float4 f1 = make_float4(0.f, 0.f, 0.f, 0.f);
        if (rv) {
            const float* src = emb + (size_t)row * EDIM + lane * 8;
            f0 = *(const float4*)src;
            f1 = *(const float4*)(src + 4);
        }
        float v[8] = {f0.x, f0.y, f0.z, f0.w, f1.x, f1.y, f1.z, f1.w};
        uint32_t hp[4], lp[4];
        #pragma unroll
        for (int i = 0; i < 4; i++) {
            __nv_bfloat16 ha = __float2bfloat16(v[2 * i]);
            __nv_bfloat16 hb = __float2bfloat16(v[2 * i + 1]);
            hp[i] = pack_bf16(ha, hb);
            lp[i] = pack_bf16(__float2bfloat16(v[2 * i]     - __bfloat162float(ha)),
                              __float2bfloat16(v[2 * i + 1] - __bfloat162float(hb)));
        }
        __nv_bfloat16* dr = d_ecat + (size_t)row * KC2;
        *(uint4*)(dr + lane * 8)       = make_uint4(hp[0], hp[1], hp[2], hp[3]);
        *(uint4*)(dr + 256 + lane * 8) = make_uint4(lp[0], lp[1], lp[2], lp[3]);
    }
}

// ---------------- K5: bf16 mma.sync GEMM + bias + sigmoid ----------------
// A (zcat tile, 128 m x 512 k) persistent in SMEM as 8 subtiles of 128x64.
// B double-buffered: per k-quarter load {B_hi, B_lo} (2 x 16KB).
// Per k-quarter: 3 passes (zhi*ehi, zlo*ehi, zhi*elo); ks=3 -> 1 k16-step.
#define A_SUB(t, q) (((t) * 4 + (q)) * 16384)
#define B_BASE      131072
#define B_STAGE     32768
#define K5_SMEM     (131072 + 65536)

__device__ __forceinline__ void k5_loadA(uint32_t sb, int m0, int tid) {
    #pragma unroll
    for (int t = 0; t < 2; t++)
        #pragma unroll
        for (int q = 0; q < 4; q++)
            #pragma unroll
            for (int i = 0; i < 4; i++) {
                int idx = tid + i * 256;
                int row = idx >> 3, u = idx & 7;
                cp_async16(sb + A_SUB(t, q) + swz(row * 128 + u * 16),
                           d_zcat + (size_t)(m0 + row) * KC2 + t * 256 + q * 64 + u * 8);
            }
}
__device__ __forceinline__ void k5_loadB(uint32_t sb, int stage, int ks, int n0, int tid) {
    uint32_t base = sb + B_BASE + stage * B_STAGE;
    #pragma unroll
    for (int h = 0; h < 2; h++)
        #pragma unroll
        for (int i = 0; i < 4; i++) {
            int idx = tid + i * 256;
            int row = idx >> 3, u = idx & 7;
            cp_async16(base + h * 16384 + swz(row * 128 + u * 16),
                       d_ecat + (size_t)(n0 + row) * KC2 + h * 256 + ks * 64 + u * 8);
        }
    cp_commit();
}

__global__ void __launch_bounds__(256, 1) k5_mma(const float* __restrict__ bias_e,
                                                 float* __restrict__ out) {
    extern __shared__ char smem[];
    const uint32_t sb = smem_u32(smem);
    int tid = threadIdx.x, lane = tid & 31, wid = tid >> 5;
    int wm = wid & 3, wn = wid >> 2;
    int m0 = blockIdx.x * 128, n0 = blockIdx.y * 128;

    float acc[2][8][4];
    #pragma unroll
    for (int f = 0; f < 2; f++)
        #pragma unroll
        for (int h = 0; h < 8; h++)
            #pragma unroll
            for (int i = 0; i < 4; i++) acc[f][h][i] = 0.f;

    k5_loadA(sb, m0, tid);
    k5_loadB(sb, 0, 0, n0, tid);    // group 0 = A + B0
    k5_loadB(sb, 1, 1, n0, tid);    // group 1 = B1

    for (int ks = 0; ks < 4; ks++) {
        if (ks < 3) asm volatile("cp.async.wait_group 1;" ::: "memory");
        else        asm volatile("cp.async.wait_group 0;" ::: "memory");
        __syncthreads();

        const int scount = (ks < 3) ? 4 : 1;
        const uint32_t bst = sb + B_BASE + (ks & 1) * B_STAGE;
        #pragma unroll
        for (int pass = 0; pass < 3; pass++) {
            uint32_t abase = sb + A_SUB(pass == 1 ? 1 : 0, ks);
            uint32_t bbase = bst + (pass == 2 ? 16384 : 0);
            for (int s = 0; s < scount; s++) {
                uint32_t a[2][4];
                #pragma unroll
                for (int f = 0; f < 2; f++) {
                    int row = wm * 32 + f * 16 + (lane & 15);
                    int u = s * 2 + (lane >> 4);
                    ldm4(a[f], abase + swz(row * 128 + u * 16));
                }
                #pragma unroll
                for (int j = 0; j < 4; j++) {
                    uint32_t b[4];
                    int row = wn * 64 + j * 16 + ((lane >> 4) << 3) + (lane & 7);
                    int u = s * 2 + ((lane >> 3) & 1);
                    ldm4(b, bbase + swz(row * 128 + u * 16));
                    #pragma unroll
                    for (int g = 0; g < 2; g++)
                        #pragma unroll
                        for (int f = 0; f < 2; f++)
                            mma16816(acc[f][j * 2 + g], a[f], b + g * 2);
                }
            }
        }
        __syncthreads();
        if (ks + 2 <= 3) k5_loadB(sb, ks & 1, ks + 2, n0, tid);
    }

    // epilogue
    int g = lane >> 2, q = lane & 3;
    #pragma unroll
    for (int f = 0; f < 2; f++) {
        int mrow = m0 + wm * 32 + f * 16 + g;
        #pragma unroll
        for (int h = 0; h < 8; h++) {
            int n = n0 + wn * 64 + h * 8 + q * 2;
            if (n < NUM_ENT) {
                float b0 = bias_e[n], b1 = bias_e[n + 1];
                float v0 = acc[f][h][0] + b0, v1 = acc[f][h][1] + b1;
                float v2 = acc[f][h][2] + b0, v3 = acc[f][h][3] + b1;
                *(float2*)&out[(size_t)mrow * NUM_ENT + n] =
                    make_float2(1.f / (1.f + __expf(-v0)), 1.f / (1.f + __expf(-v1)));
                *(float2*)&out[(size_t)(mrow + 8) * NUM_ENT + n] =
                    make_float2(1.f / (1.f + __expf(-v2)), 1.f / (1.f + __expf(-v3)));
            }
        }
    }
}

// ---------------- launcher ----------------
extern "C" void kernel_launch(void* const* d_in, const int* in_sizes, int n_in,
                              void* d_out, int out_size) {
    const int*   e1     = (const int*)d_in[0];
    const int*   rel    = (const int*)d_in[1];
    const float* emb    = (const float*)d_in[2];
    const float* conv_w = (const float*)d_in[3];
    const float* conv_b = (const float*)d_in[4];
    const float* g0     = (const float*)d_in[5];
    const float* b0     = (const float*)d_in[6];
    const float* g1     = (const float*)d_in[7];
    const float* b1     = (const float*)d_in[8];
    const float* g2     = (const float*)d_in[9];
    const float* b2     = (const float*)d_in[10];
    const float* fc_w   = (const float*)d_in[11];
    // d_in[12] = fc_b: cancels exactly under training-mode bn2
    const float* bias_e = (const float*)d_in[13];
    float* out = (float*)d_out;

    cudaFuncSetAttribute(k3_fc,  cudaFuncAttributeMaxDynamicSharedMemorySize, FC_SMEM);
    cudaFuncSetAttribute(k5_mma, cudaFuncAttributeMaxDynamicSharedMemorySize, K5_SMEM);

    k4b_ecat<<<N_GRID, 256>>>(emb);
    k0_zero<<<800, 256>>>();
    k1_bn0<<<16, 512>>>(e1, emb);
    k1b_bn0fin<<<1, 1>>>(g0, b0);
    k2_conv<<<B, 256>>>(e1, rel, emb, conv_w, conv_b);
    k3a_bn1<<<1, 32>>>(g1, b1);
    k3_fc<<<dim3(2, 8, 12), 256, FC_SMEM>>>(fc_w);
    k4_bn2<<<EDIM, 256>>>(g2, b2);
    k5_mma<<<dim3(4, N_GRID), 256, K5_SMEM>>>(bias_e, out);
}

// round 6
// speedup vs baseline: 1.2790x; 1.2790x over previous
#include <cuda_runtime.h>
#include <cuda_bf16.h>
#include <cstdint>

#define B 512
#define EDIM 200
#define NUM_ENT 100000
#define FDIM 4608          // 32*8*18
#define EPS 1e-5f
#define KC2 512            // [hi(256) | lo(256)]
#define ENT_TILE 128
#define N_GRID ((NUM_ENT + ENT_TILE - 1) / ENT_TILE)   // 782
#define ENT_PAD (N_GRID * ENT_TILE)                    // 100096

// ---------------- device scratch (static allocations only) ----------------
__device__ float d_y[B * FDIM];            // conv output, pre-bn1
__device__ float d_h[B * EDIM];            // fc output, pre-bn2
__device__ __nv_bfloat16 d_zcat[B * KC2];          // [batch][512] = [z_hi|z_lo]
__device__ __nv_bfloat16 d_ecat[ENT_PAD * KC2];    // [ent][512]  = [e_hi|e_lo]
__device__ float d_chsum[32];
__device__ float d_chsq[32];
__device__ float d_bn0acc[2];              // {sum, sumsq} partials
__device__ float d_bn0[2];                 // {scale, shift}
__device__ float d_bn1a[32];
__device__ float d_bn1c[32];

// ---------------- PTX helpers (sm_80-compatible subset only) ----------------
__device__ __forceinline__ uint32_t smem_u32(const void* p) {
    uint32_t a;
    asm("{ .reg .u64 t; cvta.to.shared.u64 t, %1; cvt.u32.u64 %0, t; }" : "=r"(a) : "l"(p));
    return a;
}
__device__ __forceinline__ void cp_async16(uint32_t dst, const void* src) {
    asm volatile("cp.async.cg.shared.global [%0], [%1], 16;" :: "r"(dst), "l"(src) : "memory");
}
__device__ __forceinline__ void cp_commit() {
    asm volatile("cp.async.commit_group;" ::: "memory");
}
__device__ __forceinline__ void ldm4(uint32_t* r, uint32_t a) {
    asm volatile("ldmatrix.sync.aligned.m8n8.x4.shared.b16 {%0,%1,%2,%3}, [%4];"
                 : "=r"(r[0]), "=r"(r[1]), "=r"(r[2]), "=r"(r[3]) : "r"(a));
}
__device__ __forceinline__ void mma16816(float* d, const uint32_t* a, const uint32_t* b) {
    asm volatile("mma.sync.aligned.m16n8k16.row.col.f32.bf16.bf16.f32 "
                 "{%0,%1,%2,%3}, {%4,%5,%6,%7}, {%8,%9}, {%0,%1,%2,%3};"
                 : "+f"(d[0]), "+f"(d[1]), "+f"(d[2]), "+f"(d[3])
                 : "r"(a[0]), "r"(a[1]), "r"(a[2]), "r"(a[3]), "r"(b[0]), "r"(b[1]));
}
__device__ __forceinline__ uint32_t swz(uint32_t off) { return off ^ ((off >> 3) & 0x70); }
__device__ __forceinline__ uint32_t pack_bf16(__nv_bfloat16 a, __nv_bfloat16 b) {
    return (uint32_t)__bfloat16_as_ushort(a) | ((uint32_t)__bfloat16_as_ushort(b) << 16);
}

// ---------------- K0: zero accumulators ----------------
__global__ void k0_zero() {
    int i = blockIdx.x * blockDim.x + threadIdx.x;
    if (i < B * EDIM) d_h[i] = 0.f;
    if (i < B * KC2 / 2) ((uint32_t*)d_zcat)[i] = 0u;
    if (i < 32) { d_chsum[i] = 0.f; d_chsq[i] = 0.f; }
    if (i < 2) d_bn0acc[i] = 0.f;
}

// ---------------- K1: bn0 stats (multi-CTA) ----------------
__global__ void k1_bn0(const int* __restrict__ e1, const float* __restrict__ emb) {
    int tid = threadIdx.x, lane = tid & 31;
    float s = 0.f, q = 0.f;
    for (int idx = blockIdx.x * 512 + tid; idx < B * EDIM; idx += gridDim.x * 512) {
        int b = idx / EDIM, j = idx - b * EDIM;
        float v = emb[(size_t)e1[b] * EDIM + j];
        s += v; q += v * v;
    }
    #pragma unroll
    for (int o = 16; o; o >>= 1) {
        s += __shfl_down_sync(0xffffffffu, s, o);
        q += __shfl_down_sync(0xffffffffu, q, o);
    }
    if (lane == 0) { atomicAdd(&d_bn0acc[0], s); atomicAdd(&d_bn0acc[1], q); }
}
__global__ void k1b_bn0fin(const float* __restrict__ g0, const float* __restrict__ b0) {
    const float inv = 1.f / (float)(B * EDIM);
    float m = d_bn0acc[0] * inv;
    float var = d_bn0acc[1] * inv - m * m;
    float sc = rsqrtf(var + EPS) * g0[0];
    d_bn0[0] = sc;
    d_bn0[1] = b0[0] - m * sc;
}

// ---------------- K2: relation-indexed 3x3 conv ----------------
__global__ void k2_conv(const int* __restrict__ e1, const int* __restrict__ rel,
                        const float* __restrict__ emb,
                        const float* __restrict__ conv_w, const float* __restrict__ conv_b) {
    __shared__ float sx[200];
    __shared__ float sw[288];
    __shared__ float scb[32];
    int b = blockIdx.x;
    int tid = threadIdx.x;
    int r = rel[b];
    float bn_s = d_bn0[0], bn_b = d_bn0[1];
    if (tid < 200) sx[tid] = fmaf(emb[(size_t)e1[b] * EDIM + tid], bn_s, bn_b);
    for (int i = tid; i < 288; i += 256) sw[i] = conv_w[(size_t)r * 288 + i];
    if (tid < 32) scb[tid] = conv_b[(size_t)r * 32 + tid];
    __syncthreads();

    int o = tid >> 3;
    int i = tid & 7;
    const float* w = &sw[o * 9];
    float cb = scb[o];
    float ls = 0.f, lq = 0.f;
    float* yrow = &d_y[(size_t)b * FDIM + o * 144 + i * 18];
    #pragma unroll
    for (int j = 0; j < 18; j++) {
        float acc = cb;
        #pragma unroll
        for (int di = 0; di < 3; di++)
            #pragma unroll
            for (int dj = 0; dj < 3; dj++)
                acc = fmaf(sx[(i + di) * 20 + (j + dj)], w[di * 3 + dj], acc);
        yrow[j] = acc;
        ls += acc; lq += acc * acc;
    }
    #pragma unroll
    for (int off = 4; off; off >>= 1) {
        ls += __shfl_down_sync(0xffffffffu, ls, off, 8);
        lq += __shfl_down_sync(0xffffffffu, lq, off, 8);
    }
    if ((tid & 7) == 0) {
        atomicAdd(&d_chsum[o], ls);
        atomicAdd(&d_chsq[o], lq);
    }
}

// ---------------- K3a: bn1 affine ----------------
__global__ void k3a_bn1(const float* __restrict__ g1, const float* __restrict__ b1) {
    int c = threadIdx.x;
    if (c < 32) {
        const float inv = 1.f / (float)(B * 144);
        float m = d_chsum[c] * inv;
        float var = d_chsq[c] * inv - m * m;
        float a = rsqrtf(var + EPS) * g1[c];
        d_bn1a[c] = a;
        d_bn1c[c] = b1[c] - m * a;
    }
}

// ---------------- K3: fc GEMM (fp32 SIMT, 12 k-splits x 3 inner chunks) ----------------
#define FC_SY_STRIDE 68
#define FC_SW_STRIDE 132
#define FC_SMEM ((128*FC_SY_STRIDE + 128*FC_SW_STRIDE) * 4)
__global__ void __launch_bounds__(256) k3_fc(const float* __restrict__ fc_w) {
    extern __shared__ float sm[];
    float* s_y = sm;
    float* s_w = sm + 128 * FC_SY_STRIDE;
    __shared__ float s_a[32], s_c[32];

    int tid = threadIdx.x;
    int n0 = blockIdx.x * 128, m0 = blockIdx.y * 64;
    if (tid < 32) { s_a[tid] = d_bn1a[tid]; s_c[tid] = d_bn1c[tid]; }

    int mg = (tid & 15) * 4;
    int ng = (tid >> 4) * 8;
    float acc[32];
    #pragma unroll
    for (int i = 0; i < 32; i++) acc[i] = 0.f;

    for (int cc = 0; cc < 3; cc++) {
        int k0 = blockIdx.z * 384 + cc * 128;
        __syncthreads();
        #pragma unroll
        for (int i = 0; i < 8; i++) {
            int p = tid + i * 256;
            int m = p >> 5, c4 = p & 31;
            float4 v = *(const float4*)&d_y[(size_t)(m0 + m) * FDIM + k0 + c4 * 4];
            int kk = k0 + c4 * 4;
            int ch0 = kk / 144, ch1 = (kk + 1) / 144, ch2 = (kk + 2) / 144, ch3 = (kk + 3) / 144;
            s_y[(c4 * 4 + 0) * FC_SY_STRIDE + m] = fmaxf(fmaf(v.x, s_a[ch0], s_c[ch0]), 0.f);
            s_y[(c4 * 4 + 1) * FC_SY_STRIDE + m] = fmaxf(fmaf(v.y, s_a[ch1], s_c[ch1]), 0.f);
            s_y[(c4 * 4 + 2) * FC_SY_STRIDE + m] = fmaxf(fmaf(v.z, s_a[ch2], s_c[ch2]), 0.f);
            s_y[(c4 * 4 + 3) * FC_SY_STRIDE + m] = fmaxf(fmaf(v.w, s_a[ch3], s_c[ch3]), 0.f);
        }
        #pragma unroll
        for (int i = 0; i < 16; i++) {
            int p = tid + i * 256;
            int n = p >> 5, c4 = p & 31;
            float4 v = make_float4(0.f, 0.f, 0.f, 0.f);
            if (n0 + n < EDIM) v = *(const float4*)&fc_w[(size_t)(n0 + n) * FDIM + k0 + c4 * 4];
            s_w[(c4 * 4 + 0) * FC_SW_STRIDE + n] = v.x;
            s_w[(c4 * 4 + 1) * FC_SW_STRIDE + n] = v.y;
            s_w[(c4 * 4 + 2) * FC_SW_STRIDE + n] = v.z;
            s_w[(c4 * 4 + 3) * FC_SW_STRIDE + n] = v.w;
        }
        __syncthreads();

        #pragma unroll 8
        for (int k = 0; k < 128; k++) {
            float4 z = *(const float4*)(s_y + k * FC_SY_STRIDE + mg);
            float4 ea = *(const float4*)(s_w + k * FC_SW_STRIDE + ng);
            float4 eb = *(const float4*)(s_w + k * FC_SW_STRIDE + ng + 4);
            float zz[4] = {z.x, z.y, z.z, z.w};
            float ee[8] = {ea.x, ea.y, ea.z, ea.w, eb.x, eb.y, eb.z, eb.w};
            #pragma unroll
            for (int mi = 0; mi < 4; mi++)
                #pragma unroll
                for (int nj = 0; nj < 8; nj++)
                    acc[mi * 8 + nj] = fmaf(zz[mi], ee[nj], acc[mi * 8 + nj]);
        }
    }

    #pragma unroll
    for (int mi = 0; mi < 4; mi++)
        #pragma unroll
        for (int nj = 0; nj < 8; nj++) {
            int n = n0 + ng + nj;
            if (n < EDIM)
                atomicAdd(&d_h[(size_t)(m0 + mg + mi) * EDIM + n], acc[mi * 8 + nj]);
        }
}

// ---------------- K4: bn2 + relu, emit bf16 [z_hi | z_lo] ----------------
__global__ void k4_bn2(const float* __restrict__ g2, const float* __restrict__ b2) {
    int n = blockIdx.x;        // feature 0..199
    int t = threadIdx.x;       // 256
    float v0 = d_h[(size_t)t * EDIM + n];
    float v1 = d_h[(size_t)(t + 256) * EDIM + n];
    __shared__ float rs[256], rq[256];
    rs[t] = v0 + v1; rq[t] = v0 * v0 + v1 * v1;
    __syncthreads();
    for (int o = 128; o; o >>= 1) {
        if (t < o) { rs[t] += rs[t + o]; rq[t] += rq[t + o]; }
        __syncthreads();
    }
    __shared__ float sa, sc;
    if (t == 0) {
        float m = rs[0] * (1.f / 512.f);
        float var = rq[0] * (1.f / 512.f) - m * m;
        float a = rsqrtf(var + EPS) * g2[n];
        sa = a; sc = b2[n] - m * a;
    }
    __syncthreads();
    float z0 = fmaxf(fmaf(v0, sa, sc), 0.f);
    float z1 = fmaxf(fmaf(v1, sa, sc), 0.f);
    __nv_bfloat16 h0 = __float2bfloat16(z0);
    __nv_bfloat16 h1 = __float2bfloat16(z1);
    __nv_bfloat16 l0 = __float2bfloat16(z0 - __bfloat162float(h0));
    __nv_bfloat16 l1 = __float2bfloat16(z1 - __bfloat162float(h1));
    size_t r0 = (size_t)t * KC2, r1 = (size_t)(t + 256) * KC2;
    d_zcat[r0 + n] = h0; d_zcat[r0 + 256 + n] = l0;
    d_zcat[r1 + n] = h1; d_zcat[r1 + 256 + n] = l1;
}

// ---------------- K4b: build e_cat = [e_hi | e_lo], fully coalesced ----------------
__global__ void __launch_bounds__(256) k4b_ecat(const float* __restrict__ emb) {
    int warp = threadIdx.x >> 5, lane = threadIdx.x & 31;
    int row0 = blockIdx.x * 128;
    #pragma unroll 4
    for (int it = 0; it < 16; it++) {
        int row = row0 + warp + it * 8;
        bool rv = (row < NUM_ENT) && (lane < 25);     // 25*8 = 200 cols
        float4 f0 = make_float4(0.f, 0.f, 0.f, 0.f);
        float4 f1 = make_float4(0.f, 0.f, 0.f, 0.f);
        if (rv) {
            const float* src = emb + (size_t)row * EDIM + lane * 8;
            f0 = *(const float4*)src;
            f1 = *(const float4*)(src + 4);
        }
        float v[8] = {f0.x, f0.y, f0.z, f0.w, f1.x, f1.y, f1.z, f1.w};
        uint32_t hp[4], lp[4];
        #pragma unroll
        for (int i = 0; i < 4; i++) {
            __nv_bfloat16 ha = __float2bfloat16(v[2 * i]);
            __nv_bfloat16 hb = __float2bfloat16(v[2 * i + 1]);
            hp[i] = pack_bf16(ha, hb);
            lp[i] = pack_bf16(__float2bfloat16(v[2 * i]     - __bfloat162float(ha)),
                              __float2bfloat16(v[2 * i + 1] - __bfloat162float(hb)));
        }
        __nv_bfloat16* dr = d_ecat + (size_t)row * KC2;
        *(uint4*)(dr + lane * 8)       = make_uint4(hp[0], hp[1], hp[2], hp[3]);
        *(uint4*)(dr + 256 + lane * 8) = make_uint4(lp[0], lp[1], lp[2], lp[3]);
    }
}

// ---------------- K5: bf16 mma.sync GEMM + bias + sigmoid ----------------
// CTA tile: M=64 (batch) x N=128 (ent); 8 warps as 2(m) x 4(n), warp tile 32x32.
// Per k-quarter ks (64 cols): stage {A_hi(8K), A_lo(8K), B_hi(16K), B_lo(16K)} = 48KB,
// double-buffered (prefetch-before-wait). 3 passes: zhi*ehi, zlo*ehi, zhi*elo.
// ks=3 has only 8 real cols -> 1 k16-step. 96KB smem -> 2 CTAs/SM.
#define T_AH 0
#define T_AL 8192
#define T_BH 16384
#define T_BL 32768
#define ST_STRIDE 49152
#define K5_SMEM (2 * ST_STRIDE)

__device__ __forceinline__ void k5_load(uint32_t sb, int buf, int ks, int m0, int n0, int tid) {
    uint32_t base = sb + buf * ST_STRIDE;
    int koff = ks * 64;
    #pragma unroll
    for (int i = 0; i < 2; i++) {                    // A: 64 rows x 128B
        int idx = tid + i * 256;
        int row = idx >> 3, u = idx & 7;
        uint32_t so = swz(row * 128 + u * 16);
        const __nv_bfloat16* zr = d_zcat + (size_t)(m0 + row) * KC2 + koff + u * 8;
        cp_async16(base + T_AH + so, zr);
        cp_async16(base + T_AL + so, zr + 256);
    }
    #pragma unroll
    for (int i = 0; i < 4; i++) {                    // B: 128 rows x 128B
        int idx = tid + i * 256;
        int row = idx >> 3, u = idx & 7;
        uint32_t so = swz(row * 128 + u * 16);
        const __nv_bfloat16* er = d_ecat + (size_t)(n0 + row) * KC2 + koff + u * 8;
        cp_async16(base + T_BH + so, er);
        cp_async16(base + T_BL + so, er + 256);
    }
    cp_commit();
}

__global__ void __launch_bounds__(256, 2) k5_mma(const float* __restrict__ bias_e,
                                                 float* __restrict__ out) {
    extern __shared__ char smem[];
    const uint32_t sb = smem_u32(smem);
    int tid = threadIdx.x, lane = tid & 31, wid = tid >> 5;
    int wm = wid & 1, wn = wid >> 1;                 // 2(m) x 4(n)
    int m0 = blockIdx.x * 64, n0 = blockIdx.y * 128;

    float acc[2][4][4];
    #pragma unroll
    for (int f = 0; f < 2; f++)
        #pragma unroll
        for (int h = 0; h < 4; h++)
            #pragma unroll
            for (int i = 0; i < 4; i++) acc[f][h][i] = 0.f;

    k5_load(sb, 0, 0, m0, n0, tid);

    for (int ks = 0; ks < 4; ks++) {
        int buf = ks & 1;
        if (ks < 3) {
            k5_load(sb, buf ^ 1, ks + 1, m0, n0, tid);
            asm volatile("cp.async.wait_group 1;" ::: "memory");
        } else {
            asm volatile("cp.async.wait_group 0;" ::: "memory");
        }
        __syncthreads();

        const int scount = (ks < 3) ? 4 : 1;
        const uint32_t st = sb + buf * ST_STRIDE;
        #pragma unroll
        for (int pass = 0; pass < 3; pass++) {
            uint32_t abase = st + (pass == 1 ? T_AL : T_AH);
            uint32_t bbase = st + (pass == 2 ? T_BL : T_BH);
            for (int s = 0; s < scount; s++) {
                uint32_t a[2][4];
                #pragma unroll
                for (int f = 0; f < 2; f++) {
                    int row = wm * 32 + f * 16 + (lane & 15);
                    int u = s * 2 + (lane >> 4);
                    ldm4(a[f], abase + swz(row * 128 + u * 16));
                }
                #pragma unroll
                for (int j = 0; j < 2; j++) {
                    uint32_t b[4];
                    int row = wn * 32 + j * 16 + ((lane >> 4) << 3) + (lane & 7);
                    int u = s * 2 + ((lane >> 3) & 1);
                    ldm4(b, bbase + swz(row * 128 + u * 16));
                    #pragma unroll
                    for (int g = 0; g < 2; g++)
                        #pragma unroll
                        for (int f = 0; f < 2; f++)
                            mma16816(acc[f][j * 2 + g], a[f], b + g * 2);
                }
            }
        }
        __syncthreads();
    }

    // epilogue: c-frag (m16n8): c0,c1 row g cols 2q,2q+1; c2,c3 row g+8
    int g = lane >> 2, q = lane & 3;
    #pragma unroll
    for (int f = 0; f < 2; f++) {
        int mrow = m0 + wm * 32 + f * 16 + g;
        #pragma unroll
        for (int h = 0; h < 4; h++) {
            int n = n0 + wn * 32 + h * 8 + q * 2;
            if (n < NUM_ENT) {
                float b0 = bias_e[n], b1 = bias_e[n + 1];
                float v0 = acc[f][h][0] + b0, v1 = acc[f][h][1] + b1;
                float v2 = acc[f][h][2] + b0, v3 = acc[f][h][3] + b1;
                *(float2*)&out[(size_t)mrow * NUM_ENT + n] =
                    make_float2(1.f / (1.f + __expf(-v0)), 1.f / (1.f + __expf(-v1)));
                *(float2*)&out[(size_t)(mrow + 8) * NUM_ENT + n] =
                    make_float2(1.f / (1.f + __expf(-v2)), 1.f / (1.f + __expf(-v3)));
            }
        }
    }
}

// ---------------- launcher ----------------
extern "C" void kernel_launch(void* const* d_in, const int* in_sizes, int n_in,
                              void* d_out, int out_size) {
    const int*   e1     = (const int*)d_in[0];
    const int*   rel    = (const int*)d_in[1];
    const float* emb    = (const float*)d_in[2];
    const float* conv_w = (const float*)d_in[3];
    const float* conv_b = (const float*)d_in[4];
    const float* g0     = (const float*)d_in[5];
    const float* b0     = (const float*)d_in[6];
    const float* g1     = (const float*)d_in[7];
    const float* b1     = (const float*)d_in[8];
    const float* g2     = (const float*)d_in[9];
    const float* b2     = (const float*)d_in[10];
    const float* fc_w   = (const float*)d_in[11];
    // d_in[12] = fc_b: cancels exactly under training-mode bn2
    const float* bias_e = (const float*)d_in[13];
    float* out = (float*)d_out;

    cudaFuncSetAttribute(k3_fc,  cudaFuncAttributeMaxDynamicSharedMemorySize, FC_SMEM);
    cudaFuncSetAttribute(k5_mma, cudaFuncAttributeMaxDynamicSharedMemorySize, K5_SMEM);

    k4b_ecat<<<N_GRID, 256>>>(emb);
    k0_zero<<<800, 256>>>();
    k1_bn0<<<16, 512>>>(e1, emb);
    k1b_bn0fin<<<1, 1>>>(g0, b0);
    k2_conv<<<B, 256>>>(e1, rel, emb, conv_w, conv_b);
    k3a_bn1<<<1, 32>>>(g1, b1);
    k3_fc<<<dim3(2, 8, 12), 256, FC_SMEM>>>(fc_w);
    k4_bn2<<<EDIM, 256>>>(g2, b2);
    k5_mma<<<dim3(8, N_GRID), 256, K5_SMEM>>>(bias_e, out);
}

// round 7
// speedup vs baseline: 1.6629x; 1.3002x over previous
#include <cuda_runtime.h>
#include <cuda_bf16.h>
#include <cuda_fp16.h>
#include <cstdint>

#define B 512
#define EDIM 200
#define NUM_ENT 100000
#define FDIM 4608          // 32*8*18
#define EPS 1e-5f
#define KH 256             // fp16 K padded 200 -> 256
#define ENT_TILE 128
#define N_GRID ((NUM_ENT + ENT_TILE - 1) / ENT_TILE)   // 782
#define ENT_PAD (N_GRID * ENT_TILE)                    // 100096

// ---------------- device scratch (static allocations only) ----------------
__device__ float d_y[B * FDIM];            // conv output, pre-bn1
__device__ float d_h[B * EDIM];            // fc output, pre-bn2
__device__ __half d_zcat[B * KH];          // [batch][256] fp16 z (cols 200.. zero)
__device__ __half d_ecat[ENT_PAD * KH];    // [ent][256]  fp16 e (pad zero)
__device__ float d_chsum[32];
__device__ float d_chsq[32];
__device__ float d_bn0acc[2];              // {sum, sumsq} partials
__device__ float d_bn0[2];                 // {scale, shift}
__device__ float d_bn1a[32];
__device__ float d_bn1c[32];

// ---------------- PTX helpers (sm_80-compatible subset only) ----------------
__device__ __forceinline__ uint32_t smem_u32(const void* p) {
    uint32_t a;
    asm("{ .reg .u64 t; cvta.to.shared.u64 t, %1; cvt.u32.u64 %0, t; }" : "=r"(a) : "l"(p));
    return a;
}
__device__ __forceinline__ void cp_async16(uint32_t dst, const void* src) {
    asm volatile("cp.async.cg.shared.global [%0], [%1], 16;" :: "r"(dst), "l"(src) : "memory");
}
__device__ __forceinline__ void cp_commit() {
    asm volatile("cp.async.commit_group;" ::: "memory");
}
__device__ __forceinline__ void ldm4(uint32_t* r, uint32_t a) {
    asm volatile("ldmatrix.sync.aligned.m8n8.x4.shared.b16 {%0,%1,%2,%3}, [%4];"
                 : "=r"(r[0]), "=r"(r[1]), "=r"(r[2]), "=r"(r[3]) : "r"(a));
}
__device__ __forceinline__ void mma16816h(float* d, const uint32_t* a, const uint32_t* b) {
    asm volatile("mma.sync.aligned.m16n8k16.row.col.f32.f16.f16.f32 "
                 "{%0,%1,%2,%3}, {%4,%5,%6,%7}, {%8,%9}, {%0,%1,%2,%3};"
                 : "+f"(d[0]), "+f"(d[1]), "+f"(d[2]), "+f"(d[3])
                 : "r"(a[0]), "r"(a[1]), "r"(a[2]), "r"(a[3]), "r"(b[0]), "r"(b[1]));
}
__device__ __forceinline__ uint32_t swz(uint32_t off) { return off ^ ((off >> 3) & 0x70); }
__device__ __forceinline__ uint32_t pack_h2(__half a, __half b) {
    return (uint32_t)__half_as_ushort(a) | ((uint32_t)__half_as_ushort(b) << 16);
}

// ---------------- K0: zero accumulators ----------------
__global__ void k0_zero() {
    int i = blockIdx.x * blockDim.x + threadIdx.x;
    if (i < B * EDIM) d_h[i] = 0.f;
    if (i < B * KH / 2) ((uint32_t*)d_zcat)[i] = 0u;
    if (i < 32) { d_chsum[i] = 0.f; d_chsq[i] = 0.f; }
    if (i < 2) d_bn0acc[i] = 0.f;
}

// ---------------- K1: bn0 stats (multi-CTA) ----------------
__global__ void k1_bn0(const int* __restrict__ e1, const float* __restrict__ emb) {
    int tid = threadIdx.x, lane = tid & 31;
    float s = 0.f, q = 0.f;
    for (int idx = blockIdx.x * 512 + tid; idx < B * EDIM; idx += gridDim.x * 512) {
        int b = idx / EDIM, j = idx - b * EDIM;
        float v = emb[(size_t)e1[b] * EDIM + j];
        s += v; q += v * v;
    }
    #pragma unroll
    for (int o = 16; o; o >>= 1) {
        s += __shfl_down_sync(0xffffffffu, s, o);
        q += __shfl_down_sync(0xffffffffu, q, o);
    }
    if (lane == 0) { atomicAdd(&d_bn0acc[0], s); atomicAdd(&d_bn0acc[1], q); }
}
__global__ void k1b_bn0fin(const float* __restrict__ g0, const float* __restrict__ b0) {
    const float inv = 1.f / (float)(B * EDIM);
    float m = d_bn0acc[0] * inv;
    float var = d_bn0acc[1] * inv - m * m;
    float sc = rsqrtf(var + EPS) * g0[0];
    d_bn0[0] = sc;
    d_bn0[1] = b0[0] - m * sc;
}

// ---------------- K2: relation-indexed 3x3 conv ----------------
__global__ void k2_conv(const int* __restrict__ e1, const int* __restrict__ rel,
                        const float* __restrict__ emb,
                        const float* __restrict__ conv_w, const float* __restrict__ conv_b) {
    __shared__ float sx[200];
    __shared__ float sw[288];
    __shared__ float scb[32];
    int b = blockIdx.x;
    int tid = threadIdx.x;
    int r = rel[b];
    float bn_s = d_bn0[0], bn_b = d_bn0[1];
    if (tid < 200) sx[tid] = fmaf(emb[(size_t)e1[b] * EDIM + tid], bn_s, bn_b);
    for (int i = tid; i < 288; i += 256) sw[i] = conv_w[(size_t)r * 288 + i];
    if (tid < 32) scb[tid] = conv_b[(size_t)r * 32 + tid];
    __syncthreads();

    int o = tid >> 3;
    int i = tid & 7;
    const float* w = &sw[o * 9];
    float cb = scb[o];
    float ls = 0.f, lq = 0.f;
    float* yrow = &d_y[(size_t)b * FDIM + o * 144 + i * 18];
    #pragma unroll
    for (int j = 0; j < 18; j++) {
        float acc = cb;
        #pragma unroll
        for (int di = 0; di < 3; di++)
            #pragma unroll
            for (int dj = 0; dj < 3; dj++)
                acc = fmaf(sx[(i + di) * 20 + (j + dj)], w[di * 3 + dj], acc);
        yrow[j] = acc;
        ls += acc; lq += acc * acc;
    }
    #pragma unroll
    for (int off = 4; off; off >>= 1) {
        ls += __shfl_down_sync(0xffffffffu, ls, off, 8);
        lq += __shfl_down_sync(0xffffffffu, lq, off, 8);
    }
    if ((tid & 7) == 0) {
        atomicAdd(&d_chsum[o], ls);
        atomicAdd(&d_chsq[o], lq);
    }
}

// ---------------- K3a: bn1 affine ----------------
__global__ void k3a_bn1(const float* __restrict__ g1, const float* __restrict__ b1) {
    int c = threadIdx.x;
    if (c < 32) {
        const float inv = 1.f / (float)(B * 144);
        float m = d_chsum[c] * inv;
        float var = d_chsq[c] * inv - m * m;
        float a = rsqrtf(var + EPS) * g1[c];
        d_bn1a[c] = a;
        d_bn1c[c] = b1[c] - m * a;
    }
}

// ---------------- K3: fc GEMM (fp32 SIMT, 12 k-splits x 3 inner chunks) ----------------
#define FC_SY_STRIDE 68
#define FC_SW_STRIDE 132
#define FC_SMEM ((128*FC_SY_STRIDE + 128*FC_SW_STRIDE) * 4)
__global__ void __launch_bounds__(256) k3_fc(const float* __restrict__ fc_w) {
    extern __shared__ float sm[];
    float* s_y = sm;
    float* s_w = sm + 128 * FC_SY_STRIDE;
    __shared__ float s_a[32], s_c[32];

    int tid = threadIdx.x;
    int n0 = blockIdx.x * 128, m0 = blockIdx.y * 64;
    if (tid < 32) { s_a[tid] = d_bn1a[tid]; s_c[tid] = d_bn1c[tid]; }

    int mg = (tid & 15) * 4;
    int ng = (tid >> 4) * 8;
    float acc[32];
    #pragma unroll
    for (int i = 0; i < 32; i++) acc[i] = 0.f;

    for (int cc = 0; cc < 3; cc++) {
        int k0 = blockIdx.z * 384 + cc * 128;
        __syncthreads();
        #pragma unroll
        for (int i = 0; i < 8; i++) {
            int p = tid + i * 256;
            int m = p >> 5, c4 = p & 31;
            float4 v = *(const float4*)&d_y[(size_t)(m0 + m) * FDIM + k0 + c4 * 4];
            int kk = k0 + c4 * 4;
            int ch0 = kk / 144, ch1 = (kk + 1) / 144, ch2 = (kk + 2) / 144, ch3 = (kk + 3) / 144;
            s_y[(c4 * 4 + 0) * FC_SY_STRIDE + m] = fmaxf(fmaf(v.x, s_a[ch0], s_c[ch0]), 0.f);
            s_y[(c4 * 4 + 1) * FC_SY_STRIDE + m] = fmaxf(fmaf(v.y, s_a[ch1], s_c[ch1]), 0.f);
            s_y[(c4 * 4 + 2) * FC_SY_STRIDE + m] = fmaxf(fmaf(v.z, s_a[ch2], s_c[ch2]), 0.f);
            s_y[(c4 * 4 + 3) * FC_SY_STRIDE + m] = fmaxf(fmaf(v.w, s_a[ch3], s_c[ch3]), 0.f);
        }
        #pragma unroll
        for (int i = 0; i < 16; i++) {
            int p = tid + i * 256;
            int n = p >> 5, c4 = p & 31;
            float4 v = make_float4(0.f, 0.f, 0.f, 0.f);
            if (n0 + n < EDIM) v = *(const float4*)&fc_w[(size_t)(n0 + n) * FDIM + k0 + c4 * 4];
            s_w[(c4 * 4 + 0) * FC_SW_STRIDE + n] = v.x;
            s_w[(c4 * 4 + 1) * FC_SW_STRIDE + n] = v.y;
            s_w[(c4 * 4 + 2) * FC_SW_STRIDE + n] = v.z;
            s_w[(c4 * 4 + 3) * FC_SW_STRIDE + n] = v.w;
        }
        __syncthreads();

        #pragma unroll 8
        for (int k = 0; k < 128; k++) {
            float4 z = *(const float4*)(s_y + k * FC_SY_STRIDE + mg);
            float4 ea = *(const float4*)(s_w + k * FC_SW_STRIDE + ng);
            float4 eb = *(const float4*)(s_w + k * FC_SW_STRIDE + ng + 4);
            float zz[4] = {z.x, z.y, z.z, z.w};
            float ee[8] = {ea.x, ea.y, ea.z, ea.w, eb.x, eb.y, eb.z, eb.w};
            #pragma unroll
            for (int mi = 0; mi < 4; mi++)
                #pragma unroll
                for (int nj = 0; nj < 8; nj++)
                    acc[mi * 8 + nj] = fmaf(zz[mi], ee[nj], acc[mi * 8 + nj]);
        }
    }

    #pragma unroll
    for (int mi = 0; mi < 4; mi++)
        #pragma unroll
        for (int nj = 0; nj < 8; nj++) {
            int n = n0 + ng + nj;
            if (n < EDIM)
                atomicAdd(&d_h[(size_t)(m0 + mg + mi) * EDIM + n], acc[mi * 8 + nj]);
        }
}

// ---------------- K4: bn2 + relu, emit fp16 z ----------------
__global__ void k4_bn2(const float* __restrict__ g2, const float* __restrict__ b2) {
    int n = blockIdx.x;        // feature 0..199
    int t = threadIdx.x;       // 256
    float v0 = d_h[(size_t)t * EDIM + n];
    float v1 = d_h[(size_t)(t + 256) * EDIM + n];
    __shared__ float rs[256], rq[256];
    rs[t] = v0 + v1; rq[t] = v0 * v0 + v1 * v1;
    __syncthreads();
    for (int o = 128; o; o >>= 1) {
        if (t < o) { rs[t] += rs[t + o]; rq[t] += rq[t + o]; }
        __syncthreads();
    }
    __shared__ float sa, sc;
    if (t == 0) {
        float m = rs[0] * (1.f / 512.f);
        float var = rq[0] * (1.f / 512.f) - m * m;
        float a = rsqrtf(var + EPS) * g2[n];
        sa = a; sc = b2[n] - m * a;
    }
    __syncthreads();
    float z0 = fmaxf(fmaf(v0, sa, sc), 0.f);
    float z1 = fmaxf(fmaf(v1, sa, sc), 0.f);
    d_zcat[(size_t)t * KH + n]         = __float2half(z0);
    d_zcat[(size_t)(t + 256) * KH + n] = __float2half(z1);
}

// ---------------- K4b: build fp16 e rows [ent][256], coalesced ----------------
__global__ void __launch_bounds__(256) k4b_ecat(const float* __restrict__ emb) {
    int warp = threadIdx.x >> 5, lane = threadIdx.x & 31;
    int row0 = blockIdx.x * 128;
    #pragma unroll 4
    for (int it = 0; it < 16; it++) {
        int row = row0 + warp + it * 8;
        bool rv = (row < NUM_ENT) && (lane < 25);     // 25*8 = 200 cols
        float4 f0 = make_float4(0.f, 0.f, 0.f, 0.f);
        float4 f1 = make_float4(0.f, 0.f, 0.f, 0.f);
        if (rv) {
            const float* src = emb + (size_t)row * EDIM + lane * 8;
            f0 = *(const float4*)src;
            f1 = *(const float4*)(src + 4);
        }
        uint32_t p0 = pack_h2(__float2half(f0.x), __float2half(f0.y));
        uint32_t p1 = pack_h2(__float2half(f0.z), __float2half(f0.w));
        uint32_t p2 = pack_h2(__float2half(f1.x), __float2half(f1.y));
        uint32_t p3 = pack_h2(__float2half(f1.z), __float2half(f1.w));
        *(uint4*)(d_ecat + (size_t)row * KH + lane * 8) = make_uint4(p0, p1, p2, p3);
    }
}

// ---------------- K5: fp16 mma.sync GEMM + bias + sigmoid (single pass) ----------------
// CTA tile: M=64 (batch) x N=128 (ent); 8 warps as 2(m) x 4(n), warp tile 32x32.
// K=256 in 4 quarters of 64 fp16 (128B rows); quarter 3 has only 8 real cols -> 1 k16 step.
// Double-buffered, prefetch-before-wait. 48KB smem -> 2+ CTAs/SM.
#define T_A 0
#define T_B 8192
#define ST_STRIDE 24576
#define K5_SMEM (2 * ST_STRIDE)

__device__ __forceinline__ void k5_load(uint32_t sb, int buf, int ks, int m0, int n0, int tid) {
    uint32_t base = sb + buf * ST_STRIDE;
    int koff = ks * 64;
    #pragma unroll
    for (int i = 0; i < 2; i++) {                    // A: 64 rows x 128B
        int idx = tid + i * 256;
        int row = idx >> 3, u = idx & 7;
        cp_async16(base + T_A + swz(row * 128 + u * 16),
                   d_zcat + (size_t)(m0 + row) * KH + koff + u * 8);
    }
    #pragma unroll
    for (int i = 0; i < 4; i++) {                    // B: 128 rows x 128B
        int idx = tid + i * 256;
        int row = idx >> 3, u = idx & 7;
        cp_async16(base + T_B + swz(row * 128 + u * 16),
                   d_ecat + (size_t)(n0 + row) * KH + koff + u * 8);
    }
    cp_commit();
}

__global__ void __launch_bounds__(256, 2) k5_mma(const float* __restrict__ bias_e,
                                                 float* __restrict__ out) {
    extern __shared__ char smem[];
    const uint32_t sb = smem_u32(smem);
    int tid = threadIdx.x, lane = tid & 31, wid = tid >> 5;
    int wm = wid & 1, wn = wid >> 1;                 // 2(m) x 4(n)
    int m0 = blockIdx.x * 64, n0 = blockIdx.y * 128;

    float acc[2][4][4];
    #pragma unroll
    for (int f = 0; f < 2; f++)
        #pragma unroll
        for (int h = 0; h < 4; h++)
            #pragma unroll
            for (int i = 0; i < 4; i++) acc[f][h][i] = 0.f;

    k5_load(sb, 0, 0, m0, n0, tid);

    for (int ks = 0; ks < 4; ks++) {
        int buf = ks & 1;
        if (ks < 3) {
            k5_load(sb, buf ^ 1, ks + 1, m0, n0, tid);
            asm volatile("cp.async.wait_group 1;" ::: "memory");
        } else {
            asm volatile("cp.async.wait_group 0;" ::: "memory");
        }
        __syncthreads();

        const int scount = (ks < 3) ? 4 : 1;         // quarter 3: cols 192..199 only
        const uint32_t st = sb + buf * ST_STRIDE;
        for (int s = 0; s < scount; s++) {
            uint32_t a[2][4];
            #pragma unroll
            for (int f = 0; f < 2; f++) {
                int row = wm * 32 + f * 16 + (lane & 15);
                int u = s * 2 + (lane >> 4);
                ldm4(a[f], st + T_A + swz(row * 128 + u * 16));
            }
            #pragma unroll
            for (int j = 0; j < 2; j++) {
                uint32_t b[4];
                int row = wn * 32 + j * 16 + ((lane >> 4) << 3) + (lane & 7);
                int u = s * 2 + ((lane >> 3) & 1);
                ldm4(b, st + T_B + swz(row * 128 + u * 16));
                #pragma unroll
                for (int g = 0; g < 2; g++)
                    #pragma unroll
                    for (int f = 0; f < 2; f++)
                        mma16816h(acc[f][j * 2 + g], a[f], b + g * 2);
            }
        }
        __syncthreads();
    }

    // epilogue: c-frag (m16n8): c0,c1 row g cols 2q,2q+1; c2,c3 row g+8
    int g = lane >> 2, q = lane & 3;
    #pragma unroll
    for (int f = 0; f < 2; f++) {
        int mrow = m0 + wm * 32 + f * 16 + g;
        #pragma unroll
        for (int h = 0; h < 4; h++) {
            int n = n0 + wn * 32 + h * 8 + q * 2;
            if (n < NUM_ENT) {
                float b0 = bias_e[n], b1 = bias_e[n + 1];
                float v0 = acc[f][h][0] + b0, v1 = acc[f][h][1] + b1;
                float v2 = acc[f][h][2] + b0, v3 = acc[f][h][3] + b1;
                *(float2*)&out[(size_t)mrow * NUM_ENT + n] =
                    make_float2(1.f / (1.f + __expf(-v0)), 1.f / (1.f + __expf(-v1)));
                *(float2*)&out[(size_t)(mrow + 8) * NUM_ENT + n] =
                    make_float2(1.f / (1.f + __expf(-v2)), 1.f / (1.f + __expf(-v3)));
            }
        }
    }
}

// ---------------- launcher ----------------
extern "C" void kernel_launch(void* const* d_in, const int* in_sizes, int n_in,
                              void* d_out, int out_size) {
    const int*   e1     = (const int*)d_in[0];
    const int*   rel    = (const int*)d_in[1];
    const float* emb    = (const float*)d_in[2];
    const float* conv_w = (const float*)d_in[3];
    const float* conv_b = (const float*)d_in[4];
    const float* g0     = (const float*)d_in[5];
    const float* b0     = (const float*)d_in[6];
    const float* g1     = (const float*)d_in[7];
    const float* b1     = (const float*)d_in[8];
    const float* g2     = (const float*)d_in[9];
    const float* b2     = (const float*)d_in[10];
    const float* fc_w   = (const float*)d_in[11];
    // d_in[12] = fc_b: cancels exactly under training-mode bn2
    const float* bias_e = (const float*)d_in[13];
    float* out = (float*)d_out;

    cudaFuncSetAttribute(k3_fc,  cudaFuncAttributeMaxDynamicSharedMemorySize, FC_SMEM);
    cudaFuncSetAttribute(k5_mma, cudaFuncAttributeMaxDynamicSharedMemorySize, K5_SMEM);

    k4b_ecat<<<N_GRID, 256>>>(emb);
    k0_zero<<<800, 256>>>();
    k1_bn0<<<16, 512>>>(e1, emb);
    k1b_bn0fin<<<1, 1>>>(g0, b0);
    k2_conv<<<B, 256>>>(e1, rel, emb, conv_w, conv_b);
    k3a_bn1<<<1, 32>>>(g1, b1);
    k3_fc<<<dim3(2, 8, 12), 256, FC_SMEM>>>(fc_w);
    k4_bn2<<<EDIM, 256>>>(g2, b2);
    k5_mma<<<dim3(8, N_GRID), 256, K5_SMEM>>>(bias_e, out);
}

// round 8
// speedup vs baseline: 1.7619x; 1.0595x over previous
#include <cuda_runtime.h>
#include <cuda_bf16.h>
#include <cuda_fp16.h>
#include <cstdint>

#define B 512
#define EDIM 200
#define NUM_ENT 100000
#define FDIM 4608          // 32*8*18
#define EPS 1e-5f
#define KH 256             // fp16 K padded 200 -> 256
#define ENT_TILE 256
#define N_GRID ((NUM_ENT + ENT_TILE - 1) / ENT_TILE)   // 391
#define ENT_PAD (N_GRID * ENT_TILE)                    // 100096
#define EC_GRID (ENT_PAD / 128)                        // 782

// ---------------- device scratch (static allocations only) ----------------
__device__ float d_y[B * FDIM];            // conv output, pre-bn1
__device__ float d_h[B * EDIM];            // fc output, pre-bn2
__device__ __half d_zcat[B * KH];          // [batch][256] fp16 z (cols 200.. zero)
__device__ __half d_ecat[ENT_PAD * KH];    // [ent][256]  fp16 e (pad zero)
__device__ float d_chsum[32];
__device__ float d_chsq[32];
__device__ float d_bn0acc[2];              // {sum, sumsq} partials

// ---------------- PTX helpers (sm_80-compatible subset only) ----------------
__device__ __forceinline__ uint32_t smem_u32(const void* p) {
    uint32_t a;
    asm("{ .reg .u64 t; cvta.to.shared.u64 t, %1; cvt.u32.u64 %0, t; }" : "=r"(a) : "l"(p));
    return a;
}
__device__ __forceinline__ void cp_async16(uint32_t dst, const void* src) {
    asm volatile("cp.async.cg.shared.global [%0], [%1], 16;" :: "r"(dst), "l"(src) : "memory");
}
__device__ __forceinline__ void cp_commit() {
    asm volatile("cp.async.commit_group;" ::: "memory");
}
__device__ __forceinline__ void ldm4(uint32_t* r, uint32_t a) {
    asm volatile("ldmatrix.sync.aligned.m8n8.x4.shared.b16 {%0,%1,%2,%3}, [%4];"
                 : "=r"(r[0]), "=r"(r[1]), "=r"(r[2]), "=r"(r[3]) : "r"(a));
}
__device__ __forceinline__ void mma16816h(float* d, const uint32_t* a, const uint32_t* b) {
    asm volatile("mma.sync.aligned.m16n8k16.row.col.f32.f16.f16.f32 "
                 "{%0,%1,%2,%3}, {%4,%5,%6,%7}, {%8,%9}, {%0,%1,%2,%3};"
                 : "+f"(d[0]), "+f"(d[1]), "+f"(d[2]), "+f"(d[3])
                 : "r"(a[0]), "r"(a[1]), "r"(a[2]), "r"(a[3]), "r"(b[0]), "r"(b[1]));
}
__device__ __forceinline__ uint32_t swz(uint32_t off) { return off ^ ((off >> 3) & 0x70); }
__device__ __forceinline__ uint32_t pack_h2(__half a, __half b) {
    return (uint32_t)__half_as_ushort(a) | ((uint32_t)__half_as_ushort(b) << 16);
}

// ---------------- K4b (launch 1): build fp16 e rows + zero all accumulators ----------------
__global__ void __launch_bounds__(256) k4b_ecat(const float* __restrict__ emb) {
    // fused zeroing (replaces k0_zero)
    int gi = blockIdx.x * 256 + threadIdx.x;
    if (gi < B * EDIM) d_h[gi] = 0.f;
    if (gi < B * KH / 2) ((uint32_t*)d_zcat)[gi] = 0u;
    if (gi < 32) { d_chsum[gi] = 0.f; d_chsq[gi] = 0.f; }
    if (gi < 2) d_bn0acc[gi] = 0.f;

    int warp = threadIdx.x >> 5, lane = threadIdx.x & 31;
    int row0 = blockIdx.x * 128;
    #pragma unroll 4
    for (int it = 0; it < 16; it++) {
        int row = row0 + warp + it * 8;
        bool rv = (row < NUM_ENT) && (lane < 25);     // 25*8 = 200 cols
        float4 f0 = make_float4(0.f, 0.f, 0.f, 0.f);
        float4 f1 = make_float4(0.f, 0.f, 0.f, 0.f);
        if (rv) {
            const float* src = emb + (size_t)row * EDIM + lane * 8;
            f0 = *(const float4*)src;
            f1 = *(const float4*)(src + 4);
        }
        uint32_t p0 = pack_h2(__float2half(f0.x), __float2half(f0.y));
        uint32_t p1 = pack_h2(__float2half(f0.z), __float2half(f0.w));
        uint32_t p2 = pack_h2(__float2half(f1.x), __float2half(f1.y));
        uint32_t p3 = pack_h2(__float2half(f1.z), __float2half(f1.w));
        *(uint4*)(d_ecat + (size_t)row * KH + lane * 8) = make_uint4(p0, p1, p2, p3);
    }
}

// ---------------- K1 (launch 2): bn0 stats (multi-CTA) ----------------
__global__ void k1_bn0(const int* __restrict__ e1, const float* __restrict__ emb) {
    int tid = threadIdx.x, lane = tid & 31;
    float s = 0.f, q = 0.f;
    for (int idx = blockIdx.x * 512 + tid; idx < B * EDIM; idx += gridDim.x * 512) {
        int b = idx / EDIM, j = idx - b * EDIM;
        float v = emb[(size_t)e1[b] * EDIM + j];
        s += v; q += v * v;
    }
    #pragma unroll
    for (int o = 16; o; o >>= 1) {
        s += __shfl_down_sync(0xffffffffu, s, o);
        q += __shfl_down_sync(0xffffffffu, q, o);
    }
    if (lane == 0) { atomicAdd(&d_bn0acc[0], s); atomicAdd(&d_bn0acc[1], q); }
}

// ---------------- K2 (launch 3): conv, bn0 affine derived per block ----------------
__global__ void k2_conv(const int* __restrict__ e1, const int* __restrict__ rel,
                        const float* __restrict__ emb,
                        const float* __restrict__ conv_w, const float* __restrict__ conv_b,
                        const float* __restrict__ g0, const float* __restrict__ b0) {
    __shared__ float sx[200];
    __shared__ float sw[288];
    __shared__ float scb[32];
    int b = blockIdx.x;
    int tid = threadIdx.x;
    int r = rel[b];
    // bn0 affine from accumulators (replaces k1b)
    const float inv0 = 1.f / (float)(B * EDIM);
    float m0v = d_bn0acc[0] * inv0;
    float var0 = d_bn0acc[1] * inv0 - m0v * m0v;
    float bn_s = rsqrtf(var0 + EPS) * g0[0];
    float bn_b = b0[0] - m0v * bn_s;

    if (tid < 200) sx[tid] = fmaf(emb[(size_t)e1[b] * EDIM + tid], bn_s, bn_b);
    for (int i = tid; i < 288; i += 256) sw[i] = conv_w[(size_t)r * 288 + i];
    if (tid < 32) scb[tid] = conv_b[(size_t)r * 32 + tid];
    __syncthreads();

    int o = tid >> 3;
    int i = tid & 7;
    const float* w = &sw[o * 9];
    float cb = scb[o];
    float ls = 0.f, lq = 0.f;
    float* yrow = &d_y[(size_t)b * FDIM + o * 144 + i * 18];
    #pragma unroll
    for (int j = 0; j < 18; j++) {
        float acc = cb;
        #pragma unroll
        for (int di = 0; di < 3; di++)
            #pragma unroll
            for (int dj = 0; dj < 3; dj++)
                acc = fmaf(sx[(i + di) * 20 + (j + dj)], w[di * 3 + dj], acc);
        yrow[j] = acc;
        ls += acc; lq += acc * acc;
    }
    #pragma unroll
    for (int off = 4; off; off >>= 1) {
        ls += __shfl_down_sync(0xffffffffu, ls, off, 8);
        lq += __shfl_down_sync(0xffffffffu, lq, off, 8);
    }
    if ((tid & 7) == 0) {
        atomicAdd(&d_chsum[o], ls);
        atomicAdd(&d_chsq[o], lq);
    }
}

// ---------------- K3 (launch 4): fc GEMM, bn1 affine derived in-block ----------------
#define FC_SY_STRIDE 68
#define FC_SW_STRIDE 132
#define FC_SMEM ((128*FC_SY_STRIDE + 128*FC_SW_STRIDE) * 4)
__global__ void __launch_bounds__(256) k3_fc(const float* __restrict__ fc_w,
                                             const float* __restrict__ g1,
                                             const float* __restrict__ b1) {
    extern __shared__ float sm[];
    float* s_y = sm;
    float* s_w = sm + 128 * FC_SY_STRIDE;
    __shared__ float s_a[32], s_c[32];

    int tid = threadIdx.x;
    int n0 = blockIdx.x * 128, m0 = blockIdx.y * 64;
    if (tid < 32) {        // bn1 affine from accumulators (replaces k3a)
        const float inv = 1.f / (float)(B * 144);
        float m = d_chsum[tid] * inv;
        float var = d_chsq[tid] * inv - m * m;
        float a = rsqrtf(var + EPS) * g1[tid];
        s_a[tid] = a;
        s_c[tid] = b1[tid] - m * a;
    }

    int mg = (tid & 15) * 4;
    int ng = (tid >> 4) * 8;
    float acc[32];
    #pragma unroll
    for (int i = 0; i < 32; i++) acc[i] = 0.f;

    for (int cc = 0; cc < 3; cc++) {
        int k0 = blockIdx.z * 384 + cc * 128;
        __syncthreads();
        #pragma unroll
        for (int i = 0; i < 8; i++) {
            int p = tid + i * 256;
            int m = p >> 5, c4 = p & 31;
            float4 v = *(const float4*)&d_y[(size_t)(m0 + m) * FDIM + k0 + c4 * 4];
            int kk = k0 + c4 * 4;
            int ch0 = kk / 144, ch1 = (kk + 1) / 144, ch2 = (kk + 2) / 144, ch3 = (kk + 3) / 144;
            s_y[(c4 * 4 + 0) * FC_SY_STRIDE + m] = fmaxf(fmaf(v.x, s_a[ch0], s_c[ch0]), 0.f);
            s_y[(c4 * 4 + 1) * FC_SY_STRIDE + m] = fmaxf(fmaf(v.y, s_a[ch1], s_c[ch1]), 0.f);
            s_y[(c4 * 4 + 2) * FC_SY_STRIDE + m] = fmaxf(fmaf(v.z, s_a[ch2], s_c[ch2]), 0.f);
            s_y[(c4 * 4 + 3) * FC_SY_STRIDE + m] = fmaxf(fmaf(v.w, s_a[ch3], s_c[ch3]), 0.f);
        }
        #pragma unroll
        for (int i = 0; i < 16; i++) {
            int p = tid + i * 256;
            int n = p >> 5, c4 = p & 31;
            float4 v = make_float4(0.f, 0.f, 0.f, 0.f);
            if (n0 + n < EDIM) v = *(const float4*)&fc_w[(size_t)(n0 + n) * FDIM + k0 + c4 * 4];
            s_w[(c4 * 4 + 0) * FC_SW_STRIDE + n] = v.x;
            s_w[(c4 * 4 + 1) * FC_SW_STRIDE + n] = v.y;
            s_w[(c4 * 4 + 2) * FC_SW_STRIDE + n] = v.z;
            s_w[(c4 * 4 + 3) * FC_SW_STRIDE + n] = v.w;
        }
        __syncthreads();

        #pragma unroll 8
        for (int k = 0; k < 128; k++) {
            float4 z = *(const float4*)(s_y + k * FC_SY_STRIDE + mg);
            float4 ea = *(const float4*)(s_w + k * FC_SW_STRIDE + ng);
            float4 eb = *(const float4*)(s_w + k * FC_SW_STRIDE + ng + 4);
            float zz[4] = {z.x, z.y, z.z, z.w};
            float ee[8] = {ea.x, ea.y, ea.z, ea.w, eb.x, eb.y, eb.z, eb.w};
            #pragma unroll
            for (int mi = 0; mi < 4; mi++)
                #pragma unroll
                for (int nj = 0; nj < 8; nj++)
                    acc[mi * 8 + nj] = fmaf(zz[mi], ee[nj], acc[mi * 8 + nj]);
        }
    }

    #pragma unroll
    for (int mi = 0; mi < 4; mi++)
        #pragma unroll
        for (int nj = 0; nj < 8; nj++) {
            int n = n0 + ng + nj;
            if (n < EDIM)
                atomicAdd(&d_h[(size_t)(m0 + mg + mi) * EDIM + n], acc[mi * 8 + nj]);
        }
}

// ---------------- K4 (launch 5): bn2 + relu, emit fp16 z ----------------
__global__ void k4_bn2(const float* __restrict__ g2, const float* __restrict__ b2) {
    int n = blockIdx.x;        // feature 0..199
    int t = threadIdx.x;       // 256
    float v0 = d_h[(size_t)t * EDIM + n];
    float v1 = d_h[(size_t)(t + 256) * EDIM + n];
    __shared__ float rs[256], rq[256];
    rs[t] = v0 + v1; rq[t] = v0 * v0 + v1 * v1;
    __syncthreads();
    for (int o = 128; o; o >>= 1) {
        if (t < o) { rs[t] += rs[t + o]; rq[t] += rq[t + o]; }
        __syncthreads();
    }
    __shared__ float sa, sc;
    if (t == 0) {
        float m = rs[0] * (1.f / 512.f);
        float var = rq[0] * (1.f / 512.f) - m * m;
        float a = rsqrtf(var + EPS) * g2[n];
        sa = a; sc = b2[n] - m * a;
    }
    __syncthreads();
    float z0 = fmaxf(fmaf(v0, sa, sc), 0.f);
    float z1 = fmaxf(fmaf(v1, sa, sc), 0.f);
    d_zcat[(size_t)t * KH + n]         = __float2half(z0);
    d_zcat[(size_t)(t + 256) * KH + n] = __float2half(z1);
}

// ---------------- K5 (launch 6): fp16 mma.sync GEMM + bias + sigmoid ----------------
// CTA tile: M=64 (batch) x N=256 (ent); 8 warps as 2(m) x 4(n), warp tile 32x64.
// K=256 in 4 quarters of 64 fp16; quarter 3 has 8 real cols -> 1 k16 step.
// Stage = A 8KB + B 32KB = 40KB, double-buffered 80KB -> 2 CTAs/SM.
#define T_A 0
#define T_B 8192
#define ST_STRIDE 40960
#define K5_SMEM (2 * ST_STRIDE)

__device__ __forceinline__ void k5_load(uint32_t sb, int buf, int ks, int m0, int n0, int tid) {
    uint32_t base = sb + buf * ST_STRIDE;
    int koff = ks * 64;
    #pragma unroll
    for (int i = 0; i < 2; i++) {                    // A: 64 rows x 128B
        int idx = tid + i * 256;
        int row = idx >> 3, u = idx & 7;
        cp_async16(base + T_A + swz(row * 128 + u * 16),
                   d_zcat + (size_t)(m0 + row) * KH + koff + u * 8);
    }
    #pragma unroll
    for (int i = 0; i < 8; i++) {                    // B: 256 rows x 128B
        int idx = tid + i * 256;
        int row = idx >> 3, u = idx & 7;
        cp_async16(base + T_B + swz(row * 128 + u * 16),
                   d_ecat + (size_t)(n0 + row) * KH + koff + u * 8);
    }
    cp_commit();
}

__global__ void __launch_bounds__(256, 2) k5_mma(const float* __restrict__ bias_e,
                                                 float* __restrict__ out) {
    extern __shared__ char smem[];
    const uint32_t sb = smem_u32(smem);
    int tid = threadIdx.x, lane = tid & 31, wid = tid >> 5;
    int wm = wid & 1, wn = wid >> 1;                 // 2(m) x 4(n)
    int m0 = blockIdx.x * 64, n0 = blockIdx.y * 256;

    float acc[2][8][4];
    #pragma unroll
    for (int f = 0; f < 2; f++)
        #pragma unroll
        for (int h = 0; h < 8; h++)
            #pragma unroll
            for (int i = 0; i < 4; i++) acc[f][h][i] = 0.f;

    k5_load(sb, 0, 0, m0, n0, tid);

    for (int ks = 0; ks < 4; ks++) {
        int buf = ks & 1;
        if (ks < 3) {
            k5_load(sb, buf ^ 1, ks + 1, m0, n0, tid);
            asm volatile("cp.async.wait_group 1;" ::: "memory");
        } else {
            asm volatile("cp.async.wait_group 0;" ::: "memory");
        }
        __syncthreads();

        const int scount = (ks < 3) ? 4 : 1;         // quarter 3: cols 192..199 only
        const uint32_t st = sb + buf * ST_STRIDE;
        for (int s = 0; s < scount; s++) {
            uint32_t a[2][4];
            #pragma unroll
            for (int f = 0; f < 2; f++) {
                int row = wm * 32 + f * 16 + (lane & 15);
                int u = s * 2 + (lane >> 4);
                ldm4(a[f], st + T_A + swz(row * 128 + u * 16));
            }
            #pragma unroll
            for (int j = 0; j < 4; j++) {
                uint32_t b[4];
                int row = wn * 64 + j * 16 + ((lane >> 4) << 3) + (lane & 7);
                int u = s * 2 + ((lane >> 3) & 1);
                ldm4(b, st + T_B + swz(row * 128 + u * 16));
                #pragma unroll
                for (int g = 0; g < 2; g++)
                    #pragma unroll
                    for (int f = 0; f < 2; f++)
                        mma16816h(acc[f][j * 2 + g], a[f], b + g * 2);
            }
        }
        __syncthreads();
    }

    // epilogue: c-frag (m16n8): c0,c1 row g cols 2q,2q+1; c2,c3 row g+8
    int g = lane >> 2, q = lane & 3;
    #pragma unroll
    for (int f = 0; f < 2; f++) {
        int mrow = m0 + wm * 32 + f * 16 + g;
        #pragma unroll
        for (int h = 0; h < 8; h++) {
            int n = n0 + wn * 64 + h * 8 + q * 2;
            if (n < NUM_ENT) {
                float b0 = bias_e[n], b1 = bias_e[n + 1];
                float v0 = acc[f][h][0] + b0, v1 = acc[f][h][1] + b1;
                float v2 = acc[f][h][2] + b0, v3 = acc[f][h][3] + b1;
                *(float2*)&out[(size_t)mrow * NUM_ENT + n] =
                    make_float2(1.f / (1.f + __expf(-v0)), 1.f / (1.f + __expf(-v1)));
                *(float2*)&out[(size_t)(mrow + 8) * NUM_ENT + n] =
                    make_float2(1.f / (1.f + __expf(-v2)), 1.f / (1.f + __expf(-v3)));
            }
        }
    }
}

// ---------------- launcher (6 launches; k5 is launch #6 for ncu -s 5) ----------------
extern "C" void kernel_launch(void* const* d_in, const int* in_sizes, int n_in,
                              void* d_out, int out_size) {
    const int*   e1     = (const int*)d_in[0];
    const int*   rel    = (const int*)d_in[1];
    const float* emb    = (const float*)d_in[2];
    const float* conv_w = (const float*)d_in[3];
    const float* conv_b = (const float*)d_in[4];
    const float* g0     = (const float*)d_in[5];
    const float* b0     = (const float*)d_in[6];
    const float* g1     = (const float*)d_in[7];
    const float* b1     = (const float*)d_in[8];
    const float* g2     = (const float*)d_in[9];
    const float* b2     = (const float*)d_in[10];
    const float* fc_w   = (const float*)d_in[11];
    // d_in[12] = fc_b: cancels exactly under training-mode bn2
    const float* bias_e = (const float*)d_in[13];
    float* out = (float*)d_out;

    cudaFuncSetAttribute(k3_fc,  cudaFuncAttributeMaxDynamicSharedMemorySize, FC_SMEM);
    cudaFuncSetAttribute(k5_mma, cudaFuncAttributeMaxDynamicSharedMemorySize, K5_SMEM);

    k4b_ecat<<<EC_GRID, 256>>>(emb);
    k1_bn0<<<16, 512>>>(e1, emb);
    k2_conv<<<B, 256>>>(e1, rel, emb, conv_w, conv_b, g0, b0);
    k3_fc<<<dim3(2, 8, 12), 256, FC_SMEM>>>(fc_w, g1, b1);
    k4_bn2<<<EDIM, 256>>>(g2, b2);
    k5_mma<<<dim3(8, N_GRID), 256, K5_SMEM>>>(bias_e, out);
}

// round 9
// speedup vs baseline: 2.3331x; 1.3242x over previous
#include <cuda_runtime.h>
#include <cuda_bf16.h>
#include <cuda_fp16.h>
#include <cstdint>

#define B 512
#define EDIM 200
#define NUM_ENT 100000
#define FDIM 4608          // 32*8*18
#define KFC 4608
#define EPS 1e-5f
#define KH 256             // fp16 K padded 200 -> 256
#define ENT_TILE 256
#define N_GRID ((NUM_ENT + ENT_TILE - 1) / ENT_TILE)   // 391
#define ENT_PAD (N_GRID * ENT_TILE)                    // 100096
#define EC_GRID (ENT_PAD / 128)                        // 782

// ---------------- device scratch (static allocations only) ----------------
__device__ float d_y[B * FDIM];            // conv output, pre-bn1
__device__ float d_h[B * EDIM];            // fc output, pre-bn2
__device__ __half d_ycat[B * KFC];         // relu(bn1(y)) fp16
__device__ __half d_wcat[256 * KFC];       // fc_w fp16, rows 200..255 zero
__device__ __half d_zcat[B * KH];          // [batch][256] fp16 z (cols 200.. zero)
__device__ __half d_ecat[ENT_PAD * KH];    // [ent][256]  fp16 e (pad zero)
__device__ float d_chsum[32];
__device__ float d_chsq[32];
__device__ float d_bn0acc[2];              // {sum, sumsq} partials

// ---------------- PTX helpers (sm_80-compatible subset only) ----------------
__device__ __forceinline__ uint32_t smem_u32(const void* p) {
    uint32_t a;
    asm("{ .reg .u64 t; cvta.to.shared.u64 t, %1; cvt.u32.u64 %0, t; }" : "=r"(a) : "l"(p));
    return a;
}
__device__ __forceinline__ void cp_async16(uint32_t dst, const void* src) {
    asm volatile("cp.async.cg.shared.global [%0], [%1], 16;" :: "r"(dst), "l"(src) : "memory");
}
__device__ __forceinline__ void cp_commit() {
    asm volatile("cp.async.commit_group;" ::: "memory");
}
__device__ __forceinline__ void ldm4(uint32_t* r, uint32_t a) {
    asm volatile("ldmatrix.sync.aligned.m8n8.x4.shared.b16 {%0,%1,%2,%3}, [%4];"
                 : "=r"(r[0]), "=r"(r[1]), "=r"(r[2]), "=r"(r[3]) : "r"(a));
}
__device__ __forceinline__ void mma16816h(float* d, const uint32_t* a, const uint32_t* b) {
    asm volatile("mma.sync.aligned.m16n8k16.row.col.f32.f16.f16.f32 "
                 "{%0,%1,%2,%3}, {%4,%5,%6,%7}, {%8,%9}, {%0,%1,%2,%3};"
                 : "+f"(d[0]), "+f"(d[1]), "+f"(d[2]), "+f"(d[3])
                 : "r"(a[0]), "r"(a[1]), "r"(a[2]), "r"(a[3]), "r"(b[0]), "r"(b[1]));
}
__device__ __forceinline__ uint32_t swz(uint32_t off) { return off ^ ((off >> 3) & 0x70); }
__device__ __forceinline__ uint32_t pack_h2(__half a, __half b) {
    return (uint32_t)__half_as_ushort(a) | ((uint32_t)__half_as_ushort(b) << 16);
}

// ---------------- K4b (launch 1): e->fp16, fc_w->fp16, zero accumulators ----------------
__global__ void __launch_bounds__(256) k4b_ecat(const float* __restrict__ emb,
                                                const float* __restrict__ fc_w) {
    int gi = blockIdx.x * 256 + threadIdx.x;
    if (gi < B * EDIM) d_h[gi] = 0.f;
    if (gi < B * KH / 2) ((uint32_t*)d_zcat)[gi] = 0u;
    if (gi < 32) { d_chsum[gi] = 0.f; d_chsq[gi] = 0.f; }
    if (gi < 2) d_bn0acc[gi] = 0.f;

    // fc_w -> d_wcat fp16 (rows >= 200 zero). 256*576 = 147456 segs of 8.
    if (gi < 256 * (KFC / 8)) {
        int row = gi / (KFC / 8), c0 = (gi % (KFC / 8)) * 8;
        float4 f0 = make_float4(0.f, 0.f, 0.f, 0.f);
        float4 f1 = make_float4(0.f, 0.f, 0.f, 0.f);
        if (row < EDIM) {
            const float* src = fc_w + (size_t)row * KFC + c0;
            f0 = *(const float4*)src;
            f1 = *(const float4*)(src + 4);
        }
        uint32_t p0 = pack_h2(__float2half(f0.x), __float2half(f0.y));
        uint32_t p1 = pack_h2(__float2half(f0.z), __float2half(f0.w));
        uint32_t p2 = pack_h2(__float2half(f1.x), __float2half(f1.y));
        uint32_t p3 = pack_h2(__float2half(f1.z), __float2half(f1.w));
        *(uint4*)(d_wcat + (size_t)row * KFC + c0) = make_uint4(p0, p1, p2, p3);
    }

    int warp = threadIdx.x >> 5, lane = threadIdx.x & 31;
    int row0 = blockIdx.x * 128;
    #pragma unroll 4
    for (int it = 0; it < 16; it++) {
        int row = row0 + warp + it * 8;
        bool rv = (row < NUM_ENT) && (lane < 25);     // 25*8 = 200 cols
        float4 f0 = make_float4(0.f, 0.f, 0.f, 0.f);
        float4 f1 = make_float4(0.f, 0.f, 0.f, 0.f);
        if (rv) {
            const float* src = emb + (size_t)row * EDIM + lane * 8;
            f0 = *(const float4*)src;
            f1 = *(const float4*)(src + 4);
        }
        uint32_t p0 = pack_h2(__float2half(f0.x), __float2half(f0.y));
        uint32_t p1 = pack_h2(__float2half(f0.z), __float2half(f0.w));
        uint32_t p2 = pack_h2(__float2half(f1.x), __float2half(f1.y));
        uint32_t p3 = pack_h2(__float2half(f1.z), __float2half(f1.w));
        *(uint4*)(d_ecat + (size_t)row * KH + lane * 8) = make_uint4(p0, p1, p2, p3);
    }
}

// ---------------- K1 (launch 2): bn0 stats (multi-CTA) ----------------
__global__ void k1_bn0(const int* __restrict__ e1, const float* __restrict__ emb) {
    int tid = threadIdx.x, lane = tid & 31;
    float s = 0.f, q = 0.f;
    for (int idx = blockIdx.x * 512 + tid; idx < B * EDIM; idx += gridDim.x * 512) {
        int b = idx / EDIM, j = idx - b * EDIM;
        float v = emb[(size_t)e1[b] * EDIM + j];
        s += v; q += v * v;
    }
    #pragma unroll
    for (int o = 16; o; o >>= 1) {
        s += __shfl_down_sync(0xffffffffu, s, o);
        q += __shfl_down_sync(0xffffffffu, q, o);
    }
    if (lane == 0) { atomicAdd(&d_bn0acc[0], s); atomicAdd(&d_bn0acc[1], q); }
}

// ---------------- K2 (launch 3): conv, bn0 affine derived per block ----------------
__global__ void k2_conv(const int* __restrict__ e1, const int* __restrict__ rel,
                        const float* __restrict__ emb,
                        const float* __restrict__ conv_w, const float* __restrict__ conv_b,
                        const float* __restrict__ g0, const float* __restrict__ b0) {
    __shared__ float sx[200];
    __shared__ float sw[288];
    __shared__ float scb[32];
    int b = blockIdx.x;
    int tid = threadIdx.x;
    int r = rel[b];
    const float inv0 = 1.f / (float)(B * EDIM);
    float m0v = d_bn0acc[0] * inv0;
    float var0 = d_bn0acc[1] * inv0 - m0v * m0v;
    float bn_s = rsqrtf(var0 + EPS) * g0[0];
    float bn_b = b0[0] - m0v * bn_s;

    if (tid < 200) sx[tid] = fmaf(emb[(size_t)e1[b] * EDIM + tid], bn_s, bn_b);
    for (int i = tid; i < 288; i += 256) sw[i] = conv_w[(size_t)r * 288 + i];
    if (tid < 32) scb[tid] = conv_b[(size_t)r * 32 + tid];
    __syncthreads();

    int o = tid >> 3;
    int i = tid & 7;
    const float* w = &sw[o * 9];
    float cb = scb[o];
    float ls = 0.f, lq = 0.f;
    float* yrow = &d_y[(size_t)b * FDIM + o * 144 + i * 18];
    #pragma unroll
    for (int j = 0; j < 18; j++) {
        float acc = cb;
        #pragma unroll
        for (int di = 0; di < 3; di++)
            #pragma unroll
            for (int dj = 0; dj < 3; dj++)
                acc = fmaf(sx[(i + di) * 20 + (j + dj)], w[di * 3 + dj], acc);
        yrow[j] = acc;
        ls += acc; lq += acc * acc;
    }
    #pragma unroll
    for (int off = 4; off; off >>= 1) {
        ls += __shfl_down_sync(0xffffffffu, ls, off, 8);
        lq += __shfl_down_sync(0xffffffffu, lq, off, 8);
    }
    if ((tid & 7) == 0) {
        atomicAdd(&d_chsum[o], ls);
        atomicAdd(&d_chsq[o], lq);
    }
}

// ---------------- K3p (launch 4): ycat = fp16(relu(bn1(y))) ----------------
__global__ void __launch_bounds__(256) k3p_ycat(const float* __restrict__ g1,
                                                const float* __restrict__ b1) {
    __shared__ float s_a[32], s_c[32];
    int tid = threadIdx.x;
    if (tid < 32) {
        const float inv = 1.f / (float)(B * 144);
        float m = d_chsum[tid] * inv;
        float var = d_chsq[tid] * inv - m * m;
        float a = rsqrtf(var + EPS) * g1[tid];
        s_a[tid] = a;
        s_c[tid] = b1[tid] - m * a;
    }
    __syncthreads();

    int seg = blockIdx.x * 256 + tid;               // < 512*576
    int row = seg / (KFC / 8), c0 = (seg % (KFC / 8)) * 8;
    const float* src = d_y + (size_t)row * KFC + c0;
    float4 f0 = *(const float4*)src;
    float4 f1 = *(const float4*)(src + 4);
    float v[8] = {f0.x, f0.y, f0.z, f0.w, f1.x, f1.y, f1.z, f1.w};
    uint32_t p[4];
    #pragma unroll
    for (int i = 0; i < 4; i++) {
        int ka = c0 + 2 * i;
        int ca = ka / 144, cb = (ka + 1) / 144;
        __half ha = __float2half(fmaxf(fmaf(v[2 * i],     s_a[ca], s_c[ca]), 0.f));
        __half hb = __float2half(fmaxf(fmaf(v[2 * i + 1], s_a[cb], s_c[cb]), 0.f));
        p[i] = pack_h2(ha, hb);
    }
    *(uint4*)(d_ycat + (size_t)row * KFC + c0) = make_uint4(p[0], p[1], p[2], p[3]);
}

// ---------------- K3 (launch 5): fc GEMM fp16 mma, k-split atomics ----------------
// CTA 64m x 128n; warps 2(m) x 4(n), warp tile 32x32. K split 24 x 192 (3 chunks of 64).
#define F_TA 0
#define F_TB 8192
#define F_ST 24576
#define F_SMEM (2 * F_ST)

__device__ __forceinline__ void k3_load(uint32_t sb, int buf, int kcol, int m0, int n0, int tid) {
    uint32_t base = sb + buf * F_ST;
    #pragma unroll
    for (int i = 0; i < 2; i++) {                    // A: 64 rows x 128B
        int idx = tid + i * 256;
        int row = idx >> 3, u = idx & 7;
        cp_async16(base + F_TA + swz(row * 128 + u * 16),
                   d_ycat + (size_t)(m0 + row) * KFC + kcol + u * 8);
    }
    #pragma unroll
    for (int i = 0; i < 4; i++) {                    // B: 128 rows x 128B
        int idx = tid + i * 256;
        int row = idx >> 3, u = idx & 7;
        cp_async16(base + F_TB + swz(row * 128 + u * 16),
                   d_wcat + (size_t)(n0 + row) * KFC + kcol + u * 8);
    }
    cp_commit();
}

__global__ void __launch_bounds__(256) k3_mma() {
    extern __shared__ char smem[];
    const uint32_t sb = smem_u32(smem);
    int tid = threadIdx.x, lane = tid & 31, wid = tid >> 5;
    int wm = wid & 1, wn = wid >> 1;                 // 2(m) x 4(n)
    int n0 = blockIdx.x * 128, m0 = blockIdx.y * 64;
    int kb = blockIdx.z * 192;

    float acc[2][4][4];
    #pragma unroll
    for (int f = 0; f < 2; f++)
        #pragma unroll
        for (int h = 0; h < 4; h++)
            #pragma unroll
            for (int i = 0; i < 4; i++) acc[f][h][i] = 0.f;

    k3_load(sb, 0, kb, m0, n0, tid);

    for (int c = 0; c < 3; c++) {
        int buf = c & 1;
        if (c < 2) {
            k3_load(sb, buf ^ 1, kb + (c + 1) * 64, m0, n0, tid);
            asm volatile("cp.async.wait_group 1;" ::: "memory");
        } else {
            asm volatile("cp.async.wait_group 0;" ::: "memory");
        }
        __syncthreads();

        const uint32_t st = sb + buf * F_ST;
        #pragma unroll
        for (int s = 0; s < 4; s++) {
            uint32_t a[2][4];
            #pragma unroll
            for (int f = 0; f < 2; f++) {
                int row = wm * 32 + f * 16 + (lane & 15);
                int u = s * 2 + (lane >> 4);
                ldm4(a[f], st + F_TA + swz(row * 128 + u * 16));
            }
            #pragma unroll
            for (int j = 0; j < 2; j++) {
                uint32_t b[4];
                int row = wn * 32 + j * 16 + ((lane >> 4) << 3) + (lane & 7);
                int u = s * 2 + ((lane >> 3) & 1);
                ldm4(b, st + F_TB + swz(row * 128 + u * 16));
                #pragma unroll
                for (int g = 0; g < 2; g++)
                    #pragma unroll
                    for (int f = 0; f < 2; f++)
                        mma16816h(acc[f][j * 2 + g], a[f], b + g * 2);
            }
        }
        __syncthreads();
    }

    // epilogue: atomic accumulate into d_h (fp32)
    int g = lane >> 2, q = lane & 3;
    #pragma unroll
    for (int f = 0; f < 2; f++) {
        int mrow = m0 + wm * 32 + f * 16 + g;
        #pragma unroll
        for (int h = 0; h < 4; h++) {
            int n = n0 + wn * 32 + h * 8 + q * 2;
            if (n < EDIM) {
                atomicAdd(&d_h[(size_t)mrow * EDIM + n],           acc[f][h][0]);
                atomicAdd(&d_h[(size_t)mrow * EDIM + n + 1],       acc[f][h][1]);
                atomicAdd(&d_h[(size_t)(mrow + 8) * EDIM + n],     acc[f][h][2]);
                atomicAdd(&d_h[(size_t)(mrow + 8) * EDIM + n + 1], acc[f][h][3]);
            }
        }
    }
}

// ---------------- K4 (launch 6): bn2 + relu, emit fp16 z ----------------
__global__ void k4_bn2(const float* __restrict__ g2, const float* __restrict__ b2) {
    int n = blockIdx.x;        // feature 0..199
    int t = threadIdx.x;       // 256
    float v0 = d_h[(size_t)t * EDIM + n];
    float v1 = d_h[(size_t)(t + 256) * EDIM + n];
    __shared__ float rs[256], rq[256];
    rs[t] = v0 + v1; rq[t] = v0 * v0 + v1 * v1;
    __syncthreads();
    for (int o = 128; o; o >>= 1) {
        if (t < o) { rs[t] += rs[t + o]; rq[t] += rq[t + o]; }
        __syncthreads();
    }
    __shared__ float sa, sc;
    if (t == 0) {
        float m = rs[0] * (1.f / 512.f);
        float var = rq[0] * (1.f / 512.f) - m * m;
        float a = rsqrtf(var + EPS) * g2[n];
        sa = a; sc = b2[n] - m * a;
    }
    __syncthreads();
    float z0 = fmaxf(fmaf(v0, sa, sc), 0.f);
    float z1 = fmaxf(fmaf(v1, sa, sc), 0.f);
    d_zcat[(size_t)t * KH + n]         = __float2half(z0);
    d_zcat[(size_t)(t + 256) * KH + n] = __float2half(z1);
}

// ---------------- K5 (launch 7): fp16 mma.sync GEMM + bias + sigmoid ----------------
#define T_A 0
#define T_B 8192
#define ST_STRIDE 40960
#define K5_SMEM (2 * ST_STRIDE)

__device__ __forceinline__ void k5_load(uint32_t sb, int buf, int ks, int m0, int n0, int tid) {
    uint32_t base = sb + buf * ST_STRIDE;
    int koff = ks * 64;
    #pragma unroll
    for (int i = 0; i < 2; i++) {                    // A: 64 rows x 128B
        int idx = tid + i * 256;
        int row = idx >> 3, u = idx & 7;
        cp_async16(base + T_A + swz(row * 128 + u * 16),
                   d_zcat + (size_t)(m0 + row) * KH + koff + u * 8);
    }
    #pragma unroll
    for (int i = 0; i < 8; i++) {                    // B: 256 rows x 128B
        int idx = tid + i * 256;
        int row = idx >> 3, u = idx & 7;
        cp_async16(base + T_B + swz(row * 128 + u * 16),
                   d_ecat + (size_t)(n0 + row) * KH + koff + u * 8);
    }
    cp_commit();
}

__global__ void __launch_bounds__(256, 2) k5_mma(const float* __restrict__ bias_e,
                                                 float* __restrict__ out) {
    extern __shared__ char smem[];
    const uint32_t sb = smem_u32(smem);
    int tid = threadIdx.x, lane = tid & 31, wid = tid >> 5;
    int wm = wid & 1, wn = wid >> 1;                 // 2(m) x 4(n)
    int m0 = blockIdx.x * 64, n0 = blockIdx.y * 256;

    float acc[2][8][4];
    #pragma unroll
    for (int f = 0; f < 2; f++)
        #pragma unroll
        for (int h = 0; h < 8; h++)
            #pragma unroll
            for (int i = 0; i < 4; i++) acc[f][h][i] = 0.f;

    k5_load(sb, 0, 0, m0, n0, tid);

    for (int ks = 0; ks < 4; ks++) {
        int buf = ks & 1;
        if (ks < 3) {
            k5_load(sb, buf ^ 1, ks + 1, m0, n0, tid);
            asm volatile("cp.async.wait_group 1;" ::: "memory");
        } else {
            asm volatile("cp.async.wait_group 0;" ::: "memory");
        }
        __syncthreads();

        const int scount = (ks < 3) ? 4 : 1;         // quarter 3: cols 192..199 only
        const uint32_t st = sb + buf * ST_STRIDE;
        for (int s = 0; s < scount; s++) {
            uint32_t a[2][4];
            #pragma unroll
            for (int f = 0; f < 2; f++) {
                int row = wm * 32 + f * 16 + (lane & 15);
                int u = s * 2 + (lane >> 4);
                ldm4(a[f], st + T_A + swz(row * 128 + u * 16));
            }
            #pragma unroll
            for (int j = 0; j < 4; j++) {
                uint32_t b[4];
                int row = wn * 64 + j * 16 + ((lane >> 4) << 3) + (lane & 7);
                int u = s * 2 + ((lane >> 3) & 1);
                ldm4(b, st + T_B + swz(row * 128 + u * 16));
                #pragma unroll
                for (int g = 0; g < 2; g++)
                    #pragma unroll
                    for (int f = 0; f < 2; f++)
                        mma16816h(acc[f][j * 2 + g], a[f], b + g * 2);
            }
        }
        __syncthreads();
    }

    int g = lane >> 2, q = lane & 3;
    #pragma unroll
    for (int f = 0; f < 2; f++) {
        int mrow = m0 + wm * 32 + f * 16 + g;
        #pragma unroll
        for (int h = 0; h < 8; h++) {
            int n = n0 + wn * 64 + h * 8 + q * 2;
            if (n < NUM_ENT) {
                float b0 = bias_e[n], b1 = bias_e[n + 1];
                float v0 = acc[f][h][0] + b0, v1 = acc[f][h][1] + b1;
                float v2 = acc[f][h][2] + b0, v3 = acc[f][h][3] + b1;
                *(float2*)&out[(size_t)mrow * NUM_ENT + n] =
                    make_float2(1.f / (1.f + __expf(-v0)), 1.f / (1.f + __expf(-v1)));
                *(float2*)&out[(size_t)(mrow + 8) * NUM_ENT + n] =
                    make_float2(1.f / (1.f + __expf(-v2)), 1.f / (1.f + __expf(-v3)));
            }
        }
    }
}

// ---------------- launcher (7 launches) ----------------
extern "C" void kernel_launch(void* const* d_in, const int* in_sizes, int n_in,
                              void* d_out, int out_size) {
    const int*   e1     = (const int*)d_in[0];
    const int*   rel    = (const int*)d_in[1];
    const float* emb    = (const float*)d_in[2];
    const float* conv_w = (const float*)d_in[3];
    const float* conv_b = (const float*)d_in[4];
    const float* g0     = (const float*)d_in[5];
    const float* b0     = (const float*)d_in[6];
    const float* g1     = (const float*)d_in[7];
    const float* b1     = (const float*)d_in[8];
    const float* g2     = (const float*)d_in[9];
    const float* b2     = (const float*)d_in[10];
    const float* fc_w   = (const float*)d_in[11];
    // d_in[12] = fc_b: cancels exactly under training-mode bn2
    const float* bias_e = (const float*)d_in[13];
    float* out = (float*)d_out;

    cudaFuncSetAttribute(k3_mma, cudaFuncAttributeMaxDynamicSharedMemorySize, F_SMEM);
    cudaFuncSetAttribute(k5_mma, cudaFuncAttributeMaxDynamicSharedMemorySize, K5_SMEM);

    k4b_ecat<<<EC_GRID, 256>>>(emb, fc_w);
    k1_bn0<<<16, 512>>>(e1, emb);
    k2_conv<<<B, 256>>>(e1, rel, emb, conv_w, conv_b, g0, b0);
    k3p_ycat<<<(B * KFC / 8) / 256, 256>>>(g1, b1);          // 1152 blocks
    k3_mma<<<dim3(2, 8, 24), 256, F_SMEM>>>();               // n-tiles=2 (256 pad), m=8, k=24
    k4_bn2<<<EDIM, 256>>>(g2, b2);
    k5_mma<<<dim3(8, N_GRID), 256, K5_SMEM>>>(bias_e, out);
}

// round 11
// speedup vs baseline: 2.8187x; 1.2081x over previous
#include <cuda_runtime.h>
#include <cuda_bf16.h>
#include <cuda_fp16.h>
#include <cstdint>

#define B 512
#define EDIM 200
#define NUM_ENT 100000
#define FDIM 4608          // 32*8*18
#define KFC 4608
#define EPS 1e-5f
#define KH 256             // fp16 K padded 200 -> 256
#define ENT_TILE 256
#define N_GRID ((NUM_ENT + ENT_TILE - 1) / ENT_TILE)   // 391
#define ENT_PAD (N_GRID * ENT_TILE)                    // 100096
#define ESEGS (NUM_ENT * 25)                           // 2.5M 8-col segments
#define PREP_GRID ((ESEGS + 255) / 256)                // 9766

// ---------------- device scratch (static allocations only; zero-initialized) ----------------
__device__ float d_y[B * FDIM];            // conv output, pre-bn1
__device__ float d_h[B * EDIM];            // fc output, pre-bn2
__device__ __half d_ycat[B * KFC];         // relu(bn1(y)) fp16
__device__ __half d_wcat[256 * KFC];       // fc_w fp16; rows 200..255 never written (stay 0)
__device__ __half d_zcat[B * KH];          // fp16 z; cols 200..255 never written (stay 0)
__device__ __half d_ecat[ENT_PAD * KH];    // fp16 e; pad rows/cols never written (stay 0)
__device__ float d_chsum[32];              // RESET EVERY CALL (k_prep)
__device__ float d_chsq[32];               // RESET EVERY CALL (k_prep)
__device__ float d_bn0acc[2];              // RESET EVERY CALL (k_prep)

// ---------------- PTX helpers (sm_80-compatible subset only) ----------------
__device__ __forceinline__ uint32_t smem_u32(const void* p) {
    uint32_t a;
    asm("{ .reg .u64 t; cvta.to.shared.u64 t, %1; cvt.u32.u64 %0, t; }" : "=r"(a) : "l"(p));
    return a;
}
__device__ __forceinline__ void cp_async16(uint32_t dst, const void* src) {
    asm volatile("cp.async.cg.shared.global [%0], [%1], 16;" :: "r"(dst), "l"(src) : "memory");
}
__device__ __forceinline__ void cp_commit() {
    asm volatile("cp.async.commit_group;" ::: "memory");
}
__device__ __forceinline__ void ldm4(uint32_t* r, uint32_t a) {
    asm volatile("ldmatrix.sync.aligned.m8n8.x4.shared.b16 {%0,%1,%2,%3}, [%4];"
                 : "=r"(r[0]), "=r"(r[1]), "=r"(r[2]), "=r"(r[3]) : "r"(a));
}
__device__ __forceinline__ void mma16816h(float* d, const uint32_t* a, const uint32_t* b) {
    asm volatile("mma.sync.aligned.m16n8k16.row.col.f32.f16.f16.f32 "
                 "{%0,%1,%2,%3}, {%4,%5,%6,%7}, {%8,%9}, {%0,%1,%2,%3};"
                 : "+f"(d[0]), "+f"(d[1]), "+f"(d[2]), "+f"(d[3])
                 : "r"(a[0]), "r"(a[1]), "r"(a[2]), "r"(a[3]), "r"(b[0]), "r"(b[1]));
}
__device__ __forceinline__ uint32_t swz(uint32_t off) { return off ^ ((off >> 3) & 0x70); }
__device__ __forceinline__ uint32_t pack_h2(__half a, __half b) {
    return (uint32_t)__half_as_ushort(a) | ((uint32_t)__half_as_ushort(b) << 16);
}
__device__ __forceinline__ float sigmoid_fast(float v) {
    float t;
    asm("tanh.approx.f32 %0, %1;" : "=f"(t) : "f"(0.5f * v));
    return fmaf(0.5f, t, 0.5f);
}

// ---------------- K_prep (launch 1): e->fp16, fc_w->fp16, zero d_h + accumulators ----------------
__global__ void __launch_bounds__(256) k_prep(const float* __restrict__ emb,
                                              const float* __restrict__ fc_w) {
    int gi = blockIdx.x * 256 + threadIdx.x;
    if (gi < B * EDIM) d_h[gi] = 0.f;
    if (gi < 32) { d_chsum[gi] = 0.f; d_chsq[gi] = 0.f; }   // per-call reset (bn1 stats)
    if (gi < 2) d_bn0acc[gi] = 0.f;                          // per-call reset (bn0 stats)

    // fc_w -> d_wcat fp16, rows < 200 only. 200*576 = 115200 segments.
    if (gi < EDIM * (KFC / 8)) {
        int row = gi / (KFC / 8), c0 = (gi % (KFC / 8)) * 8;
        const float* src = fc_w + (size_t)row * KFC + c0;
        float4 f0 = *(const float4*)src;
        float4 f1 = *(const float4*)(src + 4);
        uint32_t p0 = pack_h2(__float2half(f0.x), __float2half(f0.y));
        uint32_t p1 = pack_h2(__float2half(f0.z), __float2half(f0.w));
        uint32_t p2 = pack_h2(__float2half(f1.x), __float2half(f1.y));
        uint32_t p3 = pack_h2(__float2half(f1.z), __float2half(f1.w));
        *(uint4*)(d_wcat + (size_t)row * KFC + c0) = make_uint4(p0, p1, p2, p3);
    }

    // emb -> d_ecat fp16: row = gi/25, cols [c0, c0+8)
    if (gi < ESEGS) {
        int row = gi / 25, c0 = (gi - row * 25) * 8;
        const float* src = emb + (size_t)row * EDIM + c0;
        float4 f0 = *(const float4*)src;
        float4 f1 = *(const float4*)(src + 4);
        uint32_t p0 = pack_h2(__float2half(f0.x), __float2half(f0.y));
        uint32_t p1 = pack_h2(__float2half(f0.z), __float2half(f0.w));
        uint32_t p2 = pack_h2(__float2half(f1.x), __float2half(f1.y));
        uint32_t p3 = pack_h2(__float2half(f1.z), __float2half(f1.w));
        *(uint4*)(d_ecat + (size_t)row * KH + c0) = make_uint4(p0, p1, p2, p3);
    }
}

// ---------------- K1 (launch 2): bn0 stats (multi-CTA) ----------------
__global__ void k1_bn0(const int* __restrict__ e1, const float* __restrict__ emb) {
    int tid = threadIdx.x, lane = tid & 31;
    float s = 0.f, q = 0.f;
    for (int idx = blockIdx.x * 512 + tid; idx < B * EDIM; idx += gridDim.x * 512) {
        int b = idx / EDIM, j = idx - b * EDIM;
        float v = emb[(size_t)e1[b] * EDIM + j];
        s += v; q += v * v;
    }
    #pragma unroll
    for (int o = 16; o; o >>= 1) {
        s += __shfl_down_sync(0xffffffffu, s, o);
        q += __shfl_down_sync(0xffffffffu, q, o);
    }
    if (lane == 0) { atomicAdd(&d_bn0acc[0], s); atomicAdd(&d_bn0acc[1], q); }
}

// ---------------- K2 (launch 3): conv, bn0 affine derived per block ----------------
__global__ void k2_conv(const int* __restrict__ e1, const int* __restrict__ rel,
                        const float* __restrict__ emb,
                        const float* __restrict__ conv_w, const float* __restrict__ conv_b,
                        const float* __restrict__ g0, const float* __restrict__ b0) {
    __shared__ float sx[200];
    __shared__ float sw[288];
    __shared__ float scb[32];
    int b = blockIdx.x;
    int tid = threadIdx.x;
    int r = rel[b];
    const float inv0 = 1.f / (float)(B * EDIM);
    float m0v = d_bn0acc[0] * inv0;
    float var0 = d_bn0acc[1] * inv0 - m0v * m0v;
    float bn_s = rsqrtf(var0 + EPS) * g0[0];
    float bn_b = b0[0] - m0v * bn_s;

    if (tid < 200) sx[tid] = fmaf(emb[(size_t)e1[b] * EDIM + tid], bn_s, bn_b);
    for (int i = tid; i < 288; i += 256) sw[i] = conv_w[(size_t)r * 288 + i];
    if (tid < 32) scb[tid] = conv_b[(size_t)r * 32 + tid];
    __syncthreads();

    int o = tid >> 3;
    int i = tid & 7;
    const float* w = &sw[o * 9];
    float cb = scb[o];
    float ls = 0.f, lq = 0.f;
    float* yrow = &d_y[(size_t)b * FDIM + o * 144 + i * 18];
    #pragma unroll
    for (int j = 0; j < 18; j++) {
        float acc = cb;
        #pragma unroll
        for (int di = 0; di < 3; di++)
            #pragma unroll
            for (int dj = 0; dj < 3; dj++)
                acc = fmaf(sx[(i + di) * 20 + (j + dj)], w[di * 3 + dj], acc);
        yrow[j] = acc;
        ls += acc; lq += acc * acc;
    }
    #pragma unroll
    for (int off = 4; off; off >>= 1) {
        ls += __shfl_down_sync(0xffffffffu, ls, off, 8);
        lq += __shfl_down_sync(0xffffffffu, lq, off, 8);
    }
    if ((tid & 7) == 0) {
        atomicAdd(&d_chsum[o], ls);
        atomicAdd(&d_chsq[o], lq);
    }
}

// ---------------- K3p (launch 4): ycat = fp16(relu(bn1(y))) ----------------
__global__ void __launch_bounds__(256) k3p_ycat(const float* __restrict__ g1,
                                                const float* __restrict__ b1) {
    __shared__ float s_a[32], s_c[32];
    int tid = threadIdx.x;
    if (tid < 32) {
        const float inv = 1.f / (float)(B * 144);
        float m = d_chsum[tid] * inv;
        float var = d_chsq[tid] * inv - m * m;
        float a = rsqrtf(var + EPS) * g1[tid];
        s_a[tid] = a;
        s_c[tid] = b1[tid] - m * a;
    }
    __syncthreads();

    int seg = blockIdx.x * 256 + tid;               // < 512*576
    int row = seg / (KFC / 8), c0 = (seg % (KFC / 8)) * 8;
    const float* src = d_y + (size_t)row * KFC + c0;
    float4 f0 = *(const float4*)src;
    float4 f1 = *(const float4*)(src + 4);
    float v[8] = {f0.x, f0.y, f0.z, f0.w, f1.x, f1.y, f1.z, f1.w};
    uint32_t p[4];
    #pragma unroll
    for (int i = 0; i < 4; i++) {
        int ka = c0 + 2 * i;
        int ca = ka / 144, cb = (ka + 1) / 144;
        __half ha = __float2half(fmaxf(fmaf(v[2 * i],     s_a[ca], s_c[ca]), 0.f));
        __half hb = __float2half(fmaxf(fmaf(v[2 * i + 1], s_a[cb], s_c[cb]), 0.f));
        p[i] = pack_h2(ha, hb);
    }
    *(uint4*)(d_ycat + (size_t)row * KFC + c0) = make_uint4(p[0], p[1], p[2], p[3]);
}

// ---------------- K3 (launch 5): fc GEMM fp16 mma, k-split atomics ----------------
#define F_TA 0
#define F_TB 8192
#define F_ST 24576
#define F_SMEM (2 * F_ST)

__device__ __forceinline__ void k3_load(uint32_t sb, int buf, int kcol, int m0, int n0, int tid) {
    uint32_t base = sb + buf * F_ST;
    #pragma unroll
    for (int i = 0; i < 2; i++) {                    // A: 64 rows x 128B
        int idx = tid + i * 256;
        int row = idx >> 3, u = idx & 7;
        cp_async16(base + F_TA + swz(row * 128 + u * 16),
                   d_ycat + (size_t)(m0 + row) * KFC + kcol + u * 8);
    }
    #pragma unroll
    for (int i = 0; i < 4; i++) {                    // B: 128 rows x 128B
        int idx = tid + i * 256;
        int row = idx >> 3, u = idx & 7;
        cp_async16(base + F_TB + swz(row * 128 + u * 16),
                   d_wcat + (size_t)(n0 + row) * KFC + kcol + u * 8);
    }
    cp_commit();
}

__global__ void __launch_bounds__(256) k3_mma() {
    extern __shared__ char smem[];
    const uint32_t sb = smem_u32(smem);
    int tid = threadIdx.x, lane = tid & 31, wid = tid >> 5;
    int wm = wid & 1, wn = wid >> 1;                 // 2(m) x 4(n)
    int n0 = blockIdx.x * 128, m0 = blockIdx.y * 64;
    int kb = blockIdx.z * 192;

    float acc[2][4][4];
    #pragma unroll
    for (int f = 0; f < 2; f++)
        #pragma unroll
        for (int h = 0; h < 4; h++)
            #pragma unroll
            for (int i = 0; i < 4; i++) acc[f][h][i] = 0.f;

    k3_load(sb, 0, kb, m0, n0, tid);

    for (int c = 0; c < 3; c++) {
        int buf = c & 1;
        if (c < 2) {
            k3_load(sb, buf ^ 1, kb + (c + 1) * 64, m0, n0, tid);
            asm volatile("cp.async.wait_group 1;" ::: "memory");
        } else {
            asm volatile("cp.async.wait_group 0;" ::: "memory");
        }
        __syncthreads();

        const uint32_t st = sb + buf * F_ST;
        #pragma unroll
        for (int s = 0; s < 4; s++) {
            uint32_t a[2][4];
            #pragma unroll
            for (int f = 0; f < 2; f++) {
                int row = wm * 32 + f * 16 + (lane & 15);
                int u = s * 2 + (lane >> 4);
                ldm4(a[f], st + F_TA + swz(row * 128 + u * 16));
            }
            #pragma unroll
            for (int j = 0; j < 2; j++) {
                uint32_t b[4];
                int row = wn * 32 + j * 16 + ((lane >> 4) << 3) + (lane & 7);
                int u = s * 2 + ((lane >> 3) & 1);
                ldm4(b, st + F_TB + swz(row * 128 + u * 16));
                #pragma unroll
                for (int g = 0; g < 2; g++)
                    #pragma unroll
                    for (int f = 0; f < 2; f++)
                        mma16816h(acc[f][j * 2 + g], a[f], b + g * 2);
            }
        }
        __syncthreads();
    }

    int g = lane >> 2, q = lane & 3;
    #pragma unroll
    for (int f = 0; f < 2; f++) {
        int mrow = m0 + wm * 32 + f * 16 + g;
        #pragma unroll
        for (int h = 0; h < 4; h++) {
            int n = n0 + wn * 32 + h * 8 + q * 2;
            if (n < EDIM) {
                atomicAdd(&d_h[(size_t)mrow * EDIM + n],           acc[f][h][0]);
                atomicAdd(&d_h[(size_t)mrow * EDIM + n + 1],       acc[f][h][1]);
                atomicAdd(&d_h[(size_t)(mrow + 8) * EDIM + n],     acc[f][h][2]);
                atomicAdd(&d_h[(size_t)(mrow + 8) * EDIM + n + 1], acc[f][h][3]);
            }
        }
    }
}

// ---------------- K4 (launch 6): bn2 + relu, emit fp16 z ----------------
__global__ void k4_bn2(const float* __restrict__ g2, const float* __restrict__ b2) {
    int n = blockIdx.x;        // feature 0..199
    int t = threadIdx.x;       // 256
    float v0 = d_h[(size_t)t * EDIM + n];
    float v1 = d_h[(size_t)(t + 256) * EDIM + n];
    __shared__ float rs[256], rq[256];
    rs[t] = v0 + v1; rq[t] = v0 * v0 + v1 * v1;
    __syncthreads();
    for (int o = 128; o; o >>= 1) {
        if (t < o) { rs[t] += rs[t + o]; rq[t] += rq[t + o]; }
        __syncthreads();
    }
    __shared__ float sa, sc;
    if (t == 0) {
        float m = rs[0] * (1.f / 512.f);
        float var = rq[0] * (1.f / 512.f) - m * m;
        float a = rsqrtf(var + EPS) * g2[n];
        sa = a; sc = b2[n] - m * a;
    }
    __syncthreads();
    float z0 = fmaxf(fmaf(v0, sa, sc), 0.f);
    float z1 = fmaxf(fmaf(v1, sa, sc), 0.f);
    d_zcat[(size_t)t * KH + n]         = __float2half(z0);
    d_zcat[(size_t)(t + 256) * KH + n] = __float2half(z1);
}

// ---------------- K5 (launch 7): fp16 mma.sync GEMM + bias + sigmoid ----------------
#define T_A 0
#define T_B 8192
#define ST_STRIDE 40960
#define K5_SMEM (2 * ST_STRIDE)

__device__ __forceinline__ void k5_load(uint32_t sb, int buf, int ks, int m0, int n0, int tid) {
    uint32_t base = sb + buf * ST_STRIDE;
    int koff = ks * 64;
    #pragma unroll
    for (int i = 0; i < 2; i++) {                    // A: 64 rows x 128B
        int idx = tid + i * 256;
        int row = idx >> 3, u = idx & 7;
        cp_async16(base + T_A + swz(row * 128 + u * 16),
                   d_zcat + (size_t)(m0 + row) * KH + koff + u * 8);
    }
    #pragma unroll
    for (int i = 0; i < 8; i++) {                    // B: 256 rows x 128B
        int idx = tid + i * 256;
        int row = idx >> 3, u = idx & 7;
        cp_async16(base + T_B + swz(row * 128 + u * 16),
                   d_ecat + (size_t)(n0 + row) * KH + koff + u * 8);
    }
    cp_commit();
}

__global__ void __launch_bounds__(256, 2) k5_mma(const float* __restrict__ bias_e,
                                                 float* __restrict__ out) {
    extern __shared__ char smem[];
    const uint32_t sb = smem_u32(smem);
    int tid = threadIdx.x, lane = tid & 31, wid = tid >> 5;
    int wm = wid & 1, wn = wid >> 1;                 // 2(m) x 4(n)
    int m0 = blockIdx.x * 64, n0 = blockIdx.y * 256;

    float acc[2][8][4];
    #pragma unroll
    for (int f = 0; f < 2; f++)
        #pragma unroll
        for (int h = 0; h < 8; h++)
            #pragma unroll
            for (int i = 0; i < 4; i++) acc[f][h][i] = 0.f;

    k5_load(sb, 0, 0, m0, n0, tid);

    for (int ks = 0; ks < 4; ks++) {
        int buf = ks & 1;
        if (ks < 3) {
            k5_load(sb, buf ^ 1, ks + 1, m0, n0, tid);
            asm volatile("cp.async.wait_group 1;" ::: "memory");
        } else {
            asm volatile("cp.async.wait_group 0;" ::: "memory");
        }
        __syncthreads();

        const int scount = (ks < 3) ? 4 : 1;         // quarter 3: cols 192..199 only
        const uint32_t st = sb + buf * ST_STRIDE;
        for (int s = 0; s < scount; s++) {
            uint32_t a[2][4];
            #pragma unroll
            for (int f = 0; f < 2; f++) {
                int row = wm * 32 + f * 16 + (lane & 15);
                int u = s * 2 + (lane >> 4);
                ldm4(a[f], st + T_A + swz(row * 128 + u * 16));
            }
            #pragma unroll
            for (int j = 0; j < 4; j++) {
                uint32_t b[4];
                int row = wn * 64 + j * 16 + ((lane >> 4) << 3) + (lane & 7);
                int u = s * 2 + ((lane >> 3) & 1);
                ldm4(b, st + T_B + swz(row * 128 + u * 16));
                #pragma unroll
                for (int g = 0; g < 2; g++)
                    #pragma unroll
                    for (int f = 0; f < 2; f++)
                        mma16816h(acc[f][j * 2 + g], a[f], b + g * 2);
            }
        }
        __syncthreads();
    }

    int g = lane >> 2, q = lane & 3;
    #pragma unroll
    for (int f = 0; f < 2; f++) {
        int mrow = m0 + wm * 32 + f * 16 + g;
        #pragma unroll
        for (int h = 0; h < 8; h++) {
            int n = n0 + wn * 64 + h * 8 + q * 2;
            if (n < NUM_ENT) {
                float b0 = bias_e[n], b1 = bias_e[n + 1];
                *(float2*)&out[(size_t)mrow * NUM_ENT + n] =
                    make_float2(sigmoid_fast(acc[f][h][0] + b0),
                                sigmoid_fast(acc[f][h][1] + b1));
                *(float2*)&out[(size_t)(mrow + 8) * NUM_ENT + n] =
                    make_float2(sigmoid_fast(acc[f][h][2] + b0),
                                sigmoid_fast(acc[f][h][3] + b1));
            }
        }
    }
}

// ---------------- launcher (7 launches) ----------------
extern "C" void kernel_launch(void* const* d_in, const int* in_sizes, int n_in,
                              void* d_out, int out_size) {
    const int*   e1     = (const int*)d_in[0];
    const int*   rel    = (const int*)d_in[1];
    const float* emb    = (const float*)d_in[2];
    const float* conv_w = (const float*)d_in[3];
    const float* conv_b = (const float*)d_in[4];
    const float* g0     = (const float*)d_in[5];
    const float* b0     = (const float*)d_in[6];
    const float* g1     = (const float*)d_in[7];
    const float* b1     = (const float*)d_in[8];
    const float* g2     = (const float*)d_in[9];
    const float* b2     = (const float*)d_in[10];
    const float* fc_w   = (const float*)d_in[11];
    // d_in[12] = fc_b: cancels exactly under training-mode bn2
    const float* bias_e = (const float*)d_in[13];
    float* out = (float*)d_out;

    cudaFuncSetAttribute(k3_mma, cudaFuncAttributeMaxDynamicSharedMemorySize, F_SMEM);
    cudaFuncSetAttribute(k5_mma, cudaFuncAttributeMaxDynamicSharedMemorySize, K5_SMEM);

    k_prep<<<PREP_GRID, 256>>>(emb, fc_w);
    k1_bn0<<<16, 512>>>(e1, emb);
    k2_conv<<<B, 256>>>(e1, rel, emb, conv_w, conv_b, g0, b0);
    k3p_ycat<<<(B * KFC / 8) / 256, 256>>>(g1, b1);          // 1152 blocks
    k3_mma<<<dim3(2, 8, 24), 256, F_SMEM>>>();               // n=2 (256 pad), m=8, k=24
    k4_bn2<<<EDIM, 256>>>(g2, b2);
    k5_mma<<<dim3(8, N_GRID), 256, K5_SMEM>>>(bias_e, out);
}

// round 12
// speedup vs baseline: 2.8622x; 1.0154x over previous
#include <cuda_runtime.h>
#include <cuda_bf16.h>
#include <cuda_fp16.h>
#include <cstdint>

#define B 512
#define EDIM 200
#define NUM_ENT 100000
#define FDIM 4608          // 32*8*18
#define KFC 4608
#define EPS 1e-5f
#define KH 256             // fp16 K padded 200 -> 256
#define ENT_TILE 256
#define N_GRID ((NUM_ENT + ENT_TILE - 1) / ENT_TILE)   // 391
#define ENT_PAD (N_GRID * ENT_TILE)                    // 100096
#define ESEGS (NUM_ENT * 25)                           // 2.5M 8-col segments
#define PREP_GRID ((ESEGS + 255) / 256)                // 9766

// ---------------- device scratch (static allocations only; zero-initialized) ----------------
__device__ float d_y[B * FDIM];            // conv output, pre-bn1
__device__ float d_h[B * EDIM];            // fc output, pre-bn2
__device__ __half d_wcat[256 * KFC];       // fc_w fp16; rows 200..255 never written (stay 0)
__device__ __half d_zcat[B * KH];          // fp16 z; cols 200..255 never written (stay 0)
__device__ __half d_ecat[ENT_PAD * KH];    // fp16 e; pad rows/cols never written (stay 0)
__device__ float d_chsumB[16][32];         // bn1 partials, bucketed; RESET EVERY CALL
__device__ float d_chsqB[16][32];          // RESET EVERY CALL
__device__ float d_bn0B[16][2];            // bn0 partials, bucketed; RESET EVERY CALL

// ---------------- PTX helpers (sm_80-compatible subset only) ----------------
__device__ __forceinline__ uint32_t smem_u32(const void* p) {
    uint32_t a;
    asm("{ .reg .u64 t; cvta.to.shared.u64 t, %1; cvt.u32.u64 %0, t; }" : "=r"(a) : "l"(p));
    return a;
}
__device__ __forceinline__ void cp_async16(uint32_t dst, const void* src) {
    asm volatile("cp.async.cg.shared.global [%0], [%1], 16;" :: "r"(dst), "l"(src) : "memory");
}
__device__ __forceinline__ void cp_commit() {
    asm volatile("cp.async.commit_group;" ::: "memory");
}
__device__ __forceinline__ void ldm4(uint32_t* r, uint32_t a) {
    asm volatile("ldmatrix.sync.aligned.m8n8.x4.shared.b16 {%0,%1,%2,%3}, [%4];"
                 : "=r"(r[0]), "=r"(r[1]), "=r"(r[2]), "=r"(r[3]) : "r"(a));
}
__device__ __forceinline__ void mma16816h(float* d, const uint32_t* a, const uint32_t* b) {
    asm volatile("mma.sync.aligned.m16n8k16.row.col.f32.f16.f16.f32 "
                 "{%0,%1,%2,%3}, {%4,%5,%6,%7}, {%8,%9}, {%0,%1,%2,%3};"
                 : "+f"(d[0]), "+f"(d[1]), "+f"(d[2]), "+f"(d[3])
                 : "r"(a[0]), "r"(a[1]), "r"(a[2]), "r"(a[3]), "r"(b[0]), "r"(b[1]));
}
__device__ __forceinline__ uint32_t swz(uint32_t off) { return off ^ ((off >> 3) & 0x70); }
__device__ __forceinline__ uint32_t pack_h2(__half a, __half b) {
    return (uint32_t)__half_as_ushort(a) | ((uint32_t)__half_as_ushort(b) << 16);
}
__device__ __forceinline__ float sigmoid_fast(float v) {
    float t;
    asm("tanh.approx.f32 %0, %1;" : "=f"(t) : "f"(0.5f * v));
    return fmaf(0.5f, t, 0.5f);
}

// ---------------- K_prep (launch 1): e->fp16, fc_w->fp16, zero d_h + partials ----------------
__global__ void __launch_bounds__(256) k_prep(const float* __restrict__ emb,
                                              const float* __restrict__ fc_w) {
    int gi = blockIdx.x * 256 + threadIdx.x;
    if (gi < B * EDIM) d_h[gi] = 0.f;
    if (gi < 512) { (&d_chsumB[0][0])[gi] = 0.f; (&d_chsqB[0][0])[gi] = 0.f; }
    if (gi < 32) (&d_bn0B[0][0])[gi] = 0.f;

    // fc_w -> d_wcat fp16, rows < 200 only. 200*576 = 115200 segments.
    if (gi < EDIM * (KFC / 8)) {
        int row = gi / (KFC / 8), c0 = (gi % (KFC / 8)) * 8;
        const float* src = fc_w + (size_t)row * KFC + c0;
        float4 f0 = *(const float4*)src;
        float4 f1 = *(const float4*)(src + 4);
        uint32_t p0 = pack_h2(__float2half(f0.x), __float2half(f0.y));
        uint32_t p1 = pack_h2(__float2half(f0.z), __float2half(f0.w));
        uint32_t p2 = pack_h2(__float2half(f1.x), __float2half(f1.y));
        uint32_t p3 = pack_h2(__float2half(f1.z), __float2half(f1.w));
        *(uint4*)(d_wcat + (size_t)row * KFC + c0) = make_uint4(p0, p1, p2, p3);
    }

    // emb -> d_ecat fp16: row = gi/25, cols [c0, c0+8)
    if (gi < ESEGS) {
        int row = gi / 25, c0 = (gi - row * 25) * 8;
        const float* src = emb + (size_t)row * EDIM + c0;
        float4 f0 = *(const float4*)src;
        float4 f1 = *(const float4*)(src + 4);
        uint32_t p0 = pack_h2(__float2half(f0.x), __float2half(f0.y));
        uint32_t p1 = pack_h2(__float2half(f0.z), __float2half(f0.w));
        uint32_t p2 = pack_h2(__float2half(f1.x), __float2half(f1.y));
        uint32_t p3 = pack_h2(__float2half(f1.z), __float2half(f1.w));
        *(uint4*)(d_ecat + (size_t)row * KH + c0) = make_uint4(p0, p1, p2, p3);
    }
}

// ---------------- K1 (launch 2): bn0 stats -> per-block bucket ----------------
__global__ void k1_bn0(const int* __restrict__ e1, const float* __restrict__ emb) {
    int tid = threadIdx.x, lane = tid & 31;
    float s = 0.f, q = 0.f;
    for (int idx = blockIdx.x * 512 + tid; idx < B * EDIM; idx += gridDim.x * 512) {
        int b = idx / EDIM, j = idx - b * EDIM;
        float v = emb[(size_t)e1[b] * EDIM + j];
        s += v; q += v * v;
    }
    #pragma unroll
    for (int o = 16; o; o >>= 1) {
        s += __shfl_down_sync(0xffffffffu, s, o);
        q += __shfl_down_sync(0xffffffffu, q, o);
    }
    if (lane == 0) {
        atomicAdd(&d_bn0B[blockIdx.x][0], s);   // 16 warps -> own bucket
        atomicAdd(&d_bn0B[blockIdx.x][1], q);
    }
}

// ---------------- K2 (launch 3): conv; bn0 from buckets; bn1 partials bucketed ----------------
__global__ void k2_conv(const int* __restrict__ e1, const int* __restrict__ rel,
                        const float* __restrict__ emb,
                        const float* __restrict__ conv_w, const float* __restrict__ conv_b,
                        const float* __restrict__ g0, const float* __restrict__ b0) {
    __shared__ float sx[200];
    __shared__ float sw[288];
    __shared__ float scb[32];
    __shared__ float sbn[2];
    int b = blockIdx.x;
    int tid = threadIdx.x;
    int r = rel[b];

    // reduce 16 bn0 buckets (32 lanes: 16 sums + 16 sumsqs)
    if (tid < 32) {
        float v = (tid < 16) ? d_bn0B[tid][0] : d_bn0B[tid - 16][1];
        #pragma unroll
        for (int o = 8; o; o >>= 1) v += __shfl_down_sync(0xffffffffu, v, o, 16);
        if ((tid & 15) == 0) sbn[tid >> 4] = v;
    }
    __syncthreads();
    const float inv0 = 1.f / (float)(B * EDIM);
    float m0v = sbn[0] * inv0;
    float var0 = sbn[1] * inv0 - m0v * m0v;
    float bn_s = rsqrtf(var0 + EPS) * g0[0];
    float bn_b = b0[0] - m0v * bn_s;

    if (tid < 200) sx[tid] = fmaf(emb[(size_t)e1[b] * EDIM + tid], bn_s, bn_b);
    for (int i = tid; i < 288; i += 256) sw[i] = conv_w[(size_t)r * 288 + i];
    if (tid < 32) scb[tid] = conv_b[(size_t)r * 32 + tid];
    __syncthreads();

    int o = tid >> 3;
    int i = tid & 7;
    const float* w = &sw[o * 9];
    float cb = scb[o];
    float ls = 0.f, lq = 0.f;
    float* yrow = &d_y[(size_t)b * FDIM + o * 144 + i * 18];
    #pragma unroll
    for (int j = 0; j < 18; j++) {
        float acc = cb;
        #pragma unroll
        for (int di = 0; di < 3; di++)
            #pragma unroll
            for (int dj = 0; dj < 3; dj++)
                acc = fmaf(sx[(i + di) * 20 + (j + dj)], w[di * 3 + dj], acc);
        yrow[j] = acc;
        ls += acc; lq += acc * acc;
    }
    #pragma unroll
    for (int off = 4; off; off >>= 1) {
        ls += __shfl_down_sync(0xffffffffu, ls, off, 8);
        lq += __shfl_down_sync(0xffffffffu, lq, off, 8);
    }
    if ((tid & 7) == 0) {                    // bucketed: 32 CTAs/bucket -> low contention
        atomicAdd(&d_chsumB[b & 15][o], ls);
        atomicAdd(&d_chsqB[b & 15][o], lq);
    }
}

// ---------------- K3 (launch 4): fc GEMM fp16 mma; A transformed in-kernel ----------------
// CTA 64m x 128n; warps 2(m) x 4(n), warp tile 32x32. K split 24 x 192 (3 chunks of 64).
// A tile: fp32 d_y -> bn1 affine + relu -> fp16 STS (swizzled). B: cp.async from d_wcat.
#define F_TA 0
#define F_TB 8192
#define F_ST 24576
#define F_SMEM (2 * F_ST)

__device__ __forceinline__ void k3_transformA(char* smem, int buf, int kcol, int m0, int tid,
                                              const float* s_a, const float* s_c) {
    #pragma unroll
    for (int i = 0; i < 2; i++) {
        int idx = tid + i * 256;             // < 512: 64 rows x 8 segs
        int row = idx >> 3, u = idx & 7;
        const float* src = d_y + (size_t)(m0 + row) * KFC + kcol + u * 8;
        float4 f0 = *(const float4*)src;
        float4 f1 = *(const float4*)(src + 4);
        float v[8] = {f0.x, f0.y, f0.z, f0.w, f1.x, f1.y, f1.z, f1.w};
        uint32_t p[4];
        #pragma unroll
        for (int t2 = 0; t2 < 4; t2++) {
            int ka = kcol + u * 8 + 2 * t2;
            int ca = ka / 144, cb = (ka + 1) / 144;
            __half ha = __float2half(fmaxf(fmaf(v[2 * t2],     s_a[ca], s_c[ca]), 0.f));
            __half hb = __float2half(fmaxf(fmaf(v[2 * t2 + 1], s_a[cb], s_c[cb]), 0.f));
            p[t2] = pack_h2(ha, hb);
        }
        *(uint4*)(smem + buf * F_ST + F_TA + swz(row * 128 + u * 16)) =
            make_uint4(p[0], p[1], p[2], p[3]);
    }
}
__device__ __forceinline__ void k3_loadB(uint32_t sb, int buf, int kcol, int n0, int tid) {
    uint32_t base = sb + buf * F_ST;
    #pragma unroll
    for (int i = 0; i < 4; i++) {            // B: 128 rows x 128B
        int idx = tid + i * 256;
        int row = idx >> 3, u = idx & 7;
        cp_async16(base + F_TB + swz(row * 128 + u * 16),
                   d_wcat + (size_t)(n0 + row) * KFC + kcol + u * 8);
    }
    cp_commit();
}

__global__ void __launch_bounds__(256) k3_mma(const float* __restrict__ g1,
                                              const float* __restrict__ b1) {
    extern __shared__ char smem[];
    const uint32_t sb = smem_u32(smem);
    __shared__ float s_a[32], s_c[32];
    int tid = threadIdx.x, lane = tid & 31, wid = tid >> 5;
    int wm = wid & 1, wn = wid >> 1;         // 2(m) x 4(n)
    int n0 = blockIdx.x * 128, m0 = blockIdx.y * 64;
    int kb = blockIdx.z * 192;

    if (tid < 32) {                          // bn1 affine from 16 buckets
        float cs = 0.f, cq = 0.f;
        #pragma unroll
        for (int j = 0; j < 16; j++) { cs += d_chsumB[j][tid]; cq += d_chsqB[j][tid]; }
        const float inv = 1.f / (float)(B * 144);
        float m = cs * inv;
        float var = cq * inv - m * m;
        float a = rsqrtf(var + EPS) * g1[tid];
        s_a[tid] = a;
        s_c[tid] = b1[tid] - m * a;
    }
    __syncthreads();

    float acc[2][4][4];
    #pragma unroll
    for (int f = 0; f < 2; f++)
        #pragma unroll
        for (int h = 0; h < 4; h++)
            #pragma unroll
            for (int i = 0; i < 4; i++) acc[f][h][i] = 0.f;

    k3_transformA(smem, 0, kb, m0, tid, s_a, s_c);
    k3_loadB(sb, 0, kb, n0, tid);

    for (int c = 0; c < 3; c++) {
        int buf = c & 1;
        if (c < 2) {
            k3_transformA(smem, buf ^ 1, kb + (c + 1) * 64, m0, tid, s_a, s_c);
            k3_loadB(sb, buf ^ 1, kb + (c + 1) * 64, n0, tid);
            asm volatile("cp.async.wait_group 1;" ::: "memory");
        } else {
            asm volatile("cp.async.wait_group 0;" ::: "memory");
        }
        __syncthreads();

        const uint32_t st = sb + buf * F_ST;
        #pragma unroll
        for (int s = 0; s < 4; s++) {
            uint32_t a[2][4];
            #pragma unroll
            for (int f = 0; f < 2; f++) {
                int row = wm * 32 + f * 16 + (lane & 15);
                int u = s * 2 + (lane >> 4);
                ldm4(a[f], st + F_TA + swz(row * 128 + u * 16));
            }
            #pragma unroll
            for (int j = 0; j < 2; j++) {
                uint32_t b[4];
                int row = wn * 32 + j * 16 + ((lane >> 4) << 3) + (lane & 7);
                int u = s * 2 + ((lane >> 3) & 1);
                ldm4(b, st + F_TB + swz(row * 128 + u * 16));
                #pragma unroll
                for (int g = 0; g < 2; g++)
                    #pragma unroll
                    for (int f = 0; f < 2; f++)
                        mma16816h(acc[f][j * 2 + g], a[f], b + g * 2);
            }
        }
        __syncthreads();
    }

    int g = lane >> 2, q = lane & 3;
    #pragma unroll
    for (int f = 0; f < 2; f++) {
        int mrow = m0 + wm * 32 + f * 16 + g;
        #pragma unroll
        for (int h = 0; h < 4; h++) {
            int n = n0 + wn * 32 + h * 8 + q * 2;
            if (n < EDIM) {
                atomicAdd(&d_h[(size_t)mrow * EDIM + n],           acc[f][h][0]);
                atomicAdd(&d_h[(size_t)mrow * EDIM + n + 1],       acc[f][h][1]);
                atomicAdd(&d_h[(size_t)(mrow + 8) * EDIM + n],     acc[f][h][2]);
                atomicAdd(&d_h[(size_t)(mrow + 8) * EDIM + n + 1], acc[f][h][3]);
            }
        }
    }
}

// ---------------- K4 (launch 5): bn2 + relu, emit fp16 z ----------------
__global__ void k4_bn2(const float* __restrict__ g2, const float* __restrict__ b2) {
    int n = blockIdx.x;        // feature 0..199
    int t = threadIdx.x;       // 256
    float v0 = d_h[(size_t)t * EDIM + n];
    float v1 = d_h[(size_t)(t + 256) * EDIM + n];
    __shared__ float rs[256], rq[256];
    rs[t] = v0 + v1; rq[t] = v0 * v0 + v1 * v1;
    __syncthreads();
    for (int o = 128; o; o >>= 1) {
        if (t < o) { rs[t] += rs[t + o]; rq[t] += rq[t + o]; }
        __syncthreads();
    }
    __shared__ float sa, sc;
    if (t == 0) {
        float m = rs[0] * (1.f / 512.f);
        float var = rq[0] * (1.f / 512.f) - m * m;
        float a = rsqrtf(var + EPS) * g2[n];
        sa = a; sc = b2[n] - m * a;
    }
    __syncthreads();
    float z0 = fmaxf(fmaf(v0, sa, sc), 0.f);
    float z1 = fmaxf(fmaf(v1, sa, sc), 0.f);
    d_zcat[(size_t)t * KH + n]         = __float2half(z0);
    d_zcat[(size_t)(t + 256) * KH + n] = __float2half(z1);
}

// ---------------- K5 (launch 6): fp16 mma.sync GEMM + bias + sigmoid ----------------
#define T_A 0
#define T_B 8192
#define ST_STRIDE 40960
#define K5_SMEM (2 * ST_STRIDE)

__device__ __forceinline__ void k5_load(uint32_t sb, int buf, int ks, int m0, int n0, int tid) {
    uint32_t base = sb + buf * ST_STRIDE;
    int koff = ks * 64;
    if (ks < 3) {
        #pragma unroll
        for (int i = 0; i < 2; i++) {                // A: 64 rows x 128B
            int idx = tid + i * 256;
            int row = idx >> 3, u = idx & 7;
            cp_async16(base + T_A + swz(row * 128 + u * 16),
                       d_zcat + (size_t)(m0 + row) * KH + koff + u * 8);
        }
        #pragma unroll
        for (int i = 0; i < 8; i++) {                // B: 256 rows x 128B
            int idx = tid + i * 256;
            int row = idx >> 3, u = idx & 7;
            cp_async16(base + T_B + swz(row * 128 + u * 16),
                       d_ecat + (size_t)(n0 + row) * KH + koff + u * 8);
        }
    } else {
        // ks=3: only 16 cols needed (s=0 reads u in {0,1})
        if (tid < 128) {                             // A: 64 rows x 2 segs
            int row = tid >> 1, u = tid & 1;
            cp_async16(base + T_A + swz(row * 128 + u * 16),
                       d_zcat + (size_t)(m0 + row) * KH + koff + u * 8);
        }
        #pragma unroll
        for (int i = 0; i < 2; i++) {                // B: 256 rows x 2 segs
            int idx = tid + i * 256;
            int row = idx >> 1, u = idx & 1;
            cp_async16(base + T_B + swz(row * 128 + u * 16),
                       d_ecat + (size_t)(n0 + row) * KH + koff + u * 8);
        }
    }
    cp_commit();
}

__global__ void __launch_bounds__(256, 2) k5_mma(const float* __restrict__ bias_e,
                                                 float* __restrict__ out) {
    extern __shared__ char smem[];
    const uint32_t sb = smem_u32(smem);
    int tid = threadIdx.x, lane = tid & 31, wid = tid >> 5;
    int wm = wid & 1, wn = wid >> 1;                 // 2(m) x 4(n)
    int m0 = blockIdx.x * 64, n0 = blockIdx.y * 256;

    float acc[2][8][4];
    #pragma unroll
    for (int f = 0; f < 2; f++)
        #pragma unroll
        for (int h = 0; h < 8; h++)
            #pragma unroll
            for (int i = 0; i < 4; i++) acc[f][h][i] = 0.f;

    k5_load(sb, 0, 0, m0, n0, tid);

    for (int ks = 0; ks < 4; ks++) {
        int buf = ks & 1;
        if (ks < 3) {
            k5_load(sb, buf ^ 1, ks + 1, m0, n0, tid);
            asm volatile("cp.async.wait_group 1;" ::: "memory");
        } else {
            asm volatile("cp.async.wait_group 0;" ::: "memory");
        }
        __syncthreads();

        const int scount = (ks < 3) ? 4 : 1;         // quarter 3: cols 192..199 only
        const uint32_t st = sb + buf * ST_STRIDE;
        for (int s = 0; s < scount; s++) {
            uint32_t a[2][4];
            #pragma unroll
            for (int f = 0; f < 2; f++) {
                int row = wm * 32 + f * 16 + (lane & 15);
                int u = s * 2 + (lane >> 4);
                ldm4(a[f], st + T_A + swz(row * 128 + u * 16));
            }
            #pragma unroll
            for (int j = 0; j < 4; j++) {
                uint32_t b[4];
                int row = wn * 64 + j * 16 + ((lane >> 4) << 3) + (lane & 7);
                int u = s * 2 + ((lane >> 3) & 1);
                ldm4(b, st + T_B + swz(row * 128 + u * 16));
                #pragma unroll
                for (int g = 0; g < 2; g++)
                    #pragma unroll
                    for (int f = 0; f < 2; f++)
                        mma16816h(acc[f][j * 2 + g], a[f], b + g * 2);
            }
        }
        __syncthreads();
    }

    int g = lane >> 2, q = lane & 3;
    #pragma unroll
    for (int f = 0; f < 2; f++) {
        int mrow = m0 + wm * 32 + f * 16 + g;
        #pragma unroll
        for (int h = 0; h < 8; h++) {
            int n = n0 + wn * 64 + h * 8 + q * 2;
            if (n < NUM_ENT) {
                float b0 = bias_e[n], b1 = bias_e[n + 1];
                *(float2*)&out[(size_t)mrow * NUM_ENT + n] =
                    make_float2(sigmoid_fast(acc[f][h][0] + b0),
                                sigmoid_fast(acc[f][h][1] + b1));
                *(float2*)&out[(size_t)(mrow + 8) * NUM_ENT + n] =
                    make_float2(sigmoid_fast(acc[f][h][2] + b0),
                                sigmoid_fast(acc[f][h][3] + b1));
            }
        }
    }
}

// ---------------- launcher (6 launches) ----------------
extern "C" void kernel_launch(void* const* d_in, const int* in_sizes, int n_in,
                              void* d_out, int out_size) {
    const int*   e1     = (const int*)d_in[0];
    const int*   rel    = (const int*)d_in[1];
    const float* emb    = (const float*)d_in[2];
    const float* conv_w = (const float*)d_in[3];
    const float* conv_b = (const float*)d_in[4];
    const float* g0     = (const float*)d_in[5];
    const float* b0     = (const float*)d_in[6];
    const float* g1     = (const float*)d_in[7];
    const float* b1     = (const float*)d_in[8];
    const float* g2     = (const float*)d_in[9];
    const float* b2     = (const float*)d_in[10];
    const float* fc_w   = (const float*)d_in[11];
    // d_in[12] = fc_b: cancels exactly under training-mode bn2
    const float* bias_e = (const float*)d_in[13];
    float* out = (float*)d_out;

    cudaFuncSetAttribute(k3_mma, cudaFuncAttributeMaxDynamicSharedMemorySize, F_SMEM);
    cudaFuncSetAttribute(k5_mma, cudaFuncAttributeMaxDynamicSharedMemorySize, K5_SMEM);

    k_prep<<<PREP_GRID, 256>>>(emb, fc_w);
    k1_bn0<<<16, 512>>>(e1, emb);
    k2_conv<<<B, 256>>>(e1, rel, emb, conv_w, conv_b, g0, b0);
    k3_mma<<<dim3(2, 8, 24), 256, F_SMEM>>>(g1, b1);
    k4_bn2<<<EDIM, 256>>>(g2, b2);
    k5_mma<<<dim3(8, N_GRID), 256, K5_SMEM>>>(bias_e, out);
}

// round 13
// speedup vs baseline: 2.9167x; 1.0191x over previous
#include <cuda_runtime.h>
#include <cuda_bf16.h>
#include <cuda_fp16.h>
#include <cstdint>

#define B 512
#define EDIM 200
#define NUM_ENT 100000
#define FDIM 4608          // 32*8*18
#define KFC 4608
#define EPS 1e-5f
#define KH 256             // fp16 K padded 200 -> 256
#define ENT_TILE 256
#define N_GRID ((NUM_ENT + ENT_TILE - 1) / ENT_TILE)   // 391
#define ENT_PAD (N_GRID * ENT_TILE)                    // 100096
#define ESEGS (NUM_ENT * 25)                           // 2.5M 8-col segments
#define PREPE_GRID ((ESEGS + 255) / 256)               // 9766
#define WSEGS (EDIM * (KFC / 8))                       // 115200
#define PREPW_GRID ((WSEGS + 255) / 256)               // 451

// ---------------- device scratch (static allocations only; zero-initialized) ----------------
__device__ float d_y[B * FDIM];            // conv output, pre-bn1
__device__ float d_h[B * EDIM];            // fc output, pre-bn2 (zeroed per call by prep_w)
__device__ __half d_wcat[256 * KFC];       // fc_w fp16; rows 200..255 never written (stay 0)
__device__ __half d_zcat[B * KH];          // fp16 z; cols 200..255 never written (stay 0)
__device__ __half d_ecat[ENT_PAD * KH];    // fp16 e; pad rows/cols never written (stay 0)
__device__ float d_chsumB[16][32];         // bn1 partials; bucket b zeroed by k1 block b
__device__ float d_chsqB[16][32];
__device__ float d_bn0B[16][2];            // bn0 partials; STORED (not accumulated) by k1

// ---------------- PTX helpers (sm_80-compatible subset only) ----------------
__device__ __forceinline__ uint32_t smem_u32(const void* p) {
    uint32_t a;
    asm("{ .reg .u64 t; cvta.to.shared.u64 t, %1; cvt.u32.u64 %0, t; }" : "=r"(a) : "l"(p));
    return a;
}
__device__ __forceinline__ void cp_async16(uint32_t dst, const void* src) {
    asm volatile("cp.async.cg.shared.global [%0], [%1], 16;" :: "r"(dst), "l"(src) : "memory");
}
__device__ __forceinline__ void cp_commit() {
    asm volatile("cp.async.commit_group;" ::: "memory");
}
__device__ __forceinline__ void ldm4(uint32_t* r, uint32_t a) {
    asm volatile("ldmatrix.sync.aligned.m8n8.x4.shared.b16 {%0,%1,%2,%3}, [%4];"
                 : "=r"(r[0]), "=r"(r[1]), "=r"(r[2]), "=r"(r[3]) : "r"(a));
}
__device__ __forceinline__ void mma16816h(float* d, const uint32_t* a, const uint32_t* b) {
    asm volatile("mma.sync.aligned.m16n8k16.row.col.f32.f16.f16.f32 "
                 "{%0,%1,%2,%3}, {%4,%5,%6,%7}, {%8,%9}, {%0,%1,%2,%3};"
                 : "+f"(d[0]), "+f"(d[1]), "+f"(d[2]), "+f"(d[3])
                 : "r"(a[0]), "r"(a[1]), "r"(a[2]), "r"(a[3]), "r"(b[0]), "r"(b[1]));
}
__device__ __forceinline__ uint32_t swz(uint32_t off) { return off ^ ((off >> 3) & 0x70); }
__device__ __forceinline__ uint32_t pack_h2(__half a, __half b) {
    return (uint32_t)__half_as_ushort(a) | ((uint32_t)__half_as_ushort(b) << 16);
}
__device__ __forceinline__ float sigmoid_fast(float v) {
    float t;
    asm("tanh.approx.f32 %0, %1;" : "=f"(t) : "f"(0.5f * v));
    return fmaf(0.5f, t, 0.5f);
}

// ---------------- prep_w (side stream): fc_w->fp16 + zero d_h ----------------
__global__ void __launch_bounds__(256) k_prep_w(const float* __restrict__ fc_w) {
    int gi = blockIdx.x * 256 + threadIdx.x;
    if (gi < B * EDIM) d_h[gi] = 0.f;
    if (gi < WSEGS) {
        int row = gi / (KFC / 8), c0 = (gi % (KFC / 8)) * 8;
        const float* src = fc_w + (size_t)row * KFC + c0;
        float4 f0 = *(const float4*)src;
        float4 f1 = *(const float4*)(src + 4);
        uint32_t p0 = pack_h2(__float2half(f0.x), __float2half(f0.y));
        uint32_t p1 = pack_h2(__float2half(f0.z), __float2half(f0.w));
        uint32_t p2 = pack_h2(__float2half(f1.x), __float2half(f1.y));
        uint32_t p3 = pack_h2(__float2half(f1.z), __float2half(f1.w));
        *(uint4*)(d_wcat + (size_t)row * KFC + c0) = make_uint4(p0, p1, p2, p3);
    }
}

// ---------------- prep_e (side stream): emb -> fp16 ecat ----------------
__global__ void __launch_bounds__(256) k_prep_e(const float* __restrict__ emb) {
    int gi = blockIdx.x * 256 + threadIdx.x;
    if (gi < ESEGS) {
        int row = gi / 25, c0 = (gi - row * 25) * 8;
        const float* src = emb + (size_t)row * EDIM + c0;
        float4 f0 = *(const float4*)src;
        float4 f1 = *(const float4*)(src + 4);
        uint32_t p0 = pack_h2(__float2half(f0.x), __float2half(f0.y));
        uint32_t p1 = pack_h2(__float2half(f0.z), __float2half(f0.w));
        uint32_t p2 = pack_h2(__float2half(f1.x), __float2half(f1.y));
        uint32_t p3 = pack_h2(__float2half(f1.z), __float2half(f1.w));
        *(uint4*)(d_ecat + (size_t)row * KH + c0) = make_uint4(p0, p1, p2, p3);
    }
}

// ---------------- K1 (main): bn0 stats; block-reduce + STORE; zero own bn1 bucket ----------------
__global__ void k1_bn0(const int* __restrict__ e1, const float* __restrict__ emb) {
    __shared__ float ws[16], wq[16];
    int tid = threadIdx.x, lane = tid & 31, wrp = tid >> 5;
    if (tid < 32) { d_chsumB[blockIdx.x][tid] = 0.f; d_chsqB[blockIdx.x][tid] = 0.f; }
    float s = 0.f, q = 0.f;
    for (int idx = blockIdx.x * 512 + tid; idx < B * EDIM; idx += gridDim.x * 512) {
        int b = idx / EDIM, j = idx - b * EDIM;
        float v = emb[(size_t)e1[b] * EDIM + j];
        s += v; q += v * v;
    }
    #pragma unroll
    for (int o = 16; o; o >>= 1) {
        s += __shfl_down_sync(0xffffffffu, s, o);
        q += __shfl_down_sync(0xffffffffu, q, o);
    }
    if (lane == 0) { ws[wrp] = s; wq[wrp] = q; }
    __syncthreads();
    if (tid < 16) {
        float v1 = ws[tid], v2 = wq[tid];
        #pragma unroll
        for (int o = 8; o; o >>= 1) {
            v1 += __shfl_down_sync(0xffffu, v1, o, 16);
            v2 += __shfl_down_sync(0xffffu, v2, o, 16);
        }
        if (tid == 0) { d_bn0B[blockIdx.x][0] = v1; d_bn0B[blockIdx.x][1] = v2; }
    }
}

// ---------------- K2 (main): conv; bn0 from buckets; bn1 partials bucketed ----------------
__global__ void k2_conv(const int* __restrict__ e1, const int* __restrict__ rel,
                        const float* __restrict__ emb,
                        const float* __restrict__ conv_w, const float* __restrict__ conv_b,
                        const float* __restrict__ g0, const float* __restrict__ b0) {
    __shared__ float sx[200];
    __shared__ float sw[288];
    __shared__ float scb[32];
    __shared__ float sbn[2];
    int b = blockIdx.x;
    int tid = threadIdx.x;
    int r = rel[b];

    if (tid < 32) {
        float v = (tid < 16) ? d_bn0B[tid][0] : d_bn0B[tid - 16][1];
        #pragma unroll
        for (int o = 8; o; o >>= 1) v += __shfl_down_sync(0xffffffffu, v, o, 16);
        if ((tid & 15) == 0) sbn[tid >> 4] = v;
    }
    __syncthreads();
    const float inv0 = 1.f / (float)(B * EDIM);
    float m0v = sbn[0] * inv0;
    float var0 = sbn[1] * inv0 - m0v * m0v;
    float bn_s = rsqrtf(var0 + EPS) * g0[0];
    float bn_b = b0[0] - m0v * bn_s;

    if (tid < 200) sx[tid] = fmaf(emb[(size_t)e1[b] * EDIM + tid], bn_s, bn_b);
    for (int i = tid; i < 288; i += 256) sw[i] = conv_w[(size_t)r * 288 + i];
    if (tid < 32) scb[tid] = conv_b[(size_t)r * 32 + tid];
    __syncthreads();

    int o = tid >> 3;
    int i = tid & 7;
    const float* w = &sw[o * 9];
    float cb = scb[o];
    float ls = 0.f, lq = 0.f;
    float* yrow = &d_y[(size_t)b * FDIM + o * 144 + i * 18];
    #pragma unroll
    for (int j = 0; j < 18; j++) {
        float acc = cb;
        #pragma unroll
        for (int di = 0; di < 3; di++)
            #pragma unroll
            for (int dj = 0; dj < 3; dj++)
                acc = fmaf(sx[(i + di) * 20 + (j + dj)], w[di * 3 + dj], acc);
        yrow[j] = acc;
        ls += acc; lq += acc * acc;
    }
    #pragma unroll
    for (int off = 4; off; off >>= 1) {
        ls += __shfl_down_sync(0xffffffffu, ls, off, 8);
        lq += __shfl_down_sync(0xffffffffu, lq, off, 8);
    }
    if ((tid & 7) == 0) {
        atomicAdd(&d_chsumB[b & 15][o], ls);
        atomicAdd(&d_chsqB[b & 15][o], lq);
    }
}

// ---------------- K3 (main, after prep_w join): fc GEMM fp16 mma ----------------
#define F_TA 0
#define F_TB 8192
#define F_ST 24576
#define F_SMEM (2 * F_ST)

__device__ __forceinline__ void k3_transformA(char* smem, int buf, int kcol, int m0, int tid,
                                              const float* s_a, const float* s_c) {
    #pragma unroll
    for (int i = 0; i < 2; i++) {
        int idx = tid + i * 256;
        int row = idx >> 3, u = idx & 7;
        const float* src = d_y + (size_t)(m0 + row) * KFC + kcol + u * 8;
        float4 f0 = *(const float4*)src;
        float4 f1 = *(const float4*)(src + 4);
        float v[8] = {f0.x, f0.y, f0.z, f0.w, f1.x, f1.y, f1.z, f1.w};
        uint32_t p[4];
        #pragma unroll
        for (int t2 = 0; t2 < 4; t2++) {
            int ka = kcol + u * 8 + 2 * t2;
            int ca = ka / 144, cb = (ka + 1) / 144;
            __half ha = __float2half(fmaxf(fmaf(v[2 * t2],     s_a[ca], s_c[ca]), 0.f));
            __half hb = __float2half(fmaxf(fmaf(v[2 * t2 + 1], s_a[cb], s_c[cb]), 0.f));
            p[t2] = pack_h2(ha, hb);
        }
        *(uint4*)(smem + buf * F_ST + F_TA + swz(row * 128 + u * 16)) =
            make_uint4(p[0], p[1], p[2], p[3]);
    }
}
__device__ __forceinline__ void k3_loadB(uint32_t sb, int buf, int kcol, int n0, int tid) {
    uint32_t base = sb + buf * F_ST;
    #pragma unroll
    for (int i = 0; i < 4; i++) {
        int idx = tid + i * 256;
        int row = idx >> 3, u = idx & 7;
        cp_async16(base + F_TB + swz(row * 128 + u * 16),
                   d_wcat + (size_t)(n0 + row) * KFC + kcol + u * 8);
    }
    cp_commit();
}

__global__ void __launch_bounds__(256) k3_mma(const float* __restrict__ g1,
                                              const float* __restrict__ b1) {
    extern __shared__ char smem[];
    const uint32_t sb = smem_u32(smem);
    __shared__ float s_a[32], s_c[32];
    int tid = threadIdx.x, lane = tid & 31, wid = tid >> 5;
    int wm = wid & 1, wn = wid >> 1;
    int n0 = blockIdx.x * 128, m0 = blockIdx.y * 64;
    int kb = blockIdx.z * 192;

    if (tid < 32) {
        float cs = 0.f, cq = 0.f;
        #pragma unroll
        for (int j = 0; j < 16; j++) { cs += d_chsumB[j][tid]; cq += d_chsqB[j][tid]; }
        const float inv = 1.f / (float)(B * 144);
        float m = cs * inv;
        float var = cq * inv - m * m;
        float a = rsqrtf(var + EPS) * g1[tid];
        s_a[tid] = a;
        s_c[tid] = b1[tid] - m * a;
    }
    __syncthreads();

    float acc[2][4][4];
    #pragma unroll
    for (int f = 0; f < 2; f++)
        #pragma unroll
        for (int h = 0; h < 4; h++)
            #pragma unroll
            for (int i = 0; i < 4; i++) acc[f][h][i] = 0.f;

    k3_transformA(smem, 0, kb, m0, tid, s_a, s_c);
    k3_loadB(sb, 0, kb, n0, tid);

    for (int c = 0; c < 3; c++) {
        int buf = c & 1;
        if (c < 2) {
            k3_transformA(smem, buf ^ 1, kb + (c + 1) * 64, m0, tid, s_a, s_c);
            k3_loadB(sb, buf ^ 1, kb + (c + 1) * 64, n0, tid);
            asm volatile("cp.async.wait_group 1;" ::: "memory");
        } else {
            asm volatile("cp.async.wait_group 0;" ::: "memory");
        }
        __syncthreads();

        const uint32_t st = sb + buf * F_ST;
        #pragma unroll
        for (int s = 0; s < 4; s++) {
            uint32_t a[2][4];
            #pragma unroll
            for (int f = 0; f < 2; f++) {
                int row = wm * 32 + f * 16 + (lane & 15);
                int u = s * 2 + (lane >> 4);
                ldm4(a[f], st + F_TA + swz(row * 128 + u * 16));
            }
            #pragma unroll
            for (int j = 0; j < 2; j++) {
                uint32_t b[4];
                int row = wn * 32 + j * 16 + ((lane >> 4) << 3) + (lane & 7);
                int u = s * 2 + ((lane >> 3) & 1);
                ldm4(b, st + F_TB + swz(row * 128 + u * 16));
                #pragma unroll
                for (int g = 0; g < 2; g++)
                    #pragma unroll
                    for (int f = 0; f < 2; f++)
                        mma16816h(acc[f][j * 2 + g], a[f], b + g * 2);
            }
        }
        __syncthreads();
    }

    int g = lane >> 2, q = lane & 3;
    #pragma unroll
    for (int f = 0; f < 2; f++) {
        int mrow = m0 + wm * 32 + f * 16 + g;
        #pragma unroll
        for (int h = 0; h < 4; h++) {
            int n = n0 + wn * 32 + h * 8 + q * 2;
            if (n < EDIM) {
                atomicAdd(&d_h[(size_t)mrow * EDIM + n],           acc[f][h][0]);
                atomicAdd(&d_h[(size_t)mrow * EDIM + n + 1],       acc[f][h][1]);
                atomicAdd(&d_h[(size_t)(mrow + 8) * EDIM + n],     acc[f][h][2]);
                atomicAdd(&d_h[(size_t)(mrow + 8) * EDIM + n + 1], acc[f][h][3]);
            }
        }
    }
}

// ---------------- K4 (main): bn2 + relu, emit fp16 z ----------------
__global__ void k4_bn2(const float* __restrict__ g2, const float* __restrict__ b2) {
    int n = blockIdx.x;
    int t = threadIdx.x;
    float v0 = d_h[(size_t)t * EDIM + n];
    float v1 = d_h[(size_t)(t + 256) * EDIM + n];
    __shared__ float rs[256], rq[256];
    rs[t] = v0 + v1; rq[t] = v0 * v0 + v1 * v1;
    __syncthreads();
    for (int o = 128; o; o >>= 1) {
        if (t < o) { rs[t] += rs[t + o]; rq[t] += rq[t + o]; }
        __syncthreads();
    }
    __shared__ float sa, sc;
    if (t == 0) {
        float m = rs[0] * (1.f / 512.f);
        float var = rq[0] * (1.f / 512.f) - m * m;
        float a = rsqrtf(var + EPS) * g2[n];
        sa = a; sc = b2[n] - m * a;
    }
    __syncthreads();
    float z0 = fmaxf(fmaf(v0, sa, sc), 0.f);
    float z1 = fmaxf(fmaf(v1, sa, sc), 0.f);
    d_zcat[(size_t)t * KH + n]         = __float2half(z0);
    d_zcat[(size_t)(t + 256) * KH + n] = __float2half(z1);
}

// ---------------- K5 (main, after prep_e join): fp16 mma GEMM + bias + sigmoid ----------------
#define T_A 0
#define T_B 8192
#define ST_STRIDE 40960
#define K5_SMEM (2 * ST_STRIDE)

__device__ __forceinline__ void k5_load(uint32_t sb, int buf, int ks, int m0, int n0, int tid) {
    uint32_t base = sb + buf * ST_STRIDE;
    int koff = ks * 64;
    if (ks < 3) {
        #pragma unroll
        for (int i = 0; i < 2; i++) {
            int idx = tid + i * 256;
            int row = idx >> 3, u = idx & 7;
            cp_async16(base + T_A + swz(row * 128 + u * 16),
                       d_zcat + (size_t)(m0 + row) * KH + koff + u * 8);
        }
        #pragma unroll
        for (int i = 0; i < 8; i++) {
            int idx = tid + i * 256;
            int row = idx >> 3, u = idx & 7;
            cp_async16(base + T_B + swz(row * 128 + u * 16),
                       d_ecat + (size_t)(n0 + row) * KH + koff + u * 8);
        }
    } else {
        if (tid < 128) {
            int row = tid >> 1, u = tid & 1;
            cp_async16(base + T_A + swz(row * 128 + u * 16),
                       d_zcat + (size_t)(m0 + row) * KH + koff + u * 8);
        }
        #pragma unroll
        for (int i = 0; i < 2; i++) {
            int idx = tid + i * 256;
            int row = idx >> 1, u = idx & 1;
            cp_async16(base + T_B + swz(row * 128 + u * 16),
                       d_ecat + (size_t)(n0 + row) * KH + koff + u * 8);
        }
    }
    cp_commit();
}

__global__ void __launch_bounds__(256, 2) k5_mma(const float* __restrict__ bias_e,
                                                 float* __restrict__ out) {
    extern __shared__ char smem[];
    const uint32_t sb = smem_u32(smem);
    int tid = threadIdx.x, lane = tid & 31, wid = tid >> 5;
    int wm = wid & 1, wn = wid >> 1;
    int m0 = blockIdx.x * 64, n0 = blockIdx.y * 256;

    float acc[2][8][4];
    #pragma unroll
    for (int f = 0; f < 2; f++)
        #pragma unroll
        for (int h = 0; h < 8; h++)
            #pragma unroll
            for (int i = 0; i < 4; i++) acc[f][h][i] = 0.f;

    k5_load(sb, 0, 0, m0, n0, tid);

    for (int ks = 0; ks < 4; ks++) {
        int buf = ks & 1;
        if (ks < 3) {
            k5_load(sb, buf ^ 1, ks + 1, m0, n0, tid);
            asm volatile("cp.async.wait_group 1;" ::: "memory");
        } else {
            asm volatile("cp.async.wait_group 0;" ::: "memory");
        }
        __syncthreads();

        const int scount = (ks < 3) ? 4 : 1;
        const uint32_t st = sb + buf * ST_STRIDE;
        for (int s = 0; s < scount; s++) {
            uint32_t a[2][4];
            #pragma unroll
            for (int f = 0; f < 2; f++) {
                int row = wm * 32 + f * 16 + (lane & 15);
                int u = s * 2 + (lane >> 4);
                ldm4(a[f], st + T_A + swz(row * 128 + u * 16));
            }
            #pragma unroll
            for (int j = 0; j < 4; j++) {
                uint32_t b[4];
                int row = wn * 64 + j * 16 + ((lane >> 4) << 3) + (lane & 7);
                int u = s * 2 + ((lane >> 3) & 1);
                ldm4(b, st + T_B + swz(row * 128 + u * 16));
                #pragma unroll
                for (int g = 0; g < 2; g++)
                    #pragma unroll
                    for (int f = 0; f < 2; f++)
                        mma16816h(acc[f][j * 2 + g], a[f], b + g * 2);
            }
        }
        __syncthreads();
    }

    int g = lane >> 2, q = lane & 3;
    #pragma unroll
    for (int f = 0; f < 2; f++) {
        int mrow = m0 + wm * 32 + f * 16 + g;
        #pragma unroll
        for (int h = 0; h < 8; h++) {
            int n = n0 + wn * 64 + h * 8 + q * 2;
            if (n < NUM_ENT) {
                float b0 = bias_e[n], b1 = bias_e[n + 1];
                *(float2*)&out[(size_t)mrow * NUM_ENT + n] =
                    make_float2(sigmoid_fast(acc[f][h][0] + b0),
                                sigmoid_fast(acc[f][h][1] + b1));
                *(float2*)&out[(size_t)(mrow + 8) * NUM_ENT + n] =
                    make_float2(sigmoid_fast(acc[f][h][2] + b0),
                                sigmoid_fast(acc[f][h][3] + b1));
            }
        }
    }
}

// ---------------- stream/event resources (host-side, created once at load) ----------------
namespace {
struct StreamRes {
    cudaStream_t side = nullptr;
    cudaEvent_t ev_fork = nullptr, ev_w = nullptr, ev_e = nullptr;
    StreamRes() {
        cudaStreamCreateWithFlags(&side, cudaStreamNonBlocking);
        cudaEventCreateWithFlags(&ev_fork, cudaEventDisableTiming);
        cudaEventCreateWithFlags(&ev_w, cudaEventDisableTiming);
        cudaEventCreateWithFlags(&ev_e, cudaEventDisableTiming);
    }
};
StreamRes g_sr;
}

// ---------------- launcher: fork prep to side stream, join before k3 / k5 ----------------
extern "C" void kernel_launch(void* const* d_in, const int* in_sizes, int n_in,
                              void* d_out, int out_size) {
    const int*   e1     = (const int*)d_in[0];
    const int*   rel    = (const int*)d_in[1];
    const float* emb    = (const float*)d_in[2];
    const float* conv_w = (const float*)d_in[3];
    const float* conv_b = (const float*)d_in[4];
    const float* g0     = (const float*)d_in[5];
    const float* b0     = (const float*)d_in[6];
    const float* g1     = (const float*)d_in[7];
    const float* b1     = (const float*)d_in[8];
    const float* g2     = (const float*)d_in[9];
    const float* b2     = (const float*)d_in[10];
    const float* fc_w   = (const float*)d_in[11];
    // d_in[12] = fc_b: cancels exactly under training-mode bn2
    const float* bias_e = (const float*)d_in[13];
    float* out = (float*)d_out;

    cudaFuncSetAttribute(k3_mma, cudaFuncAttributeMaxDynamicSharedMemorySize, F_SMEM);
    cudaFuncSetAttribute(k5_mma, cudaFuncAttributeMaxDynamicSharedMemorySize, K5_SMEM);

    // fork side stream off the main (launch) stream
    cudaEventRecord(g_sr.ev_fork, 0);
    cudaStreamWaitEvent(g_sr.side, g_sr.ev_fork, 0);
    k_prep_w<<<PREPW_GRID, 256, 0, g_sr.side>>>(fc_w);
    cudaEventRecord(g_sr.ev_w, g_sr.side);
    k_prep_e<<<PREPE_GRID, 256, 0, g_sr.side>>>(emb);
    cudaEventRecord(g_sr.ev_e, g_sr.side);

    // main chain
    k1_bn0<<<16, 512>>>(e1, emb);
    k2_conv<<<B, 256>>>(e1, rel, emb, conv_w, conv_b, g0, b0);
    cudaStreamWaitEvent(0, g_sr.ev_w, 0);            // k3 needs d_wcat + d_h zero
    k3_mma<<<dim3(2, 8, 24), 256, F_SMEM>>>(g1, b1);
    k4_bn2<<<EDIM, 256>>>(g2, b2);
    cudaStreamWaitEvent(0, g_sr.ev_e, 0);            // k5 needs d_ecat
    k5_mma<<<dim3(8, N_GRID), 256, K5_SMEM>>>(bias_e, out);
}

// round 15
// speedup vs baseline: 3.0539x; 1.0470x over previous
#include <cuda_runtime.h>
#include <cuda_bf16.h>
#include <cuda_fp16.h>
#include <cstdint>

#define B 512
#define EDIM 200
#define NUM_ENT 100000
#define FDIM 4608          // 32*8*18
#define KFC 4608
#define EPS 1e-5f
#define KH 256             // fp16 K padded 200 -> 256
#define ENT_TILE 256
#define N_GRID ((NUM_ENT + ENT_TILE - 1) / ENT_TILE)   // 391
#define ENT_PAD (N_GRID * ENT_TILE)                    // 100096
#define ESEGS (NUM_ENT * 25)                           // 2.5M 8-col segments
#define PREPE_GRID ((ESEGS + 255) / 256)               // 9766
#define WSEGS (EDIM * (KFC / 8))                       // 115200
#define PREPW_GRID ((WSEGS + 255) / 256)               // 451

// ---------------- device scratch (static allocations only; zero-initialized) ----------------
__device__ float d_y[B * FDIM];            // conv output, pre-bn1
__device__ float d_h[B * EDIM];            // fc output, pre-bn2 (zeroed per call by prep_w)
__device__ __half d_wcat[256 * KFC];       // fc_w fp16; rows 200..255 never written (stay 0)
__device__ __half d_zcat[B * KH];          // fp16 z; cols 200..255 never written (stay 0)
__device__ __half d_ecat[ENT_PAD * KH];    // fp16 e; pad rows/cols never written (stay 0)
__device__ float d_chsumB[16][32];         // bn1 partials; bucket b zeroed by k1 block b
__device__ float d_chsqB[16][32];
__device__ float d_bn0B[16][2];            // bn0 partials; STORED (not accumulated) by k1

// ---------------- PTX helpers (sm_80-compatible subset only) ----------------
__device__ __forceinline__ uint32_t smem_u32(const void* p) {
    uint32_t a;
    asm("{ .reg .u64 t; cvta.to.shared.u64 t, %1; cvt.u32.u64 %0, t; }" : "=r"(a) : "l"(p));
    return a;
}
__device__ __forceinline__ void cp_async16(uint32_t dst, const void* src) {
    asm volatile("cp.async.cg.shared.global [%0], [%1], 16;" :: "r"(dst), "l"(src) : "memory");
}
__device__ __forceinline__ void cp_commit() {
    asm volatile("cp.async.commit_group;" ::: "memory");
}
__device__ __forceinline__ void ldm4(uint32_t* r, uint32_t a) {
    asm volatile("ldmatrix.sync.aligned.m8n8.x4.shared.b16 {%0,%1,%2,%3}, [%4];"
                 : "=r"(r[0]), "=r"(r[1]), "=r"(r[2]), "=r"(r[3]) : "r"(a));
}
__device__ __forceinline__ void mma16816h(float* d, const uint32_t* a, const uint32_t* b) {
    asm volatile("mma.sync.aligned.m16n8k16.row.col.f32.f16.f16.f32 "
                 "{%0,%1,%2,%3}, {%4,%5,%6,%7}, {%8,%9}, {%0,%1,%2,%3};"
                 : "+f"(d[0]), "+f"(d[1]), "+f"(d[2]), "+f"(d[3])
                 : "r"(a[0]), "r"(a[1]), "r"(a[2]), "r"(a[3]), "r"(b[0]), "r"(b[1]));
}
__device__ __forceinline__ uint32_t swz(uint32_t off) { return off ^ ((off >> 3) & 0x70); }
__device__ __forceinline__ uint32_t pack_h2(__half a, __half b) {
    return (uint32_t)__half_as_ushort(a) | ((uint32_t)__half_as_ushort(b) << 16);
}
__device__ __forceinline__ float sigmoid_fast(float v) {
    float t;
    asm("tanh.approx.f32 %0, %1;" : "=f"(t) : "f"(0.5f * v));
    return fmaf(0.5f, t, 0.5f);
}

// ---------------- prep_w (side stream): fc_w->fp16 + zero d_h ----------------
__global__ void __launch_bounds__(256) k_prep_w(const float* __restrict__ fc_w) {
    int gi = blockIdx.x * 256 + threadIdx.x;
    if (gi < B * EDIM) d_h[gi] = 0.f;
    if (gi < WSEGS) {
        int row = gi / (KFC / 8), c0 = (gi % (KFC / 8)) * 8;
        const float* src = fc_w + (size_t)row * KFC + c0;
        float4 f0 = *(const float4*)src;
        float4 f1 = *(const float4*)(src + 4);
        uint32_t p0 = pack_h2(__float2half(f0.x), __float2half(f0.y));
        uint32_t p1 = pack_h2(__float2half(f0.z), __float2half(f0.w));
        uint32_t p2 = pack_h2(__float2half(f1.x), __float2half(f1.y));
        uint32_t p3 = pack_h2(__float2half(f1.z), __float2half(f1.w));
        *(uint4*)(d_wcat + (size_t)row * KFC + c0) = make_uint4(p0, p1, p2, p3);
    }
}

// ---------------- prep_e (side stream): emb -> fp16 ecat ----------------
__global__ void __launch_bounds__(256) k_prep_e(const float* __restrict__ emb) {
    int gi = blockIdx.x * 256 + threadIdx.x;
    if (gi < ESEGS) {
        int row = gi / 25, c0 = (gi - row * 25) * 8;
        const float* src = emb + (size_t)row * EDIM + c0;
        float4 f0 = *(const float4*)src;
        float4 f1 = *(const float4*)(src + 4);
        uint32_t p0 = pack_h2(__float2half(f0.x), __float2half(f0.y));
        uint32_t p1 = pack_h2(__float2half(f0.z), __float2half(f0.w));
        uint32_t p2 = pack_h2(__float2half(f1.x), __float2half(f1.y));
        uint32_t p3 = pack_h2(__float2half(f1.z), __float2half(f1.w));
        *(uint4*)(d_ecat + (size_t)row * KH + c0) = make_uint4(p0, p1, p2, p3);
    }
}

// ---------------- K1 (main): bn0 stats; block-reduce + STORE; zero own bn1 bucket ----------------
__global__ void k1_bn0(const int* __restrict__ e1, const float* __restrict__ emb) {
    __shared__ float ws[16], wq[16];
    int tid = threadIdx.x, lane = tid & 31, wrp = tid >> 5;
    if (tid < 32) { d_chsumB[blockIdx.x][tid] = 0.f; d_chsqB[blockIdx.x][tid] = 0.f; }
    float s = 0.f, q = 0.f;
    for (int idx = blockIdx.x * 512 + tid; idx < B * EDIM; idx += gridDim.x * 512) {
        int b = idx / EDIM, j = idx - b * EDIM;
        float v = emb[(size_t)e1[b] * EDIM + j];
        s += v; q += v * v;
    }
    #pragma unroll
    for (int o = 16; o; o >>= 1) {
        s += __shfl_down_sync(0xffffffffu, s, o);
        q += __shfl_down_sync(0xffffffffu, q, o);
    }
    if (lane == 0) { ws[wrp] = s; wq[wrp] = q; }
    __syncthreads();
    if (tid < 16) {
        float v1 = ws[tid], v2 = wq[tid];
        #pragma unroll
        for (int o = 8; o; o >>= 1) {
            v1 += __shfl_down_sync(0xffffu, v1, o, 16);
            v2 += __shfl_down_sync(0xffffu, v2, o, 16);
        }
        if (tid == 0) { d_bn0B[blockIdx.x][0] = v1; d_bn0B[blockIdx.x][1] = v2; }
    }
}

// ---------------- K2 (main): conv; smem-staged y; coalesced flush ----------------
__global__ void k2_conv(const int* __restrict__ e1, const int* __restrict__ rel,
                        const float* __restrict__ emb,
                        const float* __restrict__ conv_w, const float* __restrict__ conv_b,
                        const float* __restrict__ g0, const float* __restrict__ b0) {
    __shared__ float sx[200];
    __shared__ float sw[288];
    __shared__ float scb[32];
    __shared__ float sbn[2];
    __shared__ __align__(16) float sy[FDIM];   // 18 KB staging; 16B-aligned for float4 flush
    int b = blockIdx.x;
    int tid = threadIdx.x;
    int r = rel[b];

    if (tid < 32) {
        float v = (tid < 16) ? d_bn0B[tid][0] : d_bn0B[tid - 16][1];
        #pragma unroll
        for (int o = 8; o; o >>= 1) v += __shfl_down_sync(0xffffffffu, v, o, 16);
        if ((tid & 15) == 0) sbn[tid >> 4] = v;
    }
    __syncthreads();
    const float inv0 = 1.f / (float)(B * EDIM);
    float m0v = sbn[0] * inv0;
    float var0 = sbn[1] * inv0 - m0v * m0v;
    float bn_s = rsqrtf(var0 + EPS) * g0[0];
    float bn_b = b0[0] - m0v * bn_s;

    if (tid < 200) sx[tid] = fmaf(emb[(size_t)e1[b] * EDIM + tid], bn_s, bn_b);
    for (int i = tid; i < 288; i += 256) sw[i] = conv_w[(size_t)r * 288 + i];
    if (tid < 32) scb[tid] = conv_b[(size_t)r * 32 + tid];
    __syncthreads();

    int o = tid >> 3;
    int i = tid & 7;
    const float* w = &sw[o * 9];
    float cb = scb[o];
    float ls = 0.f, lq = 0.f;
    float* syrow = &sy[o * 144 + i * 18];
    #pragma unroll
    for (int j = 0; j < 18; j++) {
        float acc = cb;
        #pragma unroll
        for (int di = 0; di < 3; di++)
            #pragma unroll
            for (int dj = 0; dj < 3; dj++)
                acc = fmaf(sx[(i + di) * 20 + (j + dj)], w[di * 3 + dj], acc);
        syrow[j] = acc;
        ls += acc; lq += acc * acc;
    }
    #pragma unroll
    for (int off = 4; off; off >>= 1) {
        ls += __shfl_down_sync(0xffffffffu, ls, off, 8);
        lq += __shfl_down_sync(0xffffffffu, lq, off, 8);
    }
    if ((tid & 7) == 0) {
        atomicAdd(&d_chsumB[b & 15][o], ls);
        atomicAdd(&d_chsqB[b & 15][o], lq);
    }
    __syncthreads();

    // coalesced flush: 1152 float4 segments, 256 threads
    float* dst = &d_y[(size_t)b * FDIM];
    #pragma unroll
    for (int s = 0; s < 4; s++) {
        int idx = tid + s * 256;
        *(float4*)(dst + idx * 4) = *(const float4*)(sy + idx * 4);
    }
    {
        int idx = tid + 1024;
        if (idx < FDIM / 4)
            *(float4*)(dst + idx * 4) = *(const float4*)(sy + idx * 4);
    }
}

// ---------------- K3 (main, after prep_w join): fc GEMM fp16 mma ----------------
#define F_TA 0
#define F_TB 8192
#define F_ST 24576
#define F_SMEM (2 * F_ST)

__device__ __forceinline__ void k3_transformA(char* smem, int buf, int kcol, int m0, int tid,
                                              const float* s_a, const float* s_c) {
    #pragma unroll
    for (int i = 0; i < 2; i++) {
        int idx = tid + i * 256;
        int row = idx >> 3, u = idx & 7;
        const float* src = d_y + (size_t)(m0 + row) * KFC + kcol + u * 8;
        float4 f0 = *(const float4*)src;
        float4 f1 = *(const float4*)(src + 4);
        float v[8] = {f0.x, f0.y, f0.z, f0.w, f1.x, f1.y, f1.z, f1.w};
        uint32_t p[4];
        #pragma unroll
        for (int t2 = 0; t2 < 4; t2++) {
            int ka = kcol + u * 8 + 2 * t2;
            int ca = ka / 144, cb = (ka + 1) / 144;
            __half ha = __float2half(fmaxf(fmaf(v[2 * t2],     s_a[ca], s_c[ca]), 0.f));
            __half hb = __float2half(fmaxf(fmaf(v[2 * t2 + 1], s_a[cb], s_c[cb]), 0.f));
            p[t2] = pack_h2(ha, hb);
        }
        *(uint4*)(smem + buf * F_ST + F_TA + swz(row * 128 + u * 16)) =
            make_uint4(p[0], p[1], p[2], p[3]);
    }
}
__device__ __forceinline__ void k3_loadB(uint32_t sb, int buf, int kcol, int n0, int tid) {
    uint32_t base = sb + buf * F_ST;
    #pragma unroll
    for (int i = 0; i < 4; i++) {
        int idx = tid + i * 256;
        int row = idx >> 3, u = idx & 7;
        cp_async16(base + F_TB + swz(row * 128 + u * 16),
                   d_wcat + (size_t)(n0 + row) * KFC + kcol + u * 8);
    }
    cp_commit();
}

__global__ void __launch_bounds__(256) k3_mma(const float* __restrict__ g1,
                                              const float* __restrict__ b1) {
    extern __shared__ char smem[];
    const uint32_t sb = smem_u32(smem);
    __shared__ float s_a[32], s_c[32];
    int tid = threadIdx.x, lane = tid & 31, wid = tid >> 5;
    int wm = wid & 1, wn = wid >> 1;
    int n0 = blockIdx.x * 128, m0 = blockIdx.y * 64;
    int kb = blockIdx.z * 192;

    if (tid < 32) {
        float cs = 0.f, cq = 0.f;
        #pragma unroll
        for (int j = 0; j < 16; j++) { cs += d_chsumB[j][tid]; cq += d_chsqB[j][tid]; }
        const float inv = 1.f / (float)(B * 144);
        float m = cs * inv;
        float var = cq * inv - m * m;
        float a = rsqrtf(var + EPS) * g1[tid];
        s_a[tid] = a;
        s_c[tid] = b1[tid] - m * a;
    }
    __syncthreads();

    float acc[2][4][4];
    #pragma unroll
    for (int f = 0; f < 2; f++)
        #pragma unroll
        for (int h = 0; h < 4; h++)
            #pragma unroll
            for (int i = 0; i < 4; i++) acc[f][h][i] = 0.f;

    k3_transformA(smem, 0, kb, m0, tid, s_a, s_c);
    k3_loadB(sb, 0, kb, n0, tid);

    for (int c = 0; c < 3; c++) {
        int buf = c & 1;
        if (c < 2) {
            k3_transformA(smem, buf ^ 1, kb + (c + 1) * 64, m0, tid, s_a, s_c);
            k3_loadB(sb, buf ^ 1, kb + (c + 1) * 64, n0, tid);
            asm volatile("cp.async.wait_group 1;" ::: "memory");
        } else {
            asm volatile("cp.async.wait_group 0;" ::: "memory");
        }
        __syncthreads();

        const uint32_t st = sb + buf * F_ST;
        #pragma unroll
        for (int s = 0; s < 4; s++) {
            uint32_t a[2][4];
            #pragma unroll
            for (int f = 0; f < 2; f++) {
                int row = wm * 32 + f * 16 + (lane & 15);
                int u = s * 2 + (lane >> 4);
                ldm4(a[f], st + F_TA + swz(row * 128 + u * 16));
            }
            #pragma unroll
            for (int j = 0; j < 2; j++) {
                uint32_t b[4];
                int row = wn * 32 + j * 16 + ((lane >> 4) << 3) + (lane & 7);
                int u = s * 2 + ((lane >> 3) & 1);
                ldm4(b, st + F_TB + swz(row * 128 + u * 16));
                #pragma unroll
                for (int g = 0; g < 2; g++)
                    #pragma unroll
                    for (int f = 0; f < 2; f++)
                        mma16816h(acc[f][j * 2 + g], a[f], b + g * 2);
            }
        }
        __syncthreads();
    }

    int g = lane >> 2, q = lane & 3;
    #pragma unroll
    for (int f = 0; f < 2; f++) {
        int mrow = m0 + wm * 32 + f * 16 + g;
        #pragma unroll
        for (int h = 0; h < 4; h++) {
            int n = n0 + wn * 32 + h * 8 + q * 2;
            if (n < EDIM) {
                atomicAdd(&d_h[(size_t)mrow * EDIM + n],           acc[f][h][0]);
                atomicAdd(&d_h[(size_t)mrow * EDIM + n + 1],       acc[f][h][1]);
                atomicAdd(&d_h[(size_t)(mrow + 8) * EDIM + n],     acc[f][h][2]);
                atomicAdd(&d_h[(size_t)(mrow + 8) * EDIM + n + 1], acc[f][h][3]);
            }
        }
    }
}

// ---------------- K4 (main): bn2 + relu, emit fp16 z ----------------
__global__ void k4_bn2(const float* __restrict__ g2, const float* __restrict__ b2) {
    int n = blockIdx.x;
    int t = threadIdx.x;
    float v0 = d_h[(size_t)t * EDIM + n];
    float v1 = d_h[(size_t)(t + 256) * EDIM + n];
    __shared__ float rs[256], rq[256];
    rs[t] = v0 + v1; rq[t] = v0 * v0 + v1 * v1;
    __syncthreads();
    for (int o = 128; o; o >>= 1) {
        if (t < o) { rs[t] += rs[t + o]; rq[t] += rq[t + o]; }
        __syncthreads();
    }
    __shared__ float sa, sc;
    if (t == 0) {
        float m = rs[0] * (1.f / 512.f);
        float var = rq[0] * (1.f / 512.f) - m * m;
        float a = rsqrtf(var + EPS) * g2[n];
        sa = a; sc = b2[n] - m * a;
    }
    __syncthreads();
    float z0 = fmaxf(fmaf(v0, sa, sc), 0.f);
    float z1 = fmaxf(fmaf(v1, sa, sc), 0.f);
    d_zcat[(size_t)t * KH + n]         = __float2half(z0);
    d_zcat[(size_t)(t + 256) * KH + n] = __float2half(z1);
}

// ---------------- K5 (main, after prep_e join): fp16 mma GEMM + bias + sigmoid ----------------
#define T_A 0
#define T_B 8192
#define ST_STRIDE 40960
#define K5_SMEM (2 * ST_STRIDE)

__device__ __forceinline__ void k5_load(uint32_t sb, int buf, int ks, int m0, int n0, int tid) {
    uint32_t base = sb + buf * ST_STRIDE;
    int koff = ks * 64;
    if (ks < 3) {
        #pragma unroll
        for (int i = 0; i < 2; i++) {
            int idx = tid + i * 256;
            int row = idx >> 3, u = idx & 7;
            cp_async16(base + T_A + swz(row * 128 + u * 16),
                       d_zcat + (size_t)(m0 + row) * KH + koff + u * 8);
        }
        #pragma unroll
        for (int i = 0; i < 8; i++) {
            int idx = tid + i * 256;
            int row = idx >> 3, u = idx & 7;
            cp_async16(base + T_B + swz(row * 128 + u * 16),
                       d_ecat + (size_t)(n0 + row) * KH + koff + u * 8);
        }
    } else {
        if (tid < 128) {
            int row = tid >> 1, u = tid & 1;
            cp_async16(base + T_A + swz(row * 128 + u * 16),
                       d_zcat + (size_t)(m0 + row) * KH + koff + u * 8);
        }
        #pragma unroll
        for (int i = 0; i < 2; i++) {
            int idx = tid + i * 256;
            int row = idx >> 1, u = idx & 1;
            cp_async16(base + T_B + swz(row * 128 + u * 16),
                       d_ecat + (size_t)(n0 + row) * KH + koff + u * 8);
        }
    }
    cp_commit();
}

__global__ void __launch_bounds__(256, 2) k5_mma(const float* __restrict__ bias_e,
                                                 float* __restrict__ out) {
    extern __shared__ char smem[];
    const uint32_t sb = smem_u32(smem);
    int tid = threadIdx.x, lane = tid & 31, wid = tid >> 5;
    int wm = wid & 1, wn = wid >> 1;
    int m0 = blockIdx.x * 64, n0 = blockIdx.y * 256;

    float acc[2][8][4];
    #pragma unroll
    for (int f = 0; f < 2; f++)
        #pragma unroll
        for (int h = 0; h < 8; h++)
            #pragma unroll
            for (int i = 0; i < 4; i++) acc[f][h][i] = 0.f;

    k5_load(sb, 0, 0, m0, n0, tid);

    for (int ks = 0; ks < 4; ks++) {
        int buf = ks & 1;
        if (ks < 3) {
            k5_load(sb, buf ^ 1, ks + 1, m0, n0, tid);
            asm volatile("cp.async.wait_group 1;" ::: "memory");
        } else {
            asm volatile("cp.async.wait_group 0;" ::: "memory");
        }
        __syncthreads();

        const int scount = (ks < 3) ? 4 : 1;
        const uint32_t st = sb + buf * ST_STRIDE;
        for (int s = 0; s < scount; s++) {
            uint32_t a[2][4];
            #pragma unroll
            for (int f = 0; f < 2; f++) {
                int row = wm * 32 + f * 16 + (lane & 15);
                int u = s * 2 + (lane >> 4);
                ldm4(a[f], st + T_A + swz(row * 128 + u * 16));
            }
            #pragma unroll
            for (int j = 0; j < 4; j++) {
                uint32_t b[4];
                int row = wn * 64 + j * 16 + ((lane >> 4) << 3) + (lane & 7);
                int u = s * 2 + ((lane >> 3) & 1);
                ldm4(b, st + T_B + swz(row * 128 + u * 16));
                #pragma unroll
                for (int g = 0; g < 2; g++)
                    #pragma unroll
                    for (int f = 0; f < 2; f++)
                        mma16816h(acc[f][j * 2 + g], a[f], b + g * 2);
            }
        }
        __syncthreads();
    }

    int g = lane >> 2, q = lane & 3;
    #pragma unroll
    for (int f = 0; f < 2; f++) {
        int mrow = m0 + wm * 32 + f * 16 + g;
        #pragma unroll
        for (int h = 0; h < 8; h++) {
            int n = n0 + wn * 64 + h * 8 + q * 2;
            if (n < NUM_ENT) {
                float b0 = bias_e[n], b1 = bias_e[n + 1];
                *(float2*)&out[(size_t)mrow * NUM_ENT + n] =
                    make_float2(sigmoid_fast(acc[f][h][0] + b0),
                                sigmoid_fast(acc[f][h][1] + b1));
                *(float2*)&out[(size_t)(mrow + 8) * NUM_ENT + n] =
                    make_float2(sigmoid_fast(acc[f][h][2] + b0),
                                sigmoid_fast(acc[f][h][3] + b1));
            }
        }
    }
}

// ---------------- stream/event resources (host-side, created once at load) ----------------
namespace {
struct StreamRes {
    cudaStream_t side = nullptr;
    cudaEvent_t ev_fork = nullptr, ev_w = nullptr, ev_e = nullptr;
    StreamRes() {
        cudaStreamCreateWithFlags(&side, cudaStreamNonBlocking);
        cudaEventCreateWithFlags(&ev_fork, cudaEventDisableTiming);
        cudaEventCreateWithFlags(&ev_w, cudaEventDisableTiming);
        cudaEventCreateWithFlags(&ev_e, cudaEventDisableTiming);
    }
};
StreamRes g_sr;
}

// ---------------- launcher: fork prep to side stream, join before k3 / k5 ----------------
extern "C" void kernel_launch(void* const* d_in, const int* in_sizes, int n_in,
                              void* d_out, int out_size) {
    const int*   e1     = (const int*)d_in[0];
    const int*   rel    = (const int*)d_in[1];
    const float* emb    = (const float*)d_in[2];
    const float* conv_w = (const float*)d_in[3];
    const float* conv_b = (const float*)d_in[4];
    const float* g0     = (const float*)d_in[5];
    const float* b0     = (const float*)d_in[6];
    const float* g1     = (const float*)d_in[7];
    const float* b1     = (const float*)d_in[8];
    const float* g2     = (const float*)d_in[9];
    const float* b2     = (const float*)d_in[10];
    const float* fc_w   = (const float*)d_in[11];
    // d_in[12] = fc_b: cancels exactly under training-mode bn2
    const float* bias_e = (const float*)d_in[13];
    float* out = (float*)d_out;

    cudaFuncSetAttribute(k3_mma, cudaFuncAttributeMaxDynamicSharedMemorySize, F_SMEM);
    cudaFuncSetAttribute(k5_mma, cudaFuncAttributeMaxDynamicSharedMemorySize, K5_SMEM);

    // fork side stream off the main (launch) stream
    cudaEventRecord(g_sr.ev_fork, 0);
    cudaStreamWaitEvent(g_sr.side, g_sr.ev_fork, 0);
    k_prep_w<<<PREPW_GRID, 256, 0, g_sr.side>>>(fc_w);
    cudaEventRecord(g_sr.ev_w, g_sr.side);
    k_prep_e<<<PREPE_GRID, 256, 0, g_sr.side>>>(emb);
    cudaEventRecord(g_sr.ev_e, g_sr.side);

    // main chain
    k1_bn0<<<16, 512>>>(e1, emb);
    k2_conv<<<B, 256>>>(e1, rel, emb, conv_w, conv_b, g0, b0);
    cudaStreamWaitEvent(0, g_sr.ev_w, 0);            // k3 needs d_wcat + d_h zero
    k3_mma<<<dim3(2, 8, 24), 256, F_SMEM>>>(g1, b1);
    k4_bn2<<<EDIM, 256>>>(g2, b2);
    cudaStreamWaitEvent(0, g_sr.ev_e, 0);            // k5 needs d_ecat
    k5_mma<<<dim3(8, N_GRID), 256, K5_SMEM>>>(bias_e, out);
}

// round 16
// speedup vs baseline: 3.1141x; 1.0197x over previous
#include <cuda_runtime.h>
#include <cuda_bf16.h>
#include <cuda_fp16.h>
#include <cstdint>

#define B 512
#define EDIM 200
#define NUM_ENT 100000
#define FDIM 4608          // 32*8*18
#define KFC 4608
#define EPS 1e-5f
#define KH 256             // fp16 K padded 200 -> 256
#define ENT_TILE 256
#define N_GRID ((NUM_ENT + ENT_TILE - 1) / ENT_TILE)   // 391
#define ENT_PAD (N_GRID * ENT_TILE)                    // 100096
#define ESEGS (NUM_ENT * 25)                           // 2.5M 8-col segments
#define PREPE_GRID ((ESEGS + 255) / 256)               // 9766
#define WSEGS (EDIM * (KFC / 8))                       // 115200
#define PREPW_GRID ((WSEGS + 255) / 256)               // 451

// ---------------- device scratch (static allocations only; zero-initialized) ----------------
__device__ __half d_yh[B * KFC];           // conv output, RAW fp16 (pre-bn1)
__device__ float d_h[B * EDIM];            // fc output, pre-bn2 (zeroed per call by prep_w)
__device__ __half d_wcat[256 * KFC];       // fc_w fp16; rows 200..255 never written (stay 0)
__device__ __half d_zcat[B * KH];          // fp16 z; cols 200..255 never written (stay 0)
__device__ __half d_ecat[ENT_PAD * KH];    // fp16 e; pad rows/cols never written (stay 0)
__device__ float d_chsumB[16][32];         // bn1 partials; bucket b zeroed by k1 block b
__device__ float d_chsqB[16][32];
__device__ float d_bn0B[16][2];            // bn0 partials; STORED (not accumulated) by k1

// ---------------- PTX helpers (sm_80-compatible subset only) ----------------
__device__ __forceinline__ uint32_t smem_u32(const void* p) {
    uint32_t a;
    asm("{ .reg .u64 t; cvta.to.shared.u64 t, %1; cvt.u32.u64 %0, t; }" : "=r"(a) : "l"(p));
    return a;
}
__device__ __forceinline__ void cp_async16(uint32_t dst, const void* src) {
    asm volatile("cp.async.cg.shared.global [%0], [%1], 16;" :: "r"(dst), "l"(src) : "memory");
}
__device__ __forceinline__ void cp_commit() {
    asm volatile("cp.async.commit_group;" ::: "memory");
}
__device__ __forceinline__ void ldm4(uint32_t* r, uint32_t a) {
    asm volatile("ldmatrix.sync.aligned.m8n8.x4.shared.b16 {%0,%1,%2,%3}, [%4];"
                 : "=r"(r[0]), "=r"(r[1]), "=r"(r[2]), "=r"(r[3]) : "r"(a));
}
__device__ __forceinline__ void mma16816h(float* d, const uint32_t* a, const uint32_t* b) {
    asm volatile("mma.sync.aligned.m16n8k16.row.col.f32.f16.f16.f32 "
                 "{%0,%1,%2,%3}, {%4,%5,%6,%7}, {%8,%9}, {%0,%1,%2,%3};"
                 : "+f"(d[0]), "+f"(d[1]), "+f"(d[2]), "+f"(d[3])
                 : "r"(a[0]), "r"(a[1]), "r"(a[2]), "r"(a[3]), "r"(b[0]), "r"(b[1]));
}
__device__ __forceinline__ uint32_t swz(uint32_t off) { return off ^ ((off >> 3) & 0x70); }
__device__ __forceinline__ uint32_t pack_h2(__half a, __half b) {
    return (uint32_t)__half_as_ushort(a) | ((uint32_t)__half_as_ushort(b) << 16);
}
__device__ __forceinline__ float sigmoid_fast(float v) {
    float t;
    asm("tanh.approx.f32 %0, %1;" : "=f"(t) : "f"(0.5f * v));
    return fmaf(0.5f, t, 0.5f);
}

// ---------------- prep_w (side stream): fc_w->fp16 + zero d_h ----------------
__global__ void __launch_bounds__(256) k_prep_w(const float* __restrict__ fc_w) {
    int gi = blockIdx.x * 256 + threadIdx.x;
    if (gi < B * EDIM) d_h[gi] = 0.f;
    if (gi < WSEGS) {
        int row = gi / (KFC / 8), c0 = (gi % (KFC / 8)) * 8;
        const float* src = fc_w + (size_t)row * KFC + c0;
        float4 f0 = *(const float4*)src;
        float4 f1 = *(const float4*)(src + 4);
        uint32_t p0 = pack_h2(__float2half(f0.x), __float2half(f0.y));
        uint32_t p1 = pack_h2(__float2half(f0.z), __float2half(f0.w));
        uint32_t p2 = pack_h2(__float2half(f1.x), __float2half(f1.y));
        uint32_t p3 = pack_h2(__float2half(f1.z), __float2half(f1.w));
        *(uint4*)(d_wcat + (size_t)row * KFC + c0) = make_uint4(p0, p1, p2, p3);
    }
}

// ---------------- prep_e (side stream): emb -> fp16 ecat ----------------
__global__ void __launch_bounds__(256) k_prep_e(const float* __restrict__ emb) {
    int gi = blockIdx.x * 256 + threadIdx.x;
    if (gi < ESEGS) {
        int row = gi / 25, c0 = (gi - row * 25) * 8;
        const float* src = emb + (size_t)row * EDIM + c0;
        float4 f0 = *(const float4*)src;
        float4 f1 = *(const float4*)(src + 4);
        uint32_t p0 = pack_h2(__float2half(f0.x), __float2half(f0.y));
        uint32_t p1 = pack_h2(__float2half(f0.z), __float2half(f0.w));
        uint32_t p2 = pack_h2(__float2half(f1.x), __float2half(f1.y));
        uint32_t p3 = pack_h2(__float2half(f1.z), __float2half(f1.w));
        *(uint4*)(d_ecat + (size_t)row * KH + c0) = make_uint4(p0, p1, p2, p3);
    }
}

// ---------------- K1 (main): bn0 stats; block-reduce + STORE; zero own bn1 bucket ----------------
__global__ void k1_bn0(const int* __restrict__ e1, const float* __restrict__ emb) {
    __shared__ float ws[16], wq[16];
    int tid = threadIdx.x, lane = tid & 31, wrp = tid >> 5;
    if (tid < 32) { d_chsumB[blockIdx.x][tid] = 0.f; d_chsqB[blockIdx.x][tid] = 0.f; }
    float s = 0.f, q = 0.f;
    for (int idx = blockIdx.x * 512 + tid; idx < B * EDIM; idx += gridDim.x * 512) {
        int b = idx / EDIM, j = idx - b * EDIM;
        float v = emb[(size_t)e1[b] * EDIM + j];
        s += v; q += v * v;
    }
    #pragma unroll
    for (int o = 16; o; o >>= 1) {
        s += __shfl_down_sync(0xffffffffu, s, o);
        q += __shfl_down_sync(0xffffffffu, q, o);
    }
    if (lane == 0) { ws[wrp] = s; wq[wrp] = q; }
    __syncthreads();
    if (tid < 16) {
        float v1 = ws[tid], v2 = wq[tid];
        #pragma unroll
        for (int o = 8; o; o >>= 1) {
            v1 += __shfl_down_sync(0xffffu, v1, o, 16);
            v2 += __shfl_down_sync(0xffffu, v2, o, 16);
        }
        if (tid == 0) { d_bn0B[blockIdx.x][0] = v1; d_bn0B[blockIdx.x][1] = v2; }
    }
}

// ---------------- K2 (main): conv; smem-staged; fp16 flush ----------------
__global__ void k2_conv(const int* __restrict__ e1, const int* __restrict__ rel,
                        const float* __restrict__ emb,
                        const float* __restrict__ conv_w, const float* __restrict__ conv_b,
                        const float* __restrict__ g0, const float* __restrict__ b0) {
    __shared__ float sx[200];
    __shared__ float sw[288];
    __shared__ float scb[32];
    __shared__ float sbn[2];
    __shared__ __align__(16) float sy[FDIM];   // 18 KB staging
    int b = blockIdx.x;
    int tid = threadIdx.x;
    int r = rel[b];

    if (tid < 32) {
        float v = (tid < 16) ? d_bn0B[tid][0] : d_bn0B[tid - 16][1];
        #pragma unroll
        for (int o = 8; o; o >>= 1) v += __shfl_down_sync(0xffffffffu, v, o, 16);
        if ((tid & 15) == 0) sbn[tid >> 4] = v;
    }
    __syncthreads();
    const float inv0 = 1.f / (float)(B * EDIM);
    float m0v = sbn[0] * inv0;
    float var0 = sbn[1] * inv0 - m0v * m0v;
    float bn_s = rsqrtf(var0 + EPS) * g0[0];
    float bn_b = b0[0] - m0v * bn_s;

    if (tid < 200) sx[tid] = fmaf(emb[(size_t)e1[b] * EDIM + tid], bn_s, bn_b);
    for (int i = tid; i < 288; i += 256) sw[i] = conv_w[(size_t)r * 288 + i];
    if (tid < 32) scb[tid] = conv_b[(size_t)r * 32 + tid];
    __syncthreads();

    int o = tid >> 3;
    int i = tid & 7;
    const float* w = &sw[o * 9];
    float cb = scb[o];
    float ls = 0.f, lq = 0.f;
    float* syrow = &sy[o * 144 + i * 18];
    #pragma unroll
    for (int j = 0; j < 18; j++) {
        float acc = cb;
        #pragma unroll
        for (int di = 0; di < 3; di++)
            #pragma unroll
            for (int dj = 0; dj < 3; dj++)
                acc = fmaf(sx[(i + di) * 20 + (j + dj)], w[di * 3 + dj], acc);
        syrow[j] = acc;
        ls += acc; lq += acc * acc;
    }
    #pragma unroll
    for (int off = 4; off; off >>= 1) {
        ls += __shfl_down_sync(0xffffffffu, ls, off, 8);
        lq += __shfl_down_sync(0xffffffffu, lq, off, 8);
    }
    if ((tid & 7) == 0) {
        atomicAdd(&d_chsumB[b & 15][o], ls);
        atomicAdd(&d_chsqB[b & 15][o], lq);
    }
    __syncthreads();

    // fp16 flush: 576 segments of 8, coalesced uint4 stores
    __half* dst = d_yh + (size_t)b * KFC;
    #pragma unroll
    for (int s = 0; s < 2; s++) {
        int seg = tid + s * 256;
        const float* sp = sy + seg * 8;
        uint32_t p0 = pack_h2(__float2half(sp[0]), __float2half(sp[1]));
        uint32_t p1 = pack_h2(__float2half(sp[2]), __float2half(sp[3]));
        uint32_t p2 = pack_h2(__float2half(sp[4]), __float2half(sp[5]));
        uint32_t p3 = pack_h2(__float2half(sp[6]), __float2half(sp[7]));
        *(uint4*)(dst + seg * 8) = make_uint4(p0, p1, p2, p3);
    }
    {
        int seg = tid + 512;
        if (seg < KFC / 8) {
            const float* sp = sy + seg * 8;
            uint32_t p0 = pack_h2(__float2half(sp[0]), __float2half(sp[1]));
            uint32_t p1 = pack_h2(__float2half(sp[2]), __float2half(sp[3]));
            uint32_t p2 = pack_h2(__float2half(sp[4]), __float2half(sp[5]));
            uint32_t p3 = pack_h2(__float2half(sp[6]), __float2half(sp[7]));
            *(uint4*)(dst + seg * 8) = make_uint4(p0, p1, p2, p3);
        }
    }
}

// ---------------- K3 (main, after prep_w join): fc GEMM fp16 mma ----------------
#define F_TA 0
#define F_TB 8192
#define F_ST 24576
#define F_SMEM (2 * F_ST)

__device__ __forceinline__ void k3_transformA(char* smem, int buf, int kcol, int m0, int tid,
                                              const float* s_a, const float* s_c) {
    #pragma unroll
    for (int i = 0; i < 2; i++) {
        int idx = tid + i * 256;
        int row = idx >> 3, u = idx & 7;
        uint4 raw = *(const uint4*)(d_yh + (size_t)(m0 + row) * KFC + kcol + u * 8);
        const uint32_t rr[4] = {raw.x, raw.y, raw.z, raw.w};
        uint32_t p[4];
        #pragma unroll
        for (int t2 = 0; t2 < 4; t2++) {
            int ka = kcol + u * 8 + 2 * t2;
            int ca = ka / 144, cb = (ka + 1) / 144;
            float va = __half2float(__ushort_as_half((unsigned short)(rr[t2] & 0xffffu)));
            float vb = __half2float(__ushort_as_half((unsigned short)(rr[t2] >> 16)));
            __half ha = __float2half(fmaxf(fmaf(va, s_a[ca], s_c[ca]), 0.f));
            __half hb = __float2half(fmaxf(fmaf(vb, s_a[cb], s_c[cb]), 0.f));
            p[t2] = pack_h2(ha, hb);
        }
        *(uint4*)(smem + buf * F_ST + F_TA + swz(row * 128 + u * 16)) =
            make_uint4(p[0], p[1], p[2], p[3]);
    }
}
__device__ __forceinline__ void k3_loadB(uint32_t sb, int buf, int kcol, int n0, int tid) {
    uint32_t base = sb + buf * F_ST;
    #pragma unroll
    for (int i = 0; i < 4; i++) {
        int idx = tid + i * 256;
        int row = idx >> 3, u = idx & 7;
        cp_async16(base + F_TB + swz(row * 128 + u * 16),
                   d_wcat + (size_t)(n0 + row) * KFC + kcol + u * 8);
    }
    cp_commit();
}

__global__ void __launch_bounds__(256) k3_mma(const float* __restrict__ g1,
                                              const float* __restrict__ b1) {
    extern __shared__ char smem[];
    const uint32_t sb = smem_u32(smem);
    __shared__ float s_a[32], s_c[32];
    int tid = threadIdx.x, lane = tid & 31, wid = tid >> 5;
    int wm = wid & 1, wn = wid >> 1;
    int n0 = blockIdx.x * 128, m0 = blockIdx.y * 64;
    int kb = blockIdx.z * 192;

    if (tid < 32) {
        float cs = 0.f, cq = 0.f;
        #pragma unroll
        for (int j = 0; j < 16; j++) { cs += d_chsumB[j][tid]; cq += d_chsqB[j][tid]; }
        const float inv = 1.f / (float)(B * 144);
        float m = cs * inv;
        float var = cq * inv - m * m;
        float a = rsqrtf(var + EPS) * g1[tid];
        s_a[tid] = a;
        s_c[tid] = b1[tid] - m * a;
    }
    __syncthreads();

    float acc[2][4][4];
    #pragma unroll
    for (int f = 0; f < 2; f++)
        #pragma unroll
        for (int h = 0; h < 4; h++)
            #pragma unroll
            for (int i = 0; i < 4; i++) acc[f][h][i] = 0.f;

    k3_transformA(smem, 0, kb, m0, tid, s_a, s_c);
    k3_loadB(sb, 0, kb, n0, tid);

    for (int c = 0; c < 3; c++) {
        int buf = c & 1;
        if (c < 2) {
            k3_transformA(smem, buf ^ 1, kb + (c + 1) * 64, m0, tid, s_a, s_c);
            k3_loadB(sb, buf ^ 1, kb + (c + 1) * 64, n0, tid);
            asm volatile("cp.async.wait_group 1;" ::: "memory");
        } else {
            asm volatile("cp.async.wait_group 0;" ::: "memory");
        }
        __syncthreads();

        const uint32_t st = sb + buf * F_ST;
        #pragma unroll
        for (int s = 0; s < 4; s++) {
            uint32_t a[2][4];
            #pragma unroll
            for (int f = 0; f < 2; f++) {
                int row = wm * 32 + f * 16 + (lane & 15);
                int u = s * 2 + (lane >> 4);
                ldm4(a[f], st + F_TA + swz(row * 128 + u * 16));
            }
            #pragma unroll
            for (int j = 0; j < 2; j++) {
                uint32_t b[4];
                int row = wn * 32 + j * 16 + ((lane >> 4) << 3) + (lane & 7);
                int u = s * 2 + ((lane >> 3) & 1);
                ldm4(b, st + F_TB + swz(row * 128 + u * 16));
                #pragma unroll
                for (int g = 0; g < 2; g++)
                    #pragma unroll
                    for (int f = 0; f < 2; f++)
                        mma16816h(acc[f][j * 2 + g], a[f], b + g * 2);
            }
        }
        __syncthreads();
    }

    int g = lane >> 2, q = lane & 3;
    #pragma unroll
    for (int f = 0; f < 2; f++) {
        int mrow = m0 + wm * 32 + f * 16 + g;
        #pragma unroll
        for (int h = 0; h < 4; h++) {
            int n = n0 + wn * 32 + h * 8 + q * 2;
            if (n < EDIM) {
                atomicAdd(&d_h[(size_t)mrow * EDIM + n],           acc[f][h][0]);
                atomicAdd(&d_h[(size_t)mrow * EDIM + n + 1],       acc[f][h][1]);
                atomicAdd(&d_h[(size_t)(mrow + 8) * EDIM + n],     acc[f][h][2]);
                atomicAdd(&d_h[(size_t)(mrow + 8) * EDIM + n + 1], acc[f][h][3]);
            }
        }
    }
}

// ---------------- K4 (main): bn2 + relu, emit fp16 z ----------------
__global__ void k4_bn2(const float* __restrict__ g2, const float* __restrict__ b2) {
    int n = blockIdx.x;
    int t = threadIdx.x;
    float v0 = d_h[(size_t)t * EDIM + n];
    float v1 = d_h[(size_t)(t + 256) * EDIM + n];
    __shared__ float rs[256], rq[256];
    rs[t] = v0 + v1; rq[t] = v0 * v0 + v1 * v1;
    __syncthreads();
    for (int o = 128; o; o >>= 1) {
        if (t < o) { rs[t] += rs[t + o]; rq[t] += rq[t + o]; }
        __syncthreads();
    }
    __shared__ float sa, sc;
    if (t == 0) {
        float m = rs[0] * (1.f / 512.f);
        float var = rq[0] * (1.f / 512.f) - m * m;
        float a = rsqrtf(var + EPS) * g2[n];
        sa = a; sc = b2[n] - m * a;
    }
    __syncthreads();
    float z0 = fmaxf(fmaf(v0, sa, sc), 0.f);
    float z1 = fmaxf(fmaf(v1, sa, sc), 0.f);
    d_zcat[(size_t)t * KH + n]         = __float2half(z0);
    d_zcat[(size_t)(t + 256) * KH + n] = __float2half(z1);
}

// ---------------- K5 (main, after prep_e join): fp16 mma GEMM + bias + sigmoid ----------------
#define T_A 0
#define T_B 8192
#define ST_STRIDE 40960
#define K5_SMEM (2 * ST_STRIDE)

__device__ __forceinline__ void k5_load(uint32_t sb, int buf, int ks, int m0, int n0, int tid) {
    uint32_t base = sb + buf * ST_STRIDE;
    int koff = ks * 64;
    if (ks < 3) {
        #pragma unroll
        for (int i = 0; i < 2; i++) {
            int idx = tid + i * 256;
            int row = idx >> 3, u = idx & 7;
            cp_async16(base + T_A + swz(row * 128 + u * 16),
                       d_zcat + (size_t)(m0 + row) * KH + koff + u * 8);
        }
        #pragma unroll
        for (int i = 0; i < 8; i++) {
            int idx = tid + i * 256;
            int row = idx >> 3, u = idx & 7;
            cp_async16(base + T_B + swz(row * 128 + u * 16),
                       d_ecat + (size_t)(n0 + row) * KH + koff + u * 8);
        }
    } else {
        if (tid < 128) {
            int row = tid >> 1, u = tid & 1;
            cp_async16(base + T_A + swz(row * 128 + u * 16),
                       d_zcat + (size_t)(m0 + row) * KH + koff + u * 8);
        }
        #pragma unroll
        for (int i = 0; i < 2; i++) {
            int idx = tid + i * 256;
            int row = idx >> 1, u = idx & 1;
            cp_async16(base + T_B + swz(row * 128 + u * 16),
                       d_ecat + (size_t)(n0 + row) * KH + koff + u * 8);
        }
    }
    cp_commit();
}

__global__ void __launch_bounds__(256, 2) k5_mma(const float* __restrict__ bias_e,
                                                 float* __restrict__ out) {
    extern __shared__ char smem[];
    const uint32_t sb = smem_u32(smem);
    int tid = threadIdx.x, lane = tid & 31, wid = tid >> 5;
    int wm = wid & 1, wn = wid >> 1;
    int m0 = blockIdx.x * 64, n0 = blockIdx.y * 256;

    float acc[2][8][4];
    #pragma unroll
    for (int f = 0; f < 2; f++)
        #pragma unroll
        for (int h = 0; h < 8; h++)
            #pragma unroll
            for (int i = 0; i < 4; i++) acc[f][h][i] = 0.f;

    k5_load(sb, 0, 0, m0, n0, tid);

    for (int ks = 0; ks < 4; ks++) {
        int buf = ks & 1;
        if (ks < 3) {
            k5_load(sb, buf ^ 1, ks + 1, m0, n0, tid);
            asm volatile("cp.async.wait_group 1;" ::: "memory");
        } else {
            asm volatile("cp.async.wait_group 0;" ::: "memory");
        }
        __syncthreads();

        const int scount = (ks < 3) ? 4 : 1;
        const uint32_t st = sb + buf * ST_STRIDE;
        for (int s = 0; s < scount; s++) {
            uint32_t a[2][4];
            #pragma unroll
            for (int f = 0; f < 2; f++) {
                int row = wm * 32 + f * 16 + (lane & 15);
                int u = s * 2 + (lane >> 4);
                ldm4(a[f], st + T_A + swz(row * 128 + u * 16));
            }
            #pragma unroll
            for (int j = 0; j < 4; j++) {
                uint32_t b[4];
                int row = wn * 64 + j * 16 + ((lane >> 4) << 3) + (lane & 7);
                int u = s * 2 + ((lane >> 3) & 1);
                ldm4(b, st + T_B + swz(row * 128 + u * 16));
                #pragma unroll
                for (int g = 0; g < 2; g++)
                    #pragma unroll
                    for (int f = 0; f < 2; f++)
                        mma16816h(acc[f][j * 2 + g], a[f], b + g * 2);
            }
        }
        __syncthreads();
    }

    int g = lane >> 2, q = lane & 3;
    #pragma unroll
    for (int f = 0; f < 2; f++) {
        int mrow = m0 + wm * 32 + f * 16 + g;
        #pragma unroll
        for (int h = 0; h < 8; h++) {
            int n = n0 + wn * 64 + h * 8 + q * 2;
            if (n < NUM_ENT) {
                float b0 = bias_e[n], b1 = bias_e[n + 1];
                *(float2*)&out[(size_t)mrow * NUM_ENT + n] =
                    make_float2(sigmoid_fast(acc[f][h][0] + b0),
                                sigmoid_fast(acc[f][h][1] + b1));
                *(float2*)&out[(size_t)(mrow + 8) * NUM_ENT + n] =
                    make_float2(sigmoid_fast(acc[f][h][2] + b0),
                                sigmoid_fast(acc[f][h][3] + b1));
            }
        }
    }
}

// ---------------- stream/event resources (host-side, created once at load) ----------------
namespace {
struct StreamRes {
    cudaStream_t side = nullptr;
    cudaEvent_t ev_fork = nullptr, ev_w = nullptr, ev_e = nullptr;
    StreamRes() {
        cudaStreamCreateWithFlags(&side, cudaStreamNonBlocking);
        cudaEventCreateWithFlags(&ev_fork, cudaEventDisableTiming);
        cudaEventCreateWithFlags(&ev_w, cudaEventDisableTiming);
        cudaEventCreateWithFlags(&ev_e, cudaEventDisableTiming);
    }
};
StreamRes g_sr;
}

// ---------------- launcher: fork prep to side stream, join before k3 / k5 ----------------
extern "C" void kernel_launch(void* const* d_in, const int* in_sizes, int n_in,
                              void* d_out, int out_size) {
    const int*   e1     = (const int*)d_in[0];
    const int*   rel    = (const int*)d_in[1];
    const float* emb    = (const float*)d_in[2];
    const float* conv_w = (const float*)d_in[3];
    const float* conv_b = (const float*)d_in[4];
    const float* g0     = (const float*)d_in[5];
    const float* b0     = (const float*)d_in[6];
    const float* g1     = (const float*)d_in[7];
    const float* b1     = (const float*)d_in[8];
    const float* g2     = (const float*)d_in[9];
    const float* b2     = (const float*)d_in[10];
    const float* fc_w   = (const float*)d_in[11];
    // d_in[12] = fc_b: cancels exactly under training-mode bn2
    const float* bias_e = (const float*)d_in[13];
    float* out = (float*)d_out;

    cudaFuncSetAttribute(k3_mma, cudaFuncAttributeMaxDynamicSharedMemorySize, F_SMEM);
    cudaFuncSetAttribute(k5_mma, cudaFuncAttributeMaxDynamicSharedMemorySize, K5_SMEM);

    // fork side stream off the main (launch) stream
    cudaEventRecord(g_sr.ev_fork, 0);
    cudaStreamWaitEvent(g_sr.side, g_sr.ev_fork, 0);
    k_prep_w<<<PREPW_GRID, 256, 0, g_sr.side>>>(fc_w);
    cudaEventRecord(g_sr.ev_w, g_sr.side);
    k_prep_e<<<PREPE_GRID, 256, 0, g_sr.side>>>(emb);
    cudaEventRecord(g_sr.ev_e, g_sr.side);

    // main chain
    k1_bn0<<<16, 512>>>(e1, emb);
    k2_conv<<<B, 256>>>(e1, rel, emb, conv_w, conv_b, g0, b0);
    cudaStreamWaitEvent(0, g_sr.ev_w, 0);            // k3 needs d_wcat + d_h zero
    k3_mma<<<dim3(2, 8, 24), 256, F_SMEM>>>(g1, b1);
    k4_bn2<<<EDIM, 256>>>(g2, b2);
    cudaStreamWaitEvent(0, g_sr.ev_e, 0);            // k5 needs d_ecat
    k5_mma<<<dim3(8, N_GRID), 256, K5_SMEM>>>(bias_e, out);
}